// round 10
// baseline (speedup 1.0000x reference)
#include <cuda_runtime.h>
#include <cuda_bf16.h>
#include <math.h>
#include <stdint.h>

#define N_NODES 8192
#define NFEAT   512
#define NHID    256
#define NLAT    64
#define NCLASS  16
#define ALPHA   0.2f
#define NWORDS  (N_NODES / 32)

// ------------------------------ device scratch ------------------------------
__device__ __align__(16) float g_Wh1 [N_NODES * NHID];
__device__ __align__(16) float g_h   [N_NODES * NHID];
__device__ __align__(16) float g_Whmu[N_NODES * NLAT];
__device__ __align__(16) float g_Whlv[N_NODES * NLAT];
__device__ __align__(16) __nv_bfloat16 g_T1h[NHID * N_NODES];
__device__ __align__(16) __nv_bfloat16 g_T1l[NHID * N_NODES];
__device__ __align__(16) __nv_bfloat16 g_Tmh[NLAT * N_NODES];
__device__ __align__(16) __nv_bfloat16 g_Tml[NLAT * N_NODES];
__device__ __align__(16) __nv_bfloat16 g_Tvh[NLAT * N_NODES];
__device__ __align__(16) __nv_bfloat16 g_Tvl[NLAT * N_NODES];
__device__ unsigned g_adjb[(size_t)N_NODES * NWORDS];
__device__ float g_s1[N_NODES], g_d1[N_NODES];
__device__ float g_smu[N_NODES], g_dmu[N_NODES];
__device__ float g_slv[N_NODES], g_dlv[N_NODES];
__device__ __align__(16) float g_E1[N_NODES],  g_F1[N_NODES];
__device__ __align__(16) float g_Emu[N_NODES], g_Fmu[N_NODES];
__device__ __align__(16) float g_Elv[N_NODES], g_Flv[N_NODES];
__device__ unsigned g_dmaxu[4];
__device__ float    g_dmaxf[4];

// ------------------------------ helpers -------------------------------------
__device__ __forceinline__ uint32_t smem_u32(const void* p) {
    uint32_t a;
    asm("{ .reg .u64 t; cvta.to.shared.u64 t, %1; cvt.u32.u64 %0, t; }"
        : "=r"(a) : "l"(p));
    return a;
}
__device__ __forceinline__ void cp_async16(uint32_t dst, const void* src) {
    asm volatile("cp.async.cg.shared.global [%0], [%1], 16;"
                 :: "r"(dst), "l"(src) : "memory");
}
#define CP_COMMIT() asm volatile("cp.async.commit_group;" ::: "memory")
#define CP_WAIT1()  asm volatile("cp.async.wait_group 1;"  ::: "memory")
#define CP_WAIT0()  asm volatile("cp.async.wait_group 0;"  ::: "memory")

__device__ __forceinline__ unsigned fenc(float x) {
    int ix = __float_as_int(x);
    return ix >= 0 ? ((unsigned)ix | 0x80000000u) : ~(unsigned)ix;
}
__device__ __forceinline__ float fdec(unsigned u) {
    int ix = (u & 0x80000000u) ? (int)(u & 0x7FFFFFFFu) : ~(int)u;
    return __int_as_float(ix);
}

// mma.sync m16n8k16 row.col bf16 -> f32 (HMMA on sm_103)
__device__ __forceinline__ void mma16816(float* c,
    uint32_t a0, uint32_t a1, uint32_t a2, uint32_t a3,
    uint32_t b0, uint32_t b1)
{
    asm volatile(
        "mma.sync.aligned.m16n8k16.row.col.f32.bf16.bf16.f32 "
        "{%0,%1,%2,%3}, {%4,%5,%6,%7}, {%8,%9}, {%0,%1,%2,%3};"
        : "+f"(c[0]), "+f"(c[1]), "+f"(c[2]), "+f"(c[3])
        : "r"(a0), "r"(a1), "r"(a2), "r"(a3), "r"(b0), "r"(b1));
}
__device__ __forceinline__ void ldsm_x4(uint32_t& r0, uint32_t& r1,
                                        uint32_t& r2, uint32_t& r3, uint32_t addr)
{
    asm volatile("ldmatrix.sync.aligned.m8n8.x4.shared.b16 {%0,%1,%2,%3}, [%4];"
                 : "=r"(r0), "=r"(r1), "=r"(r2), "=r"(r3) : "r"(addr));
}
__device__ __forceinline__ void ldsm_x2(uint32_t& r0, uint32_t& r1, uint32_t addr)
{
    asm volatile("ldmatrix.sync.aligned.m8n8.x2.shared.b16 {%0,%1}, [%2];"
                 : "=r"(r0), "=r"(r1) : "r"(addr));
}

// ------------------------------ utility kernels -----------------------------
__global__ void init_kernel(unsigned* dmaxu)
{
    if (threadIdx.x < 4) dmaxu[threadIdx.x] = 0u;
}

__global__ __launch_bounds__(256)
void pack_adj_kernel(const int* __restrict__ adj, unsigned* __restrict__ bits)
{
    size_t idx = (size_t)blockIdx.x * 256 + threadIdx.x;
    int v = adj[idx] > 0;
    unsigned b = __ballot_sync(0xffffffffu, v);
    if ((threadIdx.x & 31) == 0) bits[idx >> 5] = b;
}

__global__ __launch_bounds__(256)
void tsplit_kernel(const float* __restrict__ in,
                   __nv_bfloat16* __restrict__ hiT, __nv_bfloat16* __restrict__ loT,
                   int F)
{
    __shared__ float tile[32][33];
    int m0 = blockIdx.y * 32, f0 = blockIdx.x * 32;
    int x = threadIdx.x & 31, y = threadIdx.x >> 5;
    #pragma unroll
    for (int yy = 0; yy < 4; ++yy)
        tile[y + yy * 8][x] = in[(size_t)(m0 + y + yy * 8) * F + f0 + x];
    __syncthreads();
    #pragma unroll
    for (int yy = 0; yy < 4; ++yy) {
        float v = tile[x][y + yy * 8];
        __nv_bfloat16 hi = __float2bfloat16_rn(v);
        __nv_bfloat16 lo = __float2bfloat16_rn(v - __bfloat162float(hi));
        size_t o = (size_t)(f0 + y + yy * 8) * N_NODES + m0 + x;
        hiT[o] = hi; loT[o] = lo;
    }
}

__global__ __launch_bounds__(256)
void gemm_kernel(const float* __restrict__ A, const float* __restrict__ B,
                 float* __restrict__ C, int M, int N, int K)
{
    __shared__ float As[16][64];
    __shared__ float Bs[16][64];
    const int tid = threadIdx.x;
    const int tx = tid & 15, ty = tid >> 4;
    const int m0 = blockIdx.y * 64, n0 = blockIdx.x * 64;
    float acc[4][4] = {};
    for (int k0 = 0; k0 < K; k0 += 16) {
        {
            int m = tid >> 2, kq = (tid & 3) * 4;
            float4 v = *(const float4*)&A[(size_t)(m0 + m) * K + k0 + kq];
            As[kq + 0][m] = v.x; As[kq + 1][m] = v.y;
            As[kq + 2][m] = v.z; As[kq + 3][m] = v.w;
        }
        {
            int k = tid >> 4, nq = (tid & 15) * 4;
            *(float4*)&Bs[k][nq] = *(const float4*)&B[(size_t)(k0 + k) * N + n0 + nq];
        }
        __syncthreads();
        #pragma unroll
        for (int k = 0; k < 16; ++k) {
            float a[4], b[4];
            #pragma unroll
            for (int i = 0; i < 4; ++i) a[i] = As[k][ty * 4 + i];
            #pragma unroll
            for (int j = 0; j < 4; ++j) b[j] = Bs[k][tx * 4 + j];
            #pragma unroll
            for (int i = 0; i < 4; ++i)
                #pragma unroll
                for (int j = 0; j < 4; ++j)
                    acc[i][j] += a[i] * b[j];
        }
        __syncthreads();
    }
    #pragma unroll
    for (int i = 0; i < 4; ++i) {
        float4 v = make_float4(acc[i][0], acc[i][1], acc[i][2], acc[i][3]);
        *(float4*)&C[(size_t)(m0 + ty * 4 + i) * N + n0 + tx * 4] = v;
    }
}

template <int F>
__global__ __launch_bounds__(256)
void sd_kernel(const float* __restrict__ Wh, const float* __restrict__ a,
               float* __restrict__ s, float* __restrict__ d,
               unsigned* __restrict__ dmaxu)
{
    int warp = (blockIdx.x * blockDim.x + threadIdx.x) >> 5;
    int lane = threadIdx.x & 31;
    if (warp >= N_NODES) return;
    const float* row = Wh + (size_t)warp * F;
    float ss = 0.f, dd = 0.f;
    #pragma unroll
    for (int f = lane; f < F; f += 32) {
        float w = row[f];
        ss += w * a[f];
        dd += w * a[F + f];
    }
    #pragma unroll
    for (int o = 16; o; o >>= 1) {
        ss += __shfl_down_sync(0xffffffffu, ss, o);
        dd += __shfl_down_sync(0xffffffffu, dd, o);
    }
    if (lane == 0) {
        s[warp] = ss; d[warp] = dd;
        atomicMax(dmaxu, fenc(dd));
    }
}

__global__ __launch_bounds__(256)
void ef_kernel(const float* __restrict__ d, const unsigned* __restrict__ dmaxu,
               float* __restrict__ E, float* __restrict__ F,
               float* __restrict__ dmaxf)
{
    float dm = fdec(*dmaxu);
    int i = blockIdx.x * 256 + threadIdx.x;
    float v = d[i] - dm;
    E[i] = __expf(v);
    F[i] = __expf(ALPHA * v);
    if (i == 0) *dmaxf = dm;
}

// =============================================================================
// attn1: h = ELU( softmax(mask(leaky(s_i+d_j))) @ Wh1 )
// CTA: m=128 rows x n=128 feature-slice (grid 64 x 2), 512 threads.
// 16 warps: mhalf = w>>3 (rows [64mh,64mh+64)), ncol = (w&7)*16.
// j-tile 64 double-buffered; ldmatrix; 144B row pitch; bf16x3 HMMA.
// =============================================================================
static constexpr int P1      = 144;
static constexpr int S1_B    = 0;          // 2 buf x [hi 128x144 | lo 128x144]
static constexpr int S1_BBUF = 36864;
static constexpr int S1_BLOO = 18432;
static constexpr int S1_A    = 73728;      // 2 buf x [hi 128x144 | lo 128x144]
static constexpr int S1_ABUF = 36864;
static constexpr int S1_ALOO = 18432;
static constexpr int S1_ZT   = 147456;     // 512 floats
static constexpr int S1_ZR   = 149504;     // 128 floats
static constexpr int SMEM1   = 150016;

__global__ __launch_bounds__(512, 1)
void attn1_kernel(const unsigned* __restrict__ adjb,
                  const __nv_bfloat16* __restrict__ Bh,
                  const __nv_bfloat16* __restrict__ Bl,
                  const float* __restrict__ svec, const float* __restrict__ dvec,
                  const float* __restrict__ EJ, const float* __restrict__ FJ,
                  const float* __restrict__ dmaxp, float* __restrict__ outp)
{
    extern __shared__ __align__(16) char smem[];
    const uint32_t sb = smem_u32(smem);
    const int tid = threadIdx.x, warp = tid >> 5, lane = tid & 31;
    const int g = lane >> 2, tq = lane & 3;
    const int i0 = blockIdx.y * 128;
    const int n0cta = blockIdx.x * 128;      // feature slice base
    const int mhalf = warp >> 3;
    const int n0w = (warp & 7) * 16;

    const uint32_t a_lane = ((lane & 7) + ((lane >> 3) & 1) * 8) * P1 + ((lane >> 4) & 1) * 16;
    const uint32_t b_lane = ((lane & 7) + ((lane >> 4) & 1) * 8) * P1 + ((lane >> 3) & 1) * 16;

    const int r = tid >> 2, q = tid & 3;     // row, j-quarter (16 j each)
    const float sv = svec[i0 + r];
    const float mv = sv + *dmaxp;
    const float m_r = mv > 0.f ? mv : ALPHA * mv;
    const float RA = __expf(mv - m_r);
    const float RB = __expf(ALPHA * mv - m_r);
    float zacc = 0.f;

    float acc[4][2][4];
    #pragma unroll
    for (int a = 0; a < 4; ++a)
        #pragma unroll
        for (int b = 0; b < 2; ++b)
            #pragma unroll
            for (int c = 0; c < 4; ++c) acc[a][b][c] = 0.f;

    const size_t row_adj = (size_t)(i0 + r) * NWORDS;

    // prologue: stage B tile 0 (CTA's 128-feature slice, hi+lo) into buffer 0
    for (int c = tid; c < 2048; c += 512) {
        int mat = c >> 10, f = (c >> 3) & 127, ch = c & 7;
        uint32_t dst = sb + S1_B + mat * S1_BLOO + f * P1 + ch * 16;
        const __nv_bfloat16* src = (mat ? Bl : Bh) + (size_t)(n0cta + f) * N_NODES + ch * 8;
        cp_async16(dst, src);
    }
    CP_COMMIT();

    for (int t = 0; t < N_NODES / 64; ++t) {
        const int j0 = t * 64;
        const int buf = t & 1;

        if (t + 1 < N_NODES / 64) {
            const int j1 = j0 + 64;
            const uint32_t bb = sb + S1_B + (buf ^ 1) * S1_BBUF;
            for (int c = tid; c < 2048; c += 512) {
                int mat = c >> 10, f = (c >> 3) & 127, ch = c & 7;
                uint32_t dst = bb + mat * S1_BLOO + f * P1 + ch * 16;
                const __nv_bfloat16* src = (mat ? Bl : Bh)
                                           + (size_t)(n0cta + f) * N_NODES + j1 + ch * 8;
                cp_async16(dst, src);
            }
        }
        CP_COMMIT();

        // ---- P-gen into A[buf]: thread covers (r, j in [q*16, q*16+16)) -----
        {
            unsigned w = adjb[row_adj + (j0 >> 5) + (q >> 1)];
            unsigned bits = w >> ((q & 1) * 16);
            char* ahi = smem + S1_A + buf * S1_ABUF + r * P1;
            char* alo = ahi + S1_ALOO;
            const int jb = q * 16;
            #pragma unroll
            for (int qq = 0; qq < 16; qq += 2) {
                int jl = jb + qq;
                int b0 = (bits >> qq) & 1;
                int b1 = (bits >> (qq + 1)) & 1;
                float d0 = dvec[j0 + jl], d1 = dvec[j0 + jl + 1];
                float p0 = b0 ? ((sv + d0 > 0.f) ? RA * EJ[j0 + jl]     : RB * FJ[j0 + jl])     : 0.f;
                float p1 = b1 ? ((sv + d1 > 0.f) ? RA * EJ[j0 + jl + 1] : RB * FJ[j0 + jl + 1]) : 0.f;
                zacc += p0 + p1;
                __nv_bfloat162 h2 = __floats2bfloat162_rn(p0, p1);
                float l0 = p0 - __bfloat162float(h2.x);
                float l1 = p1 - __bfloat162float(h2.y);
                __nv_bfloat162 lo2 = __floats2bfloat162_rn(l0, l1);
                *(__nv_bfloat162*)(ahi + jl * 2) = h2;
                *(__nv_bfloat162*)(alo + jl * 2) = lo2;
            }
        }

        CP_WAIT1();
        __syncthreads();

        // ---- MMA on buffer buf ----------------------------------------------
        const uint32_t abase = sb + S1_A + buf * S1_ABUF + mhalf * (64 * P1) + a_lane;
        const uint32_t bbase = sb + S1_B + buf * S1_BBUF + n0w * P1 + b_lane;
        #pragma unroll
        for (int kt = 0; kt < 4; ++kt) {
            const int koff = kt * 32;
            uint32_t ah[4][4], al[4][4];
            #pragma unroll
            for (int mi = 0; mi < 4; ++mi)
                ldsm_x4(ah[mi][0], ah[mi][1], ah[mi][2], ah[mi][3],
                        abase + mi * (16 * P1) + koff);
            #pragma unroll
            for (int mi = 0; mi < 4; ++mi)
                ldsm_x4(al[mi][0], al[mi][1], al[mi][2], al[mi][3],
                        abase + S1_ALOO + mi * (16 * P1) + koff);
            uint32_t bh0, bh1, bh2, bh3, bl0, bl1, bl2, bl3;
            ldsm_x4(bh0, bh1, bh2, bh3, bbase + koff);
            ldsm_x4(bl0, bl1, bl2, bl3, bbase + S1_BLOO + koff);
            #pragma unroll
            for (int mi = 0; mi < 4; ++mi) {
                mma16816(acc[mi][0], ah[mi][0], ah[mi][1], ah[mi][2], ah[mi][3], bh0, bh1);
                mma16816(acc[mi][0], ah[mi][0], ah[mi][1], ah[mi][2], ah[mi][3], bl0, bl1);
                mma16816(acc[mi][0], al[mi][0], al[mi][1], al[mi][2], al[mi][3], bh0, bh1);
                mma16816(acc[mi][1], ah[mi][0], ah[mi][1], ah[mi][2], ah[mi][3], bh2, bh3);
                mma16816(acc[mi][1], ah[mi][0], ah[mi][1], ah[mi][2], ah[mi][3], bl2, bl3);
                mma16816(acc[mi][1], al[mi][0], al[mi][1], al[mi][2], al[mi][3], bh2, bh3);
            }
        }
        __syncthreads();
    }

    // ---- epilogue --------------------------------------------------------------
    float* zt = (float*)(smem + S1_ZT);
    float* zr = (float*)(smem + S1_ZR);
    zt[tid] = zacc;
    __syncthreads();
    if (tid < 128)
        zr[tid] = zt[4 * tid] + zt[4 * tid + 1] + zt[4 * tid + 2] + zt[4 * tid + 3];
    __syncthreads();
    #pragma unroll
    for (int mi = 0; mi < 4; ++mi) {
        int r0 = mhalf * 64 + mi * 16 + g;
        float iz0 = 1.f / zr[r0];
        float iz1 = 1.f / zr[r0 + 8];
        #pragma unroll
        for (int ni = 0; ni < 2; ++ni) {
            int col = n0cta + n0w + ni * 8 + tq * 2;
            float v0 = acc[mi][ni][0] * iz0; v0 = v0 > 0.f ? v0 : expm1f(v0);
            float v1 = acc[mi][ni][1] * iz0; v1 = v1 > 0.f ? v1 : expm1f(v1);
            float v2 = acc[mi][ni][2] * iz1; v2 = v2 > 0.f ? v2 : expm1f(v2);
            float v3 = acc[mi][ni][3] * iz1; v3 = v3 > 0.f ? v3 : expm1f(v3);
            *(float2*)&outp[(size_t)(i0 + r0) * NHID + col]     = make_float2(v0, v1);
            *(float2*)&outp[(size_t)(i0 + r0 + 8) * NHID + col] = make_float2(v2, v3);
        }
    }
}

// =============================================================================
// attn23: mu OR lv attention per CTA (grid 64 x 2), m=128, F=64. 512 threads.
// 16 warps: mhalf = w>>3, n8-col = (w&7)*8.
// =============================================================================
static constexpr int S2_B    = 0;          // 2 buf x [hi 64x144 | lo 64x144]
static constexpr int S2_BBUF = 18432;
static constexpr int S2_BLOO = 9216;
static constexpr int S2_A    = 36864;      // 2 buf x [hi 128x144 | lo 128x144]
static constexpr int S2_ABUF = 36864;
static constexpr int S2_ALOO = 18432;
static constexpr int S2_ZT   = 110592;     // 512 floats
static constexpr int S2_ZR   = 112640;     // 128 floats
static constexpr int SMEM2   = 113152;

__global__ __launch_bounds__(512, 1)
void attn23_kernel(const unsigned* __restrict__ adjb,
                   const __nv_bfloat16* __restrict__ Bmh, const __nv_bfloat16* __restrict__ Bml,
                   const __nv_bfloat16* __restrict__ Bvh, const __nv_bfloat16* __restrict__ Bvl,
                   const float* __restrict__ smuv, const float* __restrict__ dmuv,
                   const float* __restrict__ slvv, const float* __restrict__ dlvv,
                   const float* __restrict__ Em, const float* __restrict__ Fm,
                   const float* __restrict__ Ev, const float* __restrict__ Fv,
                   const float* __restrict__ dmaxp,   // [0]=mu, [1]=lv
                   float* __restrict__ out_mu, float* __restrict__ out_lv)
{
    extern __shared__ __align__(16) char smem[];
    const uint32_t sb = smem_u32(smem);
    const int tid = threadIdx.x, warp = tid >> 5, lane = tid & 31;
    const int g = lane >> 2, tq = lane & 3;
    const int which = blockIdx.x;            // 0 = mu, 1 = lv
    const int i0 = blockIdx.y * 128;
    const int mhalf = warp >> 3;
    const int n0w = (warp & 7) * 8;

    const __nv_bfloat16* BhM = which ? Bvh : Bmh;
    const __nv_bfloat16* BlM = which ? Bvl : Bml;
    const float* svp = which ? slvv : smuv;
    const float* dvp = which ? dlvv : dmuv;
    const float* Ep  = which ? Ev : Em;
    const float* Fp  = which ? Fv : Fm;

    const uint32_t a_lane = ((lane & 7) + ((lane >> 3) & 1) * 8) * P1 + ((lane >> 4) & 1) * 16;
    const uint32_t b_lane = (lane & 7) * P1 + ((lane >> 3) & 1) * 16;   // x2: lanes 0-15

    const int r = tid >> 2, q = tid & 3;
    const float sv = svp[i0 + r];
    const float mv = sv + dmaxp[which];
    const float m_r = mv > 0.f ? mv : ALPHA * mv;
    const float RA = __expf(mv - m_r);
    const float RB = __expf(ALPHA * mv - m_r);
    float zacc = 0.f;

    float acc[4][4];
    #pragma unroll
    for (int a = 0; a < 4; ++a)
        #pragma unroll
        for (int c = 0; c < 4; ++c) acc[a][c] = 0.f;

    const size_t row_adj = (size_t)(i0 + r) * NWORDS;

    // prologue: stage B tile 0 (hi+lo, 64 f-rows)
    for (int c = tid; c < 1024; c += 512) {
        int mat = c >> 9, f = (c >> 3) & 63, ch = c & 7;
        uint32_t dst = sb + S2_B + mat * S2_BLOO + f * P1 + ch * 16;
        const __nv_bfloat16* src = (mat ? BlM : BhM) + (size_t)f * N_NODES + ch * 8;
        cp_async16(dst, src);
    }
    CP_COMMIT();

    for (int t = 0; t < N_NODES / 64; ++t) {
        const int j0 = t * 64;
        const int buf = t & 1;

        if (t + 1 < N_NODES / 64) {
            const int j1 = j0 + 64;
            const uint32_t bbs = sb + S2_B + (buf ^ 1) * S2_BBUF;
            for (int c = tid; c < 1024; c += 512) {
                int mat = c >> 9, f = (c >> 3) & 63, ch = c & 7;
                uint32_t dst = bbs + mat * S2_BLOO + f * P1 + ch * 16;
                const __nv_bfloat16* src = (mat ? BlM : BhM)
                                           + (size_t)f * N_NODES + j1 + ch * 8;
                cp_async16(dst, src);
            }
        }
        CP_COMMIT();

        // ---- P-gen: thread covers (r, j in [q*16, q*16+16)) -----------------
        {
            unsigned w = adjb[row_adj + (j0 >> 5) + (q >> 1)];
            unsigned bits = w >> ((q & 1) * 16);
            char* ahi = smem + S2_A + buf * S2_ABUF + r * P1;
            char* alo = ahi + S2_ALOO;
            const int jb = q * 16;
            #pragma unroll
            for (int qq = 0; qq < 16; qq += 2) {
                int jl = jb + qq;
                int b0 = (bits >> qq) & 1;
                int b1 = (bits >> (qq + 1)) & 1;
                float d0 = dvp[j0 + jl], d1 = dvp[j0 + jl + 1];
                float p0 = b0 ? ((sv + d0 > 0.f) ? RA * Ep[j0 + jl]     : RB * Fp[j0 + jl])     : 0.f;
                float p1 = b1 ? ((sv + d1 > 0.f) ? RA * Ep[j0 + jl + 1] : RB * Fp[j0 + jl + 1]) : 0.f;
                zacc += p0 + p1;
                __nv_bfloat162 h2 = __floats2bfloat162_rn(p0, p1);
                float l0 = p0 - __bfloat162float(h2.x);
                float l1 = p1 - __bfloat162float(h2.y);
                __nv_bfloat162 lo2 = __floats2bfloat162_rn(l0, l1);
                *(__nv_bfloat162*)(ahi + jl * 2) = h2;
                *(__nv_bfloat162*)(alo + jl * 2) = lo2;
            }
        }

        CP_WAIT1();
        __syncthreads();

        // ---- MMA --------------------------------------------------------------
        const uint32_t abase = sb + S2_A + buf * S2_ABUF + mhalf * (64 * P1) + a_lane;
        const uint32_t bbase = sb + S2_B + buf * S2_BBUF + n0w * P1 + b_lane;
        #pragma unroll
        for (int kt = 0; kt < 4; ++kt) {
            const int koff = kt * 32;
            uint32_t ah[4][4], al[4][4];
            #pragma unroll
            for (int mi = 0; mi < 4; ++mi)
                ldsm_x4(ah[mi][0], ah[mi][1], ah[mi][2], ah[mi][3],
                        abase + mi * (16 * P1) + koff);
            #pragma unroll
            for (int mi = 0; mi < 4; ++mi)
                ldsm_x4(al[mi][0], al[mi][1], al[mi][2], al[mi][3],
                        abase + S2_ALOO + mi * (16 * P1) + koff);
            uint32_t bh0, bh1, bl0, bl1;
            ldsm_x2(bh0, bh1, bbase + koff);
            ldsm_x2(bl0, bl1, bbase + S2_BLOO + koff);
            #pragma unroll
            for (int mi = 0; mi < 4; ++mi) {
                mma16816(acc[mi], ah[mi][0], ah[mi][1], ah[mi][2], ah[mi][3], bh0, bh1);
                mma16816(acc[mi], ah[mi][0], ah[mi][1], ah[mi][2], ah[mi][3], bl0, bl1);
                mma16816(acc[mi], al[mi][0], al[mi][1], al[mi][2], al[mi][3], bh0, bh1);
            }
        }
        __syncthreads();
    }

    // epilogue
    float* zt = (float*)(smem + S2_ZT);
    float* zr = (float*)(smem + S2_ZR);
    zt[tid] = zacc;
    __syncthreads();
    if (tid < 128)
        zr[tid] = zt[4 * tid] + zt[4 * tid + 1] + zt[4 * tid + 2] + zt[4 * tid + 3];
    __syncthreads();
    float* outw = which ? out_lv : out_mu;
    #pragma unroll
    for (int mi = 0; mi < 4; ++mi) {
        int r0 = mhalf * 64 + mi * 16 + g;
        float iz0 = 1.f / zr[r0];
        float iz1 = 1.f / zr[r0 + 8];
        int col = n0w + tq * 2;
        *(float2*)&outw[(size_t)(i0 + r0) * NLAT + col] =
            make_float2(acc[mi][0] * iz0, acc[mi][1] * iz0);
        *(float2*)&outw[(size_t)(i0 + r0 + 8) * NLAT + col] =
            make_float2(acc[mi][2] * iz1, acc[mi][3] * iz1);
    }
}

// ---------------- z = mu + eps*exp(0.5*lv); logits = z @ Wc + bc ------------
__global__ __launch_bounds__(128)
void final_kernel(const float* __restrict__ mu, const float* __restrict__ lv,
                  const float* __restrict__ eps, const float* __restrict__ Wc,
                  const float* __restrict__ bc, float* __restrict__ logits)
{
    __shared__ float zs[8 * 64];
    const int tid = threadIdx.x;
    const int r0 = blockIdx.x * 8;
    #pragma unroll
    for (int l = tid; l < 8 * 64; l += 128) {
        int r = l >> 6, k = l & 63;
        size_t idx = (size_t)(r0 + r) * 64 + k;
        zs[l] = mu[idx] + eps[idx] * __expf(0.5f * lv[idx]);
    }
    __syncthreads();
    int r = tid >> 4, n = tid & 15;
    float acc = bc[n];
    #pragma unroll
    for (int k = 0; k < 64; ++k) acc += zs[r * 64 + k] * Wc[k * 16 + n];
    logits[(size_t)(r0 + r) * 16 + n] = acc;
}

// ------------------------------ launch --------------------------------------
extern "C" void kernel_launch(void* const* d_in, const int* in_sizes, int n_in,
                              void* d_out, int out_size)
{
    const float* x   = (const float*)d_in[0];
    const int*   adj = (const int*)  d_in[1];
    const float* eps = (const float*)d_in[2];
    const float* W1  = (const float*)d_in[3];
    const float* a1  = (const float*)d_in[4];
    const float* Wmu = (const float*)d_in[5];
    const float* amu = (const float*)d_in[6];
    const float* Wlv = (const float*)d_in[7];
    const float* alv = (const float*)d_in[8];
    const float* Wc  = (const float*)d_in[9];
    const float* bc  = (const float*)d_in[10];

    float* out    = (float*)d_out;
    float* logits = out;
    float* mu     = out + (size_t)N_NODES * NCLASS;
    float* lv     = mu  + (size_t)N_NODES * NLAT;

    float *Wh1, *h, *Whmu, *Whlv, *s1, *d1, *smu, *dmu, *slv, *dlv;
    float *E1, *F1, *Emu, *Fmu, *Elv, *Flv, *dmaxf;
    unsigned *dmaxu;
    __nv_bfloat16 *T1h, *T1l, *Tmh, *Tml, *Tvh, *Tvl;
    unsigned* adjb;
    cudaGetSymbolAddress((void**)&Wh1,  g_Wh1);
    cudaGetSymbolAddress((void**)&h,    g_h);
    cudaGetSymbolAddress((void**)&Whmu, g_Whmu);
    cudaGetSymbolAddress((void**)&Whlv, g_Whlv);
    cudaGetSymbolAddress((void**)&s1,   g_s1);
    cudaGetSymbolAddress((void**)&d1,   g_d1);
    cudaGetSymbolAddress((void**)&smu,  g_smu);
    cudaGetSymbolAddress((void**)&dmu,  g_dmu);
    cudaGetSymbolAddress((void**)&slv,  g_slv);
    cudaGetSymbolAddress((void**)&dlv,  g_dlv);
    cudaGetSymbolAddress((void**)&dmaxu, g_dmaxu);
    cudaGetSymbolAddress((void**)&dmaxf, g_dmaxf);
    cudaGetSymbolAddress((void**)&E1,   g_E1);
    cudaGetSymbolAddress((void**)&F1,   g_F1);
    cudaGetSymbolAddress((void**)&Emu,  g_Emu);
    cudaGetSymbolAddress((void**)&Fmu,  g_Fmu);
    cudaGetSymbolAddress((void**)&Elv,  g_Elv);
    cudaGetSymbolAddress((void**)&Flv,  g_Flv);
    cudaGetSymbolAddress((void**)&T1h,  g_T1h);
    cudaGetSymbolAddress((void**)&T1l,  g_T1l);
    cudaGetSymbolAddress((void**)&Tmh,  g_Tmh);
    cudaGetSymbolAddress((void**)&Tml,  g_Tml);
    cudaGetSymbolAddress((void**)&Tvh,  g_Tvh);
    cudaGetSymbolAddress((void**)&Tvl,  g_Tvl);
    cudaGetSymbolAddress((void**)&adjb, g_adjb);

    cudaFuncSetAttribute(attn1_kernel,  cudaFuncAttributeMaxDynamicSharedMemorySize, SMEM1);
    cudaFuncSetAttribute(attn23_kernel, cudaFuncAttributeMaxDynamicSharedMemorySize, SMEM2);

    init_kernel<<<1, 32>>>(dmaxu);
    pack_adj_kernel<<<(size_t)N_NODES * N_NODES / 256, 256>>>(adj, adjb);

    // layer 1
    gemm_kernel<<<dim3(NHID / 64, N_NODES / 64), 256>>>(x, W1, Wh1, N_NODES, NHID, NFEAT);
    sd_kernel<NHID><<<N_NODES * 32 / 256, 256>>>(Wh1, a1, s1, d1, dmaxu + 0);
    ef_kernel<<<N_NODES / 256, 256>>>(d1, dmaxu + 0, E1, F1, dmaxf + 0);
    tsplit_kernel<<<dim3(NHID / 32, N_NODES / 32), 256>>>(Wh1, T1h, T1l, NHID);
    attn1_kernel<<<dim3(2, N_NODES / 128), 512, SMEM1>>>(adjb, T1h, T1l, s1, d1,
                                                         E1, F1, dmaxf + 0, h);

    // layer 2/3
    gemm_kernel<<<dim3(NLAT / 64, N_NODES / 64), 256>>>(h, Wmu, Whmu, N_NODES, NLAT, NHID);
    gemm_kernel<<<dim3(NLAT / 64, N_NODES / 64), 256>>>(h, Wlv, Whlv, N_NODES, NLAT, NHID);
    sd_kernel<NLAT><<<N_NODES * 32 / 256, 256>>>(Whmu, amu, smu, dmu, dmaxu + 1);
    sd_kernel<NLAT><<<N_NODES * 32 / 256, 256>>>(Whlv, alv, slv, dlv, dmaxu + 2);
    ef_kernel<<<N_NODES / 256, 256>>>(dmu, dmaxu + 1, Emu, Fmu, dmaxf + 1);
    ef_kernel<<<N_NODES / 256, 256>>>(dlv, dmaxu + 2, Elv, Flv, dmaxf + 2);
    tsplit_kernel<<<dim3(NLAT / 32, N_NODES / 32), 256>>>(Whmu, Tmh, Tml, NLAT);
    tsplit_kernel<<<dim3(NLAT / 32, N_NODES / 32), 256>>>(Whlv, Tvh, Tvl, NLAT);
    attn23_kernel<<<dim3(2, N_NODES / 128), 512, SMEM2>>>(adjb, Tmh, Tml, Tvh, Tvl,
                                                          smu, dmu, slv, dlv,
                                                          Emu, Fmu, Elv, Flv,
                                                          dmaxf + 1, mu, lv);

    // reparameterize + classifier
    final_kernel<<<N_NODES / 8, 128>>>(mu, lv, eps, Wc, bc, logits);
}

// round 11
// speedup vs baseline: 1.1374x; 1.1374x over previous
#include <cuda_runtime.h>
#include <cuda_bf16.h>
#include <cuda_fp16.h>
#include <math.h>
#include <stdint.h>

#define N_NODES 8192
#define NFEAT   512
#define NHID    256
#define NLAT    64
#define NCLASS  16
#define ALPHA   0.2f
#define NWORDS  (N_NODES / 32)

// ------------------------------ device scratch ------------------------------
__device__ __align__(16) float g_Wh1 [N_NODES * NHID];
__device__ __align__(16) float g_h   [N_NODES * NHID];
__device__ __align__(16) float g_Whmu[N_NODES * NLAT];
__device__ __align__(16) float g_Whlv[N_NODES * NLAT];
__device__ __align__(16) __half g_T1[NHID * N_NODES];   // Wh1^T fp16 [F][N]
__device__ __align__(16) __half g_Tm[NLAT * N_NODES];
__device__ __align__(16) __half g_Tv[NLAT * N_NODES];
__device__ unsigned g_adjb[(size_t)N_NODES * NWORDS];
__device__ float g_s1[N_NODES], g_d1[N_NODES];
__device__ float g_smu[N_NODES], g_dmu[N_NODES];
__device__ float g_slv[N_NODES], g_dlv[N_NODES];
__device__ __align__(16) float g_E1[N_NODES],  g_F1[N_NODES];
__device__ __align__(16) float g_Emu[N_NODES], g_Fmu[N_NODES];
__device__ __align__(16) float g_Elv[N_NODES], g_Flv[N_NODES];
__device__ unsigned g_dmaxu[4];
__device__ float    g_dmaxf[4];

// ------------------------------ helpers -------------------------------------
__device__ __forceinline__ uint32_t smem_u32(const void* p) {
    uint32_t a;
    asm("{ .reg .u64 t; cvta.to.shared.u64 t, %1; cvt.u32.u64 %0, t; }"
        : "=r"(a) : "l"(p));
    return a;
}
__device__ __forceinline__ void cp_async16(uint32_t dst, const void* src) {
    asm volatile("cp.async.cg.shared.global [%0], [%1], 16;"
                 :: "r"(dst), "l"(src) : "memory");
}
#define CP_COMMIT() asm volatile("cp.async.commit_group;" ::: "memory")
#define CP_WAIT1()  asm volatile("cp.async.wait_group 1;"  ::: "memory")

__device__ __forceinline__ unsigned fenc(float x) {
    int ix = __float_as_int(x);
    return ix >= 0 ? ((unsigned)ix | 0x80000000u) : ~(unsigned)ix;
}
__device__ __forceinline__ float fdec(unsigned u) {
    int ix = (u & 0x80000000u) ? (int)(u & 0x7FFFFFFFu) : ~(int)u;
    return __int_as_float(ix);
}

// mma.sync m16n8k16 row.col f16 -> f32 (HMMA on sm_103)
__device__ __forceinline__ void mma16816(float* c,
    uint32_t a0, uint32_t a1, uint32_t a2, uint32_t a3,
    uint32_t b0, uint32_t b1)
{
    asm volatile(
        "mma.sync.aligned.m16n8k16.row.col.f32.f16.f16.f32 "
        "{%0,%1,%2,%3}, {%4,%5,%6,%7}, {%8,%9}, {%0,%1,%2,%3};"
        : "+f"(c[0]), "+f"(c[1]), "+f"(c[2]), "+f"(c[3])
        : "r"(a0), "r"(a1), "r"(a2), "r"(a3), "r"(b0), "r"(b1));
}
__device__ __forceinline__ void ldsm_x4(uint32_t& r0, uint32_t& r1,
                                        uint32_t& r2, uint32_t& r3, uint32_t addr)
{
    asm volatile("ldmatrix.sync.aligned.m8n8.x4.shared.b16 {%0,%1,%2,%3}, [%4];"
                 : "=r"(r0), "=r"(r1), "=r"(r2), "=r"(r3) : "r"(addr));
}
__device__ __forceinline__ void ldsm_x2(uint32_t& r0, uint32_t& r1, uint32_t addr)
{
    asm volatile("ldmatrix.sync.aligned.m8n8.x2.shared.b16 {%0,%1}, [%2];"
                 : "=r"(r0), "=r"(r1) : "r"(addr));
}

// ------------------------------ utility kernels -----------------------------
__global__ __launch_bounds__(256)
void pack_adj_kernel(const int* __restrict__ adj, unsigned* __restrict__ bits,
                     unsigned* __restrict__ dmaxu)
{
    if (blockIdx.x == 0 && threadIdx.x < 4) dmaxu[threadIdx.x] = 0u;
    size_t idx = (size_t)blockIdx.x * 256 + threadIdx.x;
    int v = adj[idx] > 0;
    unsigned b = __ballot_sync(0xffffffffu, v);
    if ((threadIdx.x & 31) == 0) bits[idx >> 5] = b;
}

// transpose + fp16 convert: in[N][F] fp32 -> T [F][N] fp16
__global__ __launch_bounds__(256)
void tconv_kernel(const float* __restrict__ in, __half* __restrict__ T, int F)
{
    __shared__ float tile[32][33];
    int m0 = blockIdx.y * 32, f0 = blockIdx.x * 32;
    int x = threadIdx.x & 31, y = threadIdx.x >> 5;
    #pragma unroll
    for (int yy = 0; yy < 4; ++yy)
        tile[y + yy * 8][x] = in[(size_t)(m0 + y + yy * 8) * F + f0 + x];
    __syncthreads();
    #pragma unroll
    for (int yy = 0; yy < 4; ++yy) {
        float v = tile[x][y + yy * 8];
        T[(size_t)(f0 + y + yy * 8) * N_NODES + m0 + x] = __float2half_rn(v);
    }
}

__global__ __launch_bounds__(256)
void gemm_kernel(const float* __restrict__ A, const float* __restrict__ B,
                 float* __restrict__ C, int M, int N, int K)
{
    __shared__ float As[16][64];
    __shared__ float Bs[16][64];
    const int tid = threadIdx.x;
    const int tx = tid & 15, ty = tid >> 4;
    const int m0 = blockIdx.y * 64, n0 = blockIdx.x * 64;
    float acc[4][4] = {};
    for (int k0 = 0; k0 < K; k0 += 16) {
        {
            int m = tid >> 2, kq = (tid & 3) * 4;
            float4 v = *(const float4*)&A[(size_t)(m0 + m) * K + k0 + kq];
            As[kq + 0][m] = v.x; As[kq + 1][m] = v.y;
            As[kq + 2][m] = v.z; As[kq + 3][m] = v.w;
        }
        {
            int k = tid >> 4, nq = (tid & 15) * 4;
            *(float4*)&Bs[k][nq] = *(const float4*)&B[(size_t)(k0 + k) * N + n0 + nq];
        }
        __syncthreads();
        #pragma unroll
        for (int k = 0; k < 16; ++k) {
            float a[4], b[4];
            #pragma unroll
            for (int i = 0; i < 4; ++i) a[i] = As[k][ty * 4 + i];
            #pragma unroll
            for (int j = 0; j < 4; ++j) b[j] = Bs[k][tx * 4 + j];
            #pragma unroll
            for (int i = 0; i < 4; ++i)
                #pragma unroll
                for (int j = 0; j < 4; ++j)
                    acc[i][j] += a[i] * b[j];
        }
        __syncthreads();
    }
    #pragma unroll
    for (int i = 0; i < 4; ++i) {
        float4 v = make_float4(acc[i][0], acc[i][1], acc[i][2], acc[i][3]);
        *(float4*)&C[(size_t)(m0 + ty * 4 + i) * N + n0 + tx * 4] = v;
    }
}

template <int F>
__global__ __launch_bounds__(256)
void sd_kernel(const float* __restrict__ Wh, const float* __restrict__ a,
               float* __restrict__ s, float* __restrict__ d,
               unsigned* __restrict__ dmaxu)
{
    int warp = (blockIdx.x * blockDim.x + threadIdx.x) >> 5;
    int lane = threadIdx.x & 31;
    if (warp >= N_NODES) return;
    const float* row = Wh + (size_t)warp * F;
    float ss = 0.f, dd = 0.f;
    #pragma unroll
    for (int f = lane; f < F; f += 32) {
        float w = row[f];
        ss += w * a[f];
        dd += w * a[F + f];
    }
    #pragma unroll
    for (int o = 16; o; o >>= 1) {
        ss += __shfl_down_sync(0xffffffffu, ss, o);
        dd += __shfl_down_sync(0xffffffffu, dd, o);
    }
    if (lane == 0) {
        s[warp] = ss; d[warp] = dd;
        atomicMax(dmaxu, fenc(dd));
    }
}

__global__ __launch_bounds__(256)
void ef_kernel(const float* __restrict__ d, const unsigned* __restrict__ dmaxu,
               float* __restrict__ E, float* __restrict__ F,
               float* __restrict__ dmaxf)
{
    float dm = fdec(*dmaxu);
    int i = blockIdx.x * 256 + threadIdx.x;
    float v = d[i] - dm;
    E[i] = __expf(v);
    F[i] = __expf(ALPHA * v);
    if (i == 0) *dmaxf = dm;
}

// =============================================================================
// attn1: h = ELU( softmax(mask(leaky(s_i+d_j))) @ Wh1 )  F=256, fp16 2-product
// CTA 64 rows, 512 threads (16 warps; warp w -> cols [16w,16w+16)).
// j-tile 64 double-buffered; ldmatrix; 144B row pitch.
// =============================================================================
static constexpr int P1      = 144;
static constexpr int S1_B    = 0;          // 2 buf x 256x144 (W fp16)
static constexpr int S1_BBUF = 36864;
static constexpr int S1_A    = 73728;      // 2 buf x [hi 64x144 | lo 64x144]
static constexpr int S1_ABUF = 18432;
static constexpr int S1_ALOO = 9216;
static constexpr int S1_ZT   = 110592;     // 512 floats
static constexpr int S1_ZR   = 112640;     // 64 floats
static constexpr int SMEM1   = 112896;

__global__ __launch_bounds__(512, 1)
void attn1_kernel(const unsigned* __restrict__ adjb,
                  const __half* __restrict__ BT,
                  const float* __restrict__ svec, const float* __restrict__ dvec,
                  const float* __restrict__ EJ, const float* __restrict__ FJ,
                  const float* __restrict__ dmaxp, float* __restrict__ outp)
{
    extern __shared__ __align__(16) char smem[];
    const uint32_t sb = smem_u32(smem);
    const int tid = threadIdx.x, warp = tid >> 5, lane = tid & 31;
    const int g = lane >> 2, tq = lane & 3;
    const int i0 = blockIdx.x * 64;
    const int n0w = warp * 16;

    const uint32_t a_lane = ((lane & 7) + ((lane >> 3) & 1) * 8) * P1 + ((lane >> 4) & 1) * 16;
    const uint32_t b_lane = ((lane & 7) + ((lane >> 4) & 1) * 8) * P1 + ((lane >> 3) & 1) * 16;

    const int r = tid >> 3, q = tid & 7;
    const float sv = svec[i0 + r];
    const float mv = sv + *dmaxp;
    const float m_r = mv > 0.f ? mv : ALPHA * mv;
    const float RA = __expf(mv - m_r);
    const float RB = __expf(ALPHA * mv - m_r);
    float zacc = 0.f;

    float acc[4][2][4];
    #pragma unroll
    for (int a = 0; a < 4; ++a)
        #pragma unroll
        for (int b = 0; b < 2; ++b)
            #pragma unroll
            for (int c = 0; c < 4; ++c) acc[a][b][c] = 0.f;

    const size_t row_adj = (size_t)(i0 + r) * NWORDS;

    // prologue: stage B tile 0 (256 f-rows x 64 j fp16 = 2048 chunks)
    for (int c = tid; c < 2048; c += 512) {
        int f = c >> 3, ch = c & 7;
        uint32_t dst = sb + S1_B + f * P1 + ch * 16;
        cp_async16(dst, BT + (size_t)f * N_NODES + ch * 8);
    }
    CP_COMMIT();

    for (int t = 0; t < N_NODES / 64; ++t) {
        const int j0 = t * 64;
        const int buf = t & 1;

        if (t + 1 < N_NODES / 64) {
            const int j1 = j0 + 64;
            const uint32_t bb = sb + S1_B + (buf ^ 1) * S1_BBUF;
            for (int c = tid; c < 2048; c += 512) {
                int f = c >> 3, ch = c & 7;
                cp_async16(bb + f * P1 + ch * 16, BT + (size_t)f * N_NODES + j1 + ch * 8);
            }
        }
        CP_COMMIT();

        // ---- P-gen into A[buf]: thread covers (r, j in [q*8, q*8+8)) --------
        {
            unsigned w = adjb[row_adj + (j0 >> 5) + (q >> 2)];
            unsigned bits = w >> ((q & 3) * 8);
            char* ahi = smem + S1_A + buf * S1_ABUF + r * P1;
            char* alo = ahi + S1_ALOO;
            const int jb = q * 8;
            #pragma unroll
            for (int qq = 0; qq < 8; qq += 2) {
                int jl = jb + qq;
                int b0 = (bits >> qq) & 1;
                int b1 = (bits >> (qq + 1)) & 1;
                float d0 = dvec[j0 + jl], d1 = dvec[j0 + jl + 1];
                float p0 = b0 ? ((sv + d0 > 0.f) ? RA * EJ[j0 + jl]     : RB * FJ[j0 + jl])     : 0.f;
                float p1 = b1 ? ((sv + d1 > 0.f) ? RA * EJ[j0 + jl + 1] : RB * FJ[j0 + jl + 1]) : 0.f;
                zacc += p0 + p1;
                __half2 h2 = __floats2half2_rn(p0, p1);
                float l0 = p0 - __half2float(__low2half(h2));
                float l1 = p1 - __half2float(__high2half(h2));
                __half2 lo2 = __floats2half2_rn(l0, l1);
                *(__half2*)(ahi + jl * 2) = h2;
                *(__half2*)(alo + jl * 2) = lo2;
            }
        }

        CP_WAIT1();
        __syncthreads();

        // ---- MMA on buffer buf ----------------------------------------------
        const uint32_t abase = sb + S1_A + buf * S1_ABUF + a_lane;
        const uint32_t bbase = sb + S1_B + buf * S1_BBUF + n0w * P1 + b_lane;
        #pragma unroll
        for (int kt = 0; kt < 4; ++kt) {
            const int koff = kt * 32;
            uint32_t ah[4][4], al[4][4];
            #pragma unroll
            for (int mi = 0; mi < 4; ++mi)
                ldsm_x4(ah[mi][0], ah[mi][1], ah[mi][2], ah[mi][3],
                        abase + mi * (16 * P1) + koff);
            #pragma unroll
            for (int mi = 0; mi < 4; ++mi)
                ldsm_x4(al[mi][0], al[mi][1], al[mi][2], al[mi][3],
                        abase + S1_ALOO + mi * (16 * P1) + koff);
            uint32_t b0, b1, b2, b3;
            ldsm_x4(b0, b1, b2, b3, bbase + koff);
            #pragma unroll
            for (int mi = 0; mi < 4; ++mi) {
                mma16816(acc[mi][0], ah[mi][0], ah[mi][1], ah[mi][2], ah[mi][3], b0, b1);
                mma16816(acc[mi][0], al[mi][0], al[mi][1], al[mi][2], al[mi][3], b0, b1);
                mma16816(acc[mi][1], ah[mi][0], ah[mi][1], ah[mi][2], ah[mi][3], b2, b3);
                mma16816(acc[mi][1], al[mi][0], al[mi][1], al[mi][2], al[mi][3], b2, b3);
            }
        }
        __syncthreads();
    }

    // ---- epilogue --------------------------------------------------------------
    float* zt = (float*)(smem + S1_ZT);
    float* zr = (float*)(smem + S1_ZR);
    zt[tid] = zacc;
    __syncthreads();
    if (tid < 64) {
        float z = 0.f;
        #pragma unroll
        for (int k = 0; k < 8; ++k) z += zt[8 * tid + k];
        zr[tid] = z;
    }
    __syncthreads();
    #pragma unroll
    for (int mi = 0; mi < 4; ++mi) {
        int r0 = mi * 16 + g;
        float iz0 = 1.f / zr[r0];
        float iz1 = 1.f / zr[r0 + 8];
        #pragma unroll
        for (int ni = 0; ni < 2; ++ni) {
            int col = n0w + ni * 8 + tq * 2;
            float v0 = acc[mi][ni][0] * iz0; v0 = v0 > 0.f ? v0 : expm1f(v0);
            float v1 = acc[mi][ni][1] * iz0; v1 = v1 > 0.f ? v1 : expm1f(v1);
            float v2 = acc[mi][ni][2] * iz1; v2 = v2 > 0.f ? v2 : expm1f(v2);
            float v3 = acc[mi][ni][3] * iz1; v3 = v3 > 0.f ? v3 : expm1f(v3);
            *(float2*)&outp[(size_t)(i0 + r0) * NHID + col]     = make_float2(v0, v1);
            *(float2*)&outp[(size_t)(i0 + r0 + 8) * NHID + col] = make_float2(v2, v3);
        }
    }
}

// =============================================================================
// attn23: fused mu & lv attention, F=64 each, fp16 2-product. 512 threads.
// warps 0-7: mu cols [8w..8w+8); warps 8-15: lv.
// =============================================================================
static constexpr int S2_B    = 0;          // 2 buf x [mu 64x144 | lv 64x144]
static constexpr int S2_BBUF = 18432;
static constexpr int S2_BMAT = 9216;
static constexpr int S2_A    = 36864;      // 2 buf x [muh|mul|lvh|lvl] 64x144 each
static constexpr int S2_ABUF = 36864;
static constexpr int S2_AMAT = 9216;
static constexpr int S2_ZT   = 110592;     // 2 x 512 floats
static constexpr int S2_ZR   = 114688;     // 2 x 64 floats
static constexpr int SMEM2   = 115200;

__global__ __launch_bounds__(512, 1)
void attn23_kernel(const unsigned* __restrict__ adjb,
                   const __half* __restrict__ Bm, const __half* __restrict__ Bv,
                   const float* __restrict__ smuv, const float* __restrict__ dmuv,
                   const float* __restrict__ slvv, const float* __restrict__ dlvv,
                   const float* __restrict__ Em, const float* __restrict__ Fm,
                   const float* __restrict__ Ev, const float* __restrict__ Fv,
                   const float* __restrict__ dmaxp,   // [0]=mu, [1]=lv
                   float* __restrict__ out_mu, float* __restrict__ out_lv)
{
    extern __shared__ __align__(16) char smem[];
    const uint32_t sb = smem_u32(smem);
    const int tid = threadIdx.x, warp = tid >> 5, lane = tid & 31;
    const int g = lane >> 2, tq = lane & 3;
    const int i0 = blockIdx.x * 64;
    const int which = warp >> 3;          // 0 = mu, 1 = lv
    const int n0w = (warp & 7) * 8;

    const uint32_t a_lane = ((lane & 7) + ((lane >> 3) & 1) * 8) * P1 + ((lane >> 4) & 1) * 16;
    const uint32_t b_lane = (lane & 7) * P1 + ((lane >> 3) & 1) * 16;   // x2: lanes 0-15

    const int r = tid >> 3, q = tid & 7;
    const float svm = smuv[i0 + r], svv = slvv[i0 + r];
    const float mvm = svm + dmaxp[0], mvv = svv + dmaxp[1];
    const float mm = mvm > 0.f ? mvm : ALPHA * mvm;
    const float ml = mvv > 0.f ? mvv : ALPHA * mvv;
    const float RAm = __expf(mvm - mm), RBm = __expf(ALPHA * mvm - mm);
    const float RAv = __expf(mvv - ml), RBv = __expf(ALPHA * mvv - ml);
    float zm = 0.f, zv = 0.f;

    float acc[4][4];
    #pragma unroll
    for (int a = 0; a < 4; ++a)
        #pragma unroll
        for (int c = 0; c < 4; ++c) acc[a][c] = 0.f;

    const size_t row_adj = (size_t)(i0 + r) * NWORDS;

    // prologue: stage B tile 0 (mu + lv, 64 f-rows each = 1024 chunks)
    for (int c = tid; c < 1024; c += 512) {
        int mat = c >> 9, f = (c >> 3) & 63, ch = c & 7;
        uint32_t dst = sb + S2_B + mat * S2_BMAT + f * P1 + ch * 16;
        const __half* src = (mat ? Bv : Bm) + (size_t)f * N_NODES + ch * 8;
        cp_async16(dst, src);
    }
    CP_COMMIT();

    for (int t = 0; t < N_NODES / 64; ++t) {
        const int j0 = t * 64;
        const int buf = t & 1;

        if (t + 1 < N_NODES / 64) {
            const int j1 = j0 + 64;
            const uint32_t bbs = sb + S2_B + (buf ^ 1) * S2_BBUF;
            for (int c = tid; c < 1024; c += 512) {
                int mat = c >> 9, f = (c >> 3) & 63, ch = c & 7;
                const __half* src = (mat ? Bv : Bm) + (size_t)f * N_NODES + j1 + ch * 8;
                cp_async16(bbs + mat * S2_BMAT + f * P1 + ch * 16, src);
            }
        }
        CP_COMMIT();

        // ---- P-gen: both matrices, thread covers (r, j in [q*8, q*8+8)) -----
        {
            unsigned w = adjb[row_adj + (j0 >> 5) + (q >> 2)];
            unsigned bits = w >> ((q & 3) * 8);
            char* amh = smem + S2_A + buf * S2_ABUF + r * P1;
            char* aml = amh + S2_AMAT;
            char* avh = amh + 2 * S2_AMAT;
            char* avl = amh + 3 * S2_AMAT;
            const int jb = q * 8;
            #pragma unroll
            for (int qq = 0; qq < 8; qq += 2) {
                int jl = jb + qq;
                int b0 = (bits >> qq) & 1;
                int b1 = (bits >> (qq + 1)) & 1;

                float d0 = dmuv[j0 + jl], d1 = dmuv[j0 + jl + 1];
                float p0 = b0 ? ((svm + d0 > 0.f) ? RAm * Em[j0 + jl]     : RBm * Fm[j0 + jl])     : 0.f;
                float p1 = b1 ? ((svm + d1 > 0.f) ? RAm * Em[j0 + jl + 1] : RBm * Fm[j0 + jl + 1]) : 0.f;
                zm += p0 + p1;
                __half2 h2 = __floats2half2_rn(p0, p1);
                __half2 l2 = __floats2half2_rn(p0 - __half2float(__low2half(h2)),
                                               p1 - __half2float(__high2half(h2)));
                *(__half2*)(amh + jl * 2) = h2;
                *(__half2*)(aml + jl * 2) = l2;

                d0 = dlvv[j0 + jl]; d1 = dlvv[j0 + jl + 1];
                p0 = b0 ? ((svv + d0 > 0.f) ? RAv * Ev[j0 + jl]     : RBv * Fv[j0 + jl])     : 0.f;
                p1 = b1 ? ((svv + d1 > 0.f) ? RAv * Ev[j0 + jl + 1] : RBv * Fv[j0 + jl + 1]) : 0.f;
                zv += p0 + p1;
                h2 = __floats2half2_rn(p0, p1);
                l2 = __floats2half2_rn(p0 - __half2float(__low2half(h2)),
                                       p1 - __half2float(__high2half(h2)));
                *(__half2*)(avh + jl * 2) = h2;
                *(__half2*)(avl + jl * 2) = l2;
            }
        }

        CP_WAIT1();
        __syncthreads();

        // ---- MMA on this warp's matrix ---------------------------------------
        const uint32_t abase = sb + S2_A + buf * S2_ABUF + which * 2 * S2_AMAT + a_lane;
        const uint32_t bbase = sb + S2_B + buf * S2_BBUF + which * S2_BMAT
                             + n0w * P1 + b_lane;
        #pragma unroll
        for (int kt = 0; kt < 4; ++kt) {
            const int koff = kt * 32;
            uint32_t ah[4][4], al[4][4];
            #pragma unroll
            for (int mi = 0; mi < 4; ++mi)
                ldsm_x4(ah[mi][0], ah[mi][1], ah[mi][2], ah[mi][3],
                        abase + mi * (16 * P1) + koff);
            #pragma unroll
            for (int mi = 0; mi < 4; ++mi)
                ldsm_x4(al[mi][0], al[mi][1], al[mi][2], al[mi][3],
                        abase + S2_AMAT + mi * (16 * P1) + koff);
            uint32_t b0, b1;
            ldsm_x2(b0, b1, bbase + koff);
            #pragma unroll
            for (int mi = 0; mi < 4; ++mi) {
                mma16816(acc[mi], ah[mi][0], ah[mi][1], ah[mi][2], ah[mi][3], b0, b1);
                mma16816(acc[mi], al[mi][0], al[mi][1], al[mi][2], al[mi][3], b0, b1);
            }
        }
        __syncthreads();
    }

    // epilogue
    float* ztm = (float*)(smem + S2_ZT);
    float* ztv = ztm + 512;
    float* zrm = (float*)(smem + S2_ZR);
    float* zrv = zrm + 64;
    ztm[tid] = zm; ztv[tid] = zv;
    __syncthreads();
    if (tid < 64) {
        float a = 0.f, b = 0.f;
        #pragma unroll
        for (int k = 0; k < 8; ++k) { a += ztm[8 * tid + k]; b += ztv[8 * tid + k]; }
        zrm[tid] = a; zrv[tid] = b;
    }
    __syncthreads();
    const float* zrow = which ? zrv : zrm;
    float* outw = which ? out_lv : out_mu;
    #pragma unroll
    for (int mi = 0; mi < 4; ++mi) {
        int r0 = mi * 16 + g;
        float iz0 = 1.f / zrow[r0];
        float iz1 = 1.f / zrow[r0 + 8];
        int col = n0w + tq * 2;
        *(float2*)&outw[(size_t)(i0 + r0) * NLAT + col] =
            make_float2(acc[mi][0] * iz0, acc[mi][1] * iz0);
        *(float2*)&outw[(size_t)(i0 + r0 + 8) * NLAT + col] =
            make_float2(acc[mi][2] * iz1, acc[mi][3] * iz1);
    }
}

// ---------------- z = mu + eps*exp(0.5*lv); logits = z @ Wc + bc ------------
__global__ __launch_bounds__(128)
void final_kernel(const float* __restrict__ mu, const float* __restrict__ lv,
                  const float* __restrict__ eps, const float* __restrict__ Wc,
                  const float* __restrict__ bc, float* __restrict__ logits)
{
    __shared__ float zs[8 * 64];
    const int tid = threadIdx.x;
    const int r0 = blockIdx.x * 8;
    #pragma unroll
    for (int l = tid; l < 8 * 64; l += 128) {
        int r = l >> 6, k = l & 63;
        size_t idx = (size_t)(r0 + r) * 64 + k;
        zs[l] = mu[idx] + eps[idx] * __expf(0.5f * lv[idx]);
    }
    __syncthreads();
    int r = tid >> 4, n = tid & 15;
    float acc = bc[n];
    #pragma unroll
    for (int k = 0; k < 64; ++k) acc += zs[r * 64 + k] * Wc[k * 16 + n];
    logits[(size_t)(r0 + r) * 16 + n] = acc;
}

// ------------------------------ launch --------------------------------------
extern "C" void kernel_launch(void* const* d_in, const int* in_sizes, int n_in,
                              void* d_out, int out_size)
{
    const float* x   = (const float*)d_in[0];
    const int*   adj = (const int*)  d_in[1];
    const float* eps = (const float*)d_in[2];
    const float* W1  = (const float*)d_in[3];
    const float* a1  = (const float*)d_in[4];
    const float* Wmu = (const float*)d_in[5];
    const float* amu = (const float*)d_in[6];
    const float* Wlv = (const float*)d_in[7];
    const float* alv = (const float*)d_in[8];
    const float* Wc  = (const float*)d_in[9];
    const float* bc  = (const float*)d_in[10];

    float* out    = (float*)d_out;
    float* logits = out;
    float* mu     = out + (size_t)N_NODES * NCLASS;
    float* lv     = mu  + (size_t)N_NODES * NLAT;

    float *Wh1, *h, *Whmu, *Whlv, *s1, *d1, *smu, *dmu, *slv, *dlv;
    float *E1, *F1, *Emu, *Fmu, *Elv, *Flv, *dmaxf;
    unsigned *dmaxu;
    __half *T1, *Tm, *Tv;
    unsigned* adjb;
    cudaGetSymbolAddress((void**)&Wh1,  g_Wh1);
    cudaGetSymbolAddress((void**)&h,    g_h);
    cudaGetSymbolAddress((void**)&Whmu, g_Whmu);
    cudaGetSymbolAddress((void**)&Whlv, g_Whlv);
    cudaGetSymbolAddress((void**)&s1,   g_s1);
    cudaGetSymbolAddress((void**)&d1,   g_d1);
    cudaGetSymbolAddress((void**)&smu,  g_smu);
    cudaGetSymbolAddress((void**)&dmu,  g_dmu);
    cudaGetSymbolAddress((void**)&slv,  g_slv);
    cudaGetSymbolAddress((void**)&dlv,  g_dlv);
    cudaGetSymbolAddress((void**)&dmaxu, g_dmaxu);
    cudaGetSymbolAddress((void**)&dmaxf, g_dmaxf);
    cudaGetSymbolAddress((void**)&E1,   g_E1);
    cudaGetSymbolAddress((void**)&F1,   g_F1);
    cudaGetSymbolAddress((void**)&Emu,  g_Emu);
    cudaGetSymbolAddress((void**)&Fmu,  g_Fmu);
    cudaGetSymbolAddress((void**)&Elv,  g_Elv);
    cudaGetSymbolAddress((void**)&Flv,  g_Flv);
    cudaGetSymbolAddress((void**)&T1,   g_T1);
    cudaGetSymbolAddress((void**)&Tm,   g_Tm);
    cudaGetSymbolAddress((void**)&Tv,   g_Tv);
    cudaGetSymbolAddress((void**)&adjb, g_adjb);

    cudaFuncSetAttribute(attn1_kernel,  cudaFuncAttributeMaxDynamicSharedMemorySize, SMEM1);
    cudaFuncSetAttribute(attn23_kernel, cudaFuncAttributeMaxDynamicSharedMemorySize, SMEM2);

    pack_adj_kernel<<<(size_t)N_NODES * N_NODES / 256, 256>>>(adj, adjb, dmaxu);

    // layer 1
    gemm_kernel<<<dim3(NHID / 64, N_NODES / 64), 256>>>(x, W1, Wh1, N_NODES, NHID, NFEAT);
    sd_kernel<NHID><<<N_NODES * 32 / 256, 256>>>(Wh1, a1, s1, d1, dmaxu + 0);
    ef_kernel<<<N_NODES / 256, 256>>>(d1, dmaxu + 0, E1, F1, dmaxf + 0);
    tconv_kernel<<<dim3(NHID / 32, N_NODES / 32), 256>>>(Wh1, T1, NHID);
    attn1_kernel<<<N_NODES / 64, 512, SMEM1>>>(adjb, T1, s1, d1, E1, F1, dmaxf + 0, h);

    // layer 2/3
    gemm_kernel<<<dim3(NLAT / 64, N_NODES / 64), 256>>>(h, Wmu, Whmu, N_NODES, NLAT, NHID);
    gemm_kernel<<<dim3(NLAT / 64, N_NODES / 64), 256>>>(h, Wlv, Whlv, N_NODES, NLAT, NHID);
    sd_kernel<NLAT><<<N_NODES * 32 / 256, 256>>>(Whmu, amu, smu, dmu, dmaxu + 1);
    sd_kernel<NLAT><<<N_NODES * 32 / 256, 256>>>(Whlv, alv, slv, dlv, dmaxu + 2);
    ef_kernel<<<N_NODES / 256, 256>>>(dmu, dmaxu + 1, Emu, Fmu, dmaxf + 1);
    ef_kernel<<<N_NODES / 256, 256>>>(dlv, dmaxu + 2, Elv, Flv, dmaxf + 2);
    tconv_kernel<<<dim3(NLAT / 32, N_NODES / 32), 256>>>(Whmu, Tm, NLAT);
    tconv_kernel<<<dim3(NLAT / 32, N_NODES / 32), 256>>>(Whlv, Tv, NLAT);
    attn23_kernel<<<N_NODES / 64, 512, SMEM2>>>(adjb, Tm, Tv,
                                                smu, dmu, slv, dlv,
                                                Emu, Fmu, Elv, Flv, dmaxf + 1, mu, lv);

    // reparameterize + classifier
    final_kernel<<<N_NODES / 8, 128>>>(mu, lv, eps, Wc, bc, logits);
}

// round 12
// speedup vs baseline: 1.4558x; 1.2799x over previous
#include <cuda_runtime.h>
#include <cuda_bf16.h>
#include <cuda_fp16.h>
#include <math.h>
#include <stdint.h>

#define N_NODES 8192
#define NFEAT   512
#define NHID    256
#define NLAT    64
#define NCLASS  16
#define ALPHA   0.2f
#define NWORDS  (N_NODES / 32)

// ------------------------------ device scratch ------------------------------
__device__ __align__(16) float g_Wh1 [N_NODES * NHID];
__device__ __align__(16) float g_h   [N_NODES * NHID];
__device__ __align__(16) float g_Whmu[N_NODES * NLAT];
__device__ __align__(16) float g_Whlv[N_NODES * NLAT];
__device__ __align__(16) __half g_T1[NHID * N_NODES];   // Wh1^T fp16 [F][N]
__device__ __align__(16) __half g_Tm[NLAT * N_NODES];
__device__ __align__(16) __half g_Tv[NLAT * N_NODES];
__device__ unsigned g_adjb[(size_t)N_NODES * NWORDS];
__device__ float g_s1[N_NODES], g_d1[N_NODES];
__device__ float g_smu[N_NODES], g_dmu[N_NODES];
__device__ float g_slv[N_NODES], g_dlv[N_NODES];
__device__ __align__(16) float g_E1[N_NODES],  g_F1[N_NODES];
__device__ __align__(16) float g_Emu[N_NODES], g_Fmu[N_NODES];
__device__ __align__(16) float g_Elv[N_NODES], g_Flv[N_NODES];
__device__ unsigned g_dmaxu[4];
__device__ float    g_dmaxf[4];

// ------------------------------ helpers -------------------------------------
__device__ __forceinline__ uint32_t smem_u32(const void* p) {
    uint32_t a;
    asm("{ .reg .u64 t; cvta.to.shared.u64 t, %1; cvt.u32.u64 %0, t; }"
        : "=r"(a) : "l"(p));
    return a;
}
__device__ __forceinline__ void cp_async16(uint32_t dst, const void* src) {
    asm volatile("cp.async.cg.shared.global [%0], [%1], 16;"
                 :: "r"(dst), "l"(src) : "memory");
}
#define CP_COMMIT() asm volatile("cp.async.commit_group;" ::: "memory")
#define CP_WAIT1()  asm volatile("cp.async.wait_group 1;"  ::: "memory")

__device__ __forceinline__ unsigned fenc(float x) {
    int ix = __float_as_int(x);
    return ix >= 0 ? ((unsigned)ix | 0x80000000u) : ~(unsigned)ix;
}
__device__ __forceinline__ float fdec(unsigned u) {
    int ix = (u & 0x80000000u) ? (int)(u & 0x7FFFFFFFu) : ~(int)u;
    return __int_as_float(ix);
}

// mma.sync m16n8k16 row.col f16 -> f32 (HMMA on sm_103)
__device__ __forceinline__ void mma16816(float* c,
    uint32_t a0, uint32_t a1, uint32_t a2, uint32_t a3,
    uint32_t b0, uint32_t b1)
{
    asm volatile(
        "mma.sync.aligned.m16n8k16.row.col.f32.f16.f16.f32 "
        "{%0,%1,%2,%3}, {%4,%5,%6,%7}, {%8,%9}, {%0,%1,%2,%3};"
        : "+f"(c[0]), "+f"(c[1]), "+f"(c[2]), "+f"(c[3])
        : "r"(a0), "r"(a1), "r"(a2), "r"(a3), "r"(b0), "r"(b1));
}
__device__ __forceinline__ void ldsm_x4(uint32_t& r0, uint32_t& r1,
                                        uint32_t& r2, uint32_t& r3, uint32_t addr)
{
    asm volatile("ldmatrix.sync.aligned.m8n8.x4.shared.b16 {%0,%1,%2,%3}, [%4];"
                 : "=r"(r0), "=r"(r1), "=r"(r2), "=r"(r3) : "r"(addr));
}
__device__ __forceinline__ void ldsm_x2(uint32_t& r0, uint32_t& r1, uint32_t addr)
{
    asm volatile("ldmatrix.sync.aligned.m8n8.x2.shared.b16 {%0,%1}, [%2];"
                 : "=r"(r0), "=r"(r1) : "r"(addr));
}

// ------------------------------ utility kernels -----------------------------
__global__ __launch_bounds__(256)
void pack_adj_kernel(const int* __restrict__ adj, unsigned* __restrict__ bits,
                     unsigned* __restrict__ dmaxu)
{
    if (blockIdx.x == 0 && threadIdx.x < 4) dmaxu[threadIdx.x] = 0u;
    size_t idx = (size_t)blockIdx.x * 256 + threadIdx.x;
    int v = adj[idx] > 0;
    unsigned b = __ballot_sync(0xffffffffu, v);
    if ((threadIdx.x & 31) == 0) bits[idx >> 5] = b;
}

// transpose + fp16 convert: in[N][F] fp32 -> T [F][N] fp16
__global__ __launch_bounds__(256)
void tconv_kernel(const float* __restrict__ in, __half* __restrict__ T, int F)
{
    __shared__ float tile[32][33];
    int m0 = blockIdx.y * 32, f0 = blockIdx.x * 32;
    int x = threadIdx.x & 31, y = threadIdx.x >> 5;
    #pragma unroll
    for (int yy = 0; yy < 4; ++yy)
        tile[y + yy * 8][x] = in[(size_t)(m0 + y + yy * 8) * F + f0 + x];
    __syncthreads();
    #pragma unroll
    for (int yy = 0; yy < 4; ++yy) {
        float v = tile[x][y + yy * 8];
        T[(size_t)(f0 + y + yy * 8) * N_NODES + m0 + x] = __float2half_rn(v);
    }
}

__global__ __launch_bounds__(256)
void gemm_kernel(const float* __restrict__ A, const float* __restrict__ B,
                 float* __restrict__ C, int M, int N, int K)
{
    __shared__ float As[16][64];
    __shared__ float Bs[16][64];
    const int tid = threadIdx.x;
    const int tx = tid & 15, ty = tid >> 4;
    const int m0 = blockIdx.y * 64, n0 = blockIdx.x * 64;
    float acc[4][4] = {};
    for (int k0 = 0; k0 < K; k0 += 16) {
        {
            int m = tid >> 2, kq = (tid & 3) * 4;
            float4 v = *(const float4*)&A[(size_t)(m0 + m) * K + k0 + kq];
            As[kq + 0][m] = v.x; As[kq + 1][m] = v.y;
            As[kq + 2][m] = v.z; As[kq + 3][m] = v.w;
        }
        {
            int k = tid >> 4, nq = (tid & 15) * 4;
            *(float4*)&Bs[k][nq] = *(const float4*)&B[(size_t)(k0 + k) * N + n0 + nq];
        }
        __syncthreads();
        #pragma unroll
        for (int k = 0; k < 16; ++k) {
            float a[4], b[4];
            #pragma unroll
            for (int i = 0; i < 4; ++i) a[i] = As[k][ty * 4 + i];
            #pragma unroll
            for (int j = 0; j < 4; ++j) b[j] = Bs[k][tx * 4 + j];
            #pragma unroll
            for (int i = 0; i < 4; ++i)
                #pragma unroll
                for (int j = 0; j < 4; ++j)
                    acc[i][j] += a[i] * b[j];
        }
        __syncthreads();
    }
    #pragma unroll
    for (int i = 0; i < 4; ++i) {
        float4 v = make_float4(acc[i][0], acc[i][1], acc[i][2], acc[i][3]);
        *(float4*)&C[(size_t)(m0 + ty * 4 + i) * N + n0 + tx * 4] = v;
    }
}

template <int F>
__global__ __launch_bounds__(256)
void sd_kernel(const float* __restrict__ Wh, const float* __restrict__ a,
               float* __restrict__ s, float* __restrict__ d,
               unsigned* __restrict__ dmaxu)
{
    int warp = (blockIdx.x * blockDim.x + threadIdx.x) >> 5;
    int lane = threadIdx.x & 31;
    if (warp >= N_NODES) return;
    const float* row = Wh + (size_t)warp * F;
    float ss = 0.f, dd = 0.f;
    #pragma unroll
    for (int f = lane; f < F; f += 32) {
        float w = row[f];
        ss += w * a[f];
        dd += w * a[F + f];
    }
    #pragma unroll
    for (int o = 16; o; o >>= 1) {
        ss += __shfl_down_sync(0xffffffffu, ss, o);
        dd += __shfl_down_sync(0xffffffffu, dd, o);
    }
    if (lane == 0) {
        s[warp] = ss; d[warp] = dd;
        atomicMax(dmaxu, fenc(dd));
    }
}

__global__ __launch_bounds__(256)
void ef_kernel(const float* __restrict__ d, const unsigned* __restrict__ dmaxu,
               float* __restrict__ E, float* __restrict__ F,
               float* __restrict__ dmaxf)
{
    float dm = fdec(*dmaxu);
    int i = blockIdx.x * 256 + threadIdx.x;
    float v = d[i] - dm;
    E[i] = __expf(v);
    F[i] = __expf(ALPHA * v);
    if (i == 0) *dmaxf = dm;
}

// =============================================================================
// attn1: h = ELU( softmax(mask(leaky(s_i+d_j))) @ Wh1 )  F=256, fp16 1-product
// CTA 64 rows, 512 threads (16 warps; warp w -> cols [16w,16w+16)).
// j-tile 128 double-buffered; ldmatrix; 272B row pitch (conflict-free).
// =============================================================================
static constexpr int P2      = 272;
static constexpr int S1_B    = 0;          // 2 buf x 256x272
static constexpr int S1_BBUF = 69632;
static constexpr int S1_A    = 139264;     // 2 buf x 64x272
static constexpr int S1_ABUF = 17408;
static constexpr int S1_ZT   = 174080;     // 512 floats
static constexpr int S1_ZR   = 176128;     // 64 floats
static constexpr int SMEM1   = 176384;

__global__ __launch_bounds__(512, 1)
void attn1_kernel(const unsigned* __restrict__ adjb,
                  const __half* __restrict__ BT,
                  const float* __restrict__ svec, const float* __restrict__ dvec,
                  const float* __restrict__ EJ, const float* __restrict__ FJ,
                  const float* __restrict__ dmaxp, float* __restrict__ outp)
{
    extern __shared__ __align__(16) char smem[];
    const uint32_t sb = smem_u32(smem);
    const int tid = threadIdx.x, warp = tid >> 5, lane = tid & 31;
    const int g = lane >> 2, tq = lane & 3;
    const int i0 = blockIdx.x * 64;
    const int n0w = warp * 16;

    const uint32_t a_lane = ((lane & 7) + ((lane >> 3) & 1) * 8) * P2 + ((lane >> 4) & 1) * 16;
    const uint32_t b_lane = ((lane & 7) + ((lane >> 4) & 1) * 8) * P2 + ((lane >> 3) & 1) * 16;

    const int r = tid >> 3, q = tid & 7;     // row, 16-j slice
    const float sv = svec[i0 + r];
    const float mv = sv + *dmaxp;
    const float m_r = mv > 0.f ? mv : ALPHA * mv;
    const float RA = __expf(mv - m_r);
    const float RB = __expf(ALPHA * mv - m_r);
    float zacc = 0.f;

    float acc[4][2][4];
    #pragma unroll
    for (int a = 0; a < 4; ++a)
        #pragma unroll
        for (int b = 0; b < 2; ++b)
            #pragma unroll
            for (int c = 0; c < 4; ++c) acc[a][b][c] = 0.f;

    const size_t row_adj = (size_t)(i0 + r) * NWORDS;

    // prologue: stage B tile 0 (256 f-rows x 128 j fp16 = 4096 chunks)
    for (int c = tid; c < 4096; c += 512) {
        int f = c >> 4, ch = c & 15;
        cp_async16(sb + S1_B + f * P2 + ch * 16, BT + (size_t)f * N_NODES + ch * 8);
    }
    CP_COMMIT();

    for (int t = 0; t < N_NODES / 128; ++t) {
        const int j0 = t * 128;
        const int buf = t & 1;

        if (t + 1 < N_NODES / 128) {
            const int j1 = j0 + 128;
            const uint32_t bb = sb + S1_B + (buf ^ 1) * S1_BBUF;
            for (int c = tid; c < 4096; c += 512) {
                int f = c >> 4, ch = c & 15;
                cp_async16(bb + f * P2 + ch * 16, BT + (size_t)f * N_NODES + j1 + ch * 8);
            }
        }
        CP_COMMIT();

        // ---- P-gen into A[buf]: thread covers (r, j in [q*16, q*16+16)) -----
        {
            unsigned w = adjb[row_adj + (j0 >> 5) + (q >> 1)];
            unsigned bits = w >> ((q & 1) * 16);
            char* ap = smem + S1_A + buf * S1_ABUF + r * P2;
            const int jb = q * 16;
            const float4* d4 = (const float4*)(dvec + j0 + jb);
            const float4* e4 = (const float4*)(EJ + j0 + jb);
            const float4* f4 = (const float4*)(FJ + j0 + jb);
            #pragma unroll
            for (int v = 0; v < 4; ++v) {
                float4 dd = d4[v], ee = e4[v], ff = f4[v];
                float p0 = ((bits >> (v * 4 + 0)) & 1)
                         ? ((sv + dd.x > 0.f) ? RA * ee.x : RB * ff.x) : 0.f;
                float p1 = ((bits >> (v * 4 + 1)) & 1)
                         ? ((sv + dd.y > 0.f) ? RA * ee.y : RB * ff.y) : 0.f;
                float p2 = ((bits >> (v * 4 + 2)) & 1)
                         ? ((sv + dd.z > 0.f) ? RA * ee.z : RB * ff.z) : 0.f;
                float p3 = ((bits >> (v * 4 + 3)) & 1)
                         ? ((sv + dd.w > 0.f) ? RA * ee.w : RB * ff.w) : 0.f;
                zacc += p0 + p1 + p2 + p3;
                __half2 h01 = __floats2half2_rn(p0, p1);
                __half2 h23 = __floats2half2_rn(p2, p3);
                uint2 pk;
                pk.x = *(uint32_t*)&h01;
                pk.y = *(uint32_t*)&h23;
                *(uint2*)(ap + (jb + v * 4) * 2) = pk;
            }
        }

        CP_WAIT1();
        __syncthreads();

        // ---- MMA on buffer buf ----------------------------------------------
        const uint32_t abase = sb + S1_A + buf * S1_ABUF + a_lane;
        const uint32_t bbase = sb + S1_B + buf * S1_BBUF + n0w * P2 + b_lane;
        #pragma unroll
        for (int kt = 0; kt < 8; ++kt) {
            const int koff = kt * 32;
            uint32_t ah[4][4];
            #pragma unroll
            for (int mi = 0; mi < 4; ++mi)
                ldsm_x4(ah[mi][0], ah[mi][1], ah[mi][2], ah[mi][3],
                        abase + mi * (16 * P2) + koff);
            uint32_t b0, b1, b2, b3;
            ldsm_x4(b0, b1, b2, b3, bbase + koff);
            #pragma unroll
            for (int mi = 0; mi < 4; ++mi) {
                mma16816(acc[mi][0], ah[mi][0], ah[mi][1], ah[mi][2], ah[mi][3], b0, b1);
                mma16816(acc[mi][1], ah[mi][0], ah[mi][1], ah[mi][2], ah[mi][3], b2, b3);
            }
        }
        __syncthreads();
    }

    // ---- epilogue --------------------------------------------------------------
    float* zt = (float*)(smem + S1_ZT);
    float* zr = (float*)(smem + S1_ZR);
    zt[tid] = zacc;
    __syncthreads();
    if (tid < 64) {
        float z = 0.f;
        #pragma unroll
        for (int k = 0; k < 8; ++k) z += zt[8 * tid + k];
        zr[tid] = z;
    }
    __syncthreads();
    #pragma unroll
    for (int mi = 0; mi < 4; ++mi) {
        int r0 = mi * 16 + g;
        float iz0 = 1.f / zr[r0];
        float iz1 = 1.f / zr[r0 + 8];
        #pragma unroll
        for (int ni = 0; ni < 2; ++ni) {
            int col = n0w + ni * 8 + tq * 2;
            float v0 = acc[mi][ni][0] * iz0; v0 = v0 > 0.f ? v0 : expm1f(v0);
            float v1 = acc[mi][ni][1] * iz0; v1 = v1 > 0.f ? v1 : expm1f(v1);
            float v2 = acc[mi][ni][2] * iz1; v2 = v2 > 0.f ? v2 : expm1f(v2);
            float v3 = acc[mi][ni][3] * iz1; v3 = v3 > 0.f ? v3 : expm1f(v3);
            *(float2*)&outp[(size_t)(i0 + r0) * NHID + col]     = make_float2(v0, v1);
            *(float2*)&outp[(size_t)(i0 + r0 + 8) * NHID + col] = make_float2(v2, v3);
        }
    }
}

// =============================================================================
// attn23: fused mu & lv attention, F=64 each, fp16 1-product. 512 threads.
// warps 0-7: mu cols [8w..8w+8); warps 8-15: lv. j-tile 128.
// =============================================================================
static constexpr int S2_B    = 0;          // 2 buf x [mu 64x272 | lv 64x272]
static constexpr int S2_BBUF = 34816;
static constexpr int S2_BMAT = 17408;
static constexpr int S2_A    = 69632;      // 2 buf x [mu 64x272 | lv 64x272]
static constexpr int S2_ABUF = 34816;
static constexpr int S2_AMAT = 17408;
static constexpr int S2_ZT   = 139264;     // 2 x 512 floats
static constexpr int S2_ZR   = 143360;     // 2 x 64 floats
static constexpr int SMEM2   = 143872;

__global__ __launch_bounds__(512, 1)
void attn23_kernel(const unsigned* __restrict__ adjb,
                   const __half* __restrict__ Bm, const __half* __restrict__ Bv,
                   const float* __restrict__ smuv, const float* __restrict__ dmuv,
                   const float* __restrict__ slvv, const float* __restrict__ dlvv,
                   const float* __restrict__ Em, const float* __restrict__ Fm,
                   const float* __restrict__ Ev, const float* __restrict__ Fv,
                   const float* __restrict__ dmaxp,   // [0]=mu, [1]=lv
                   float* __restrict__ out_mu, float* __restrict__ out_lv)
{
    extern __shared__ __align__(16) char smem[];
    const uint32_t sb = smem_u32(smem);
    const int tid = threadIdx.x, warp = tid >> 5, lane = tid & 31;
    const int g = lane >> 2, tq = lane & 3;
    const int i0 = blockIdx.x * 64;
    const int which = warp >> 3;          // 0 = mu, 1 = lv
    const int n0w = (warp & 7) * 8;

    const uint32_t a_lane = ((lane & 7) + ((lane >> 3) & 1) * 8) * P2 + ((lane >> 4) & 1) * 16;
    const uint32_t b_lane = (lane & 7) * P2 + ((lane >> 3) & 1) * 16;   // x2: lanes 0-15

    const int r = tid >> 3, q = tid & 7;
    const float svm = smuv[i0 + r], svv = slvv[i0 + r];
    const float mvm = svm + dmaxp[0], mvv = svv + dmaxp[1];
    const float mm = mvm > 0.f ? mvm : ALPHA * mvm;
    const float ml = mvv > 0.f ? mvv : ALPHA * mvv;
    const float RAm = __expf(mvm - mm), RBm = __expf(ALPHA * mvm - mm);
    const float RAv = __expf(mvv - ml), RBv = __expf(ALPHA * mvv - ml);
    float zm = 0.f, zv = 0.f;

    float acc[4][4];
    #pragma unroll
    for (int a = 0; a < 4; ++a)
        #pragma unroll
        for (int c = 0; c < 4; ++c) acc[a][c] = 0.f;

    const size_t row_adj = (size_t)(i0 + r) * NWORDS;

    // prologue: stage B tile 0 (mu + lv, 64 f-rows x 128 j = 2048 chunks)
    for (int c = tid; c < 2048; c += 512) {
        int mat = c >> 10, f = (c >> 4) & 63, ch = c & 15;
        const __half* src = (mat ? Bv : Bm) + (size_t)f * N_NODES + ch * 8;
        cp_async16(sb + S2_B + mat * S2_BMAT + f * P2 + ch * 16, src);
    }
    CP_COMMIT();

    for (int t = 0; t < N_NODES / 128; ++t) {
        const int j0 = t * 128;
        const int buf = t & 1;

        if (t + 1 < N_NODES / 128) {
            const int j1 = j0 + 128;
            const uint32_t bbs = sb + S2_B + (buf ^ 1) * S2_BBUF;
            for (int c = tid; c < 2048; c += 512) {
                int mat = c >> 10, f = (c >> 4) & 63, ch = c & 15;
                const __half* src = (mat ? Bv : Bm) + (size_t)f * N_NODES + j1 + ch * 8;
                cp_async16(bbs + mat * S2_BMAT + f * P2 + ch * 16, src);
            }
        }
        CP_COMMIT();

        // ---- P-gen: both matrices, thread covers (r, j in [q*16, q*16+16)) --
        {
            unsigned w = adjb[row_adj + (j0 >> 5) + (q >> 1)];
            unsigned bits = w >> ((q & 1) * 16);
            char* apm = smem + S2_A + buf * S2_ABUF + r * P2;
            char* apv = apm + S2_AMAT;
            const int jb = q * 16;
            const float4* dm4 = (const float4*)(dmuv + j0 + jb);
            const float4* em4 = (const float4*)(Em + j0 + jb);
            const float4* fm4 = (const float4*)(Fm + j0 + jb);
            const float4* dv4 = (const float4*)(dlvv + j0 + jb);
            const float4* ev4 = (const float4*)(Ev + j0 + jb);
            const float4* fv4 = (const float4*)(Fv + j0 + jb);
            #pragma unroll
            for (int v = 0; v < 4; ++v) {
                int b0 = (bits >> (v * 4 + 0)) & 1;
                int b1 = (bits >> (v * 4 + 1)) & 1;
                int b2 = (bits >> (v * 4 + 2)) & 1;
                int b3 = (bits >> (v * 4 + 3)) & 1;

                float4 dd = dm4[v], ee = em4[v], ff = fm4[v];
                float p0 = b0 ? ((svm + dd.x > 0.f) ? RAm * ee.x : RBm * ff.x) : 0.f;
                float p1 = b1 ? ((svm + dd.y > 0.f) ? RAm * ee.y : RBm * ff.y) : 0.f;
                float p2 = b2 ? ((svm + dd.z > 0.f) ? RAm * ee.z : RBm * ff.z) : 0.f;
                float p3 = b3 ? ((svm + dd.w > 0.f) ? RAm * ee.w : RBm * ff.w) : 0.f;
                zm += p0 + p1 + p2 + p3;
                __half2 h01 = __floats2half2_rn(p0, p1);
                __half2 h23 = __floats2half2_rn(p2, p3);
                uint2 pk;
                pk.x = *(uint32_t*)&h01;
                pk.y = *(uint32_t*)&h23;
                *(uint2*)(apm + (jb + v * 4) * 2) = pk;

                dd = dv4[v]; ee = ev4[v]; ff = fv4[v];
                p0 = b0 ? ((svv + dd.x > 0.f) ? RAv * ee.x : RBv * ff.x) : 0.f;
                p1 = b1 ? ((svv + dd.y > 0.f) ? RAv * ee.y : RBv * ff.y) : 0.f;
                p2 = b2 ? ((svv + dd.z > 0.f) ? RAv * ee.z : RBv * ff.z) : 0.f;
                p3 = b3 ? ((svv + dd.w > 0.f) ? RAv * ee.w : RBv * ff.w) : 0.f;
                zv += p0 + p1 + p2 + p3;
                h01 = __floats2half2_rn(p0, p1);
                h23 = __floats2half2_rn(p2, p3);
                pk.x = *(uint32_t*)&h01;
                pk.y = *(uint32_t*)&h23;
                *(uint2*)(apv + (jb + v * 4) * 2) = pk;
            }
        }

        CP_WAIT1();
        __syncthreads();

        // ---- MMA on this warp's matrix ---------------------------------------
        const uint32_t abase = sb + S2_A + buf * S2_ABUF + which * S2_AMAT + a_lane;
        const uint32_t bbase = sb + S2_B + buf * S2_BBUF + which * S2_BMAT
                             + n0w * P2 + b_lane;
        #pragma unroll
        for (int kt = 0; kt < 8; ++kt) {
            const int koff = kt * 32;
            uint32_t ah[4][4];
            #pragma unroll
            for (int mi = 0; mi < 4; ++mi)
                ldsm_x4(ah[mi][0], ah[mi][1], ah[mi][2], ah[mi][3],
                        abase + mi * (16 * P2) + koff);
            uint32_t b0, b1;
            ldsm_x2(b0, b1, bbase + koff);
            #pragma unroll
            for (int mi = 0; mi < 4; ++mi)
                mma16816(acc[mi], ah[mi][0], ah[mi][1], ah[mi][2], ah[mi][3], b0, b1);
        }
        __syncthreads();
    }

    // epilogue
    float* ztm = (float*)(smem + S2_ZT);
    float* ztv = ztm + 512;
    float* zrm = (float*)(smem + S2_ZR);
    float* zrv = zrm + 64;
    ztm[tid] = zm; ztv[tid] = zv;
    __syncthreads();
    if (tid < 64) {
        float a = 0.f, b = 0.f;
        #pragma unroll
        for (int k = 0; k < 8; ++k) { a += ztm[8 * tid + k]; b += ztv[8 * tid + k]; }
        zrm[tid] = a; zrv[tid] = b;
    }
    __syncthreads();
    const float* zrow = which ? zrv : zrm;
    float* outw = which ? out_lv : out_mu;
    #pragma unroll
    for (int mi = 0; mi < 4; ++mi) {
        int r0 = mi * 16 + g;
        float iz0 = 1.f / zrow[r0];
        float iz1 = 1.f / zrow[r0 + 8];
        int col = n0w + tq * 2;
        *(float2*)&outw[(size_t)(i0 + r0) * NLAT + col] =
            make_float2(acc[mi][0] * iz0, acc[mi][1] * iz0);
        *(float2*)&outw[(size_t)(i0 + r0 + 8) * NLAT + col] =
            make_float2(acc[mi][2] * iz1, acc[mi][3] * iz1);
    }
}

// ---------------- z = mu + eps*exp(0.5*lv); logits = z @ Wc + bc ------------
__global__ __launch_bounds__(128)
void final_kernel(const float* __restrict__ mu, const float* __restrict__ lv,
                  const float* __restrict__ eps, const float* __restrict__ Wc,
                  const float* __restrict__ bc, float* __restrict__ logits)
{
    __shared__ float zs[8 * 64];
    const int tid = threadIdx.x;
    const int r0 = blockIdx.x * 8;
    #pragma unroll
    for (int l = tid; l < 8 * 64; l += 128) {
        int r = l >> 6, k = l & 63;
        size_t idx = (size_t)(r0 + r) * 64 + k;
        zs[l] = mu[idx] + eps[idx] * __expf(0.5f * lv[idx]);
    }
    __syncthreads();
    int r = tid >> 4, n = tid & 15;
    float acc = bc[n];
    #pragma unroll
    for (int k = 0; k < 64; ++k) acc += zs[r * 64 + k] * Wc[k * 16 + n];
    logits[(size_t)(r0 + r) * 16 + n] = acc;
}

// ------------------------------ launch --------------------------------------
extern "C" void kernel_launch(void* const* d_in, const int* in_sizes, int n_in,
                              void* d_out, int out_size)
{
    const float* x   = (const float*)d_in[0];
    const int*   adj = (const int*)  d_in[1];
    const float* eps = (const float*)d_in[2];
    const float* W1  = (const float*)d_in[3];
    const float* a1  = (const float*)d_in[4];
    const float* Wmu = (const float*)d_in[5];
    const float* amu = (const float*)d_in[6];
    const float* Wlv = (const float*)d_in[7];
    const float* alv = (const float*)d_in[8];
    const float* Wc  = (const float*)d_in[9];
    const float* bc  = (const float*)d_in[10];

    float* out    = (float*)d_out;
    float* logits = out;
    float* mu     = out + (size_t)N_NODES * NCLASS;
    float* lv     = mu  + (size_t)N_NODES * NLAT;

    float *Wh1, *h, *Whmu, *Whlv, *s1, *d1, *smu, *dmu, *slv, *dlv;
    float *E1, *F1, *Emu, *Fmu, *Elv, *Flv, *dmaxf;
    unsigned *dmaxu;
    __half *T1, *Tm, *Tv;
    unsigned* adjb;
    cudaGetSymbolAddress((void**)&Wh1,  g_Wh1);
    cudaGetSymbolAddress((void**)&h,    g_h);
    cudaGetSymbolAddress((void**)&Whmu, g_Whmu);
    cudaGetSymbolAddress((void**)&Whlv, g_Whlv);
    cudaGetSymbolAddress((void**)&s1,   g_s1);
    cudaGetSymbolAddress((void**)&d1,   g_d1);
    cudaGetSymbolAddress((void**)&smu,  g_smu);
    cudaGetSymbolAddress((void**)&dmu,  g_dmu);
    cudaGetSymbolAddress((void**)&slv,  g_slv);
    cudaGetSymbolAddress((void**)&dlv,  g_dlv);
    cudaGetSymbolAddress((void**)&dmaxu, g_dmaxu);
    cudaGetSymbolAddress((void**)&dmaxf, g_dmaxf);
    cudaGetSymbolAddress((void**)&E1,   g_E1);
    cudaGetSymbolAddress((void**)&F1,   g_F1);
    cudaGetSymbolAddress((void**)&Emu,  g_Emu);
    cudaGetSymbolAddress((void**)&Fmu,  g_Fmu);
    cudaGetSymbolAddress((void**)&Elv,  g_Elv);
    cudaGetSymbolAddress((void**)&Flv,  g_Flv);
    cudaGetSymbolAddress((void**)&T1,   g_T1);
    cudaGetSymbolAddress((void**)&Tm,   g_Tm);
    cudaGetSymbolAddress((void**)&Tv,   g_Tv);
    cudaGetSymbolAddress((void**)&adjb, g_adjb);

    cudaFuncSetAttribute(attn1_kernel,  cudaFuncAttributeMaxDynamicSharedMemorySize, SMEM1);
    cudaFuncSetAttribute(attn23_kernel, cudaFuncAttributeMaxDynamicSharedMemorySize, SMEM2);

    pack_adj_kernel<<<(size_t)N_NODES * N_NODES / 256, 256>>>(adj, adjb, dmaxu);

    // layer 1
    gemm_kernel<<<dim3(NHID / 64, N_NODES / 64), 256>>>(x, W1, Wh1, N_NODES, NHID, NFEAT);
    sd_kernel<NHID><<<N_NODES * 32 / 256, 256>>>(Wh1, a1, s1, d1, dmaxu + 0);
    ef_kernel<<<N_NODES / 256, 256>>>(d1, dmaxu + 0, E1, F1, dmaxf + 0);
    tconv_kernel<<<dim3(NHID / 32, N_NODES / 32), 256>>>(Wh1, T1, NHID);
    attn1_kernel<<<N_NODES / 64, 512, SMEM1>>>(adjb, T1, s1, d1, E1, F1, dmaxf + 0, h);

    // layer 2/3
    gemm_kernel<<<dim3(NLAT / 64, N_NODES / 64), 256>>>(h, Wmu, Whmu, N_NODES, NLAT, NHID);
    gemm_kernel<<<dim3(NLAT / 64, N_NODES / 64), 256>>>(h, Wlv, Whlv, N_NODES, NLAT, NHID);
    sd_kernel<NLAT><<<N_NODES * 32 / 256, 256>>>(Whmu, amu, smu, dmu, dmaxu + 1);
    sd_kernel<NLAT><<<N_NODES * 32 / 256, 256>>>(Whlv, alv, slv, dlv, dmaxu + 2);
    ef_kernel<<<N_NODES / 256, 256>>>(dmu, dmaxu + 1, Emu, Fmu, dmaxf + 1);
    ef_kernel<<<N_NODES / 256, 256>>>(dlv, dmaxu + 2, Elv, Flv, dmaxf + 2);
    tconv_kernel<<<dim3(NLAT / 32, N_NODES / 32), 256>>>(Whmu, Tm, NLAT);
    tconv_kernel<<<dim3(NLAT / 32, N_NODES / 32), 256>>>(Whlv, Tv, NLAT);
    attn23_kernel<<<N_NODES / 64, 512, SMEM2>>>(adjb, Tm, Tv,
                                                smu, dmu, slv, dlv,
                                                Emu, Fmu, Elv, Flv, dmaxf + 1, mu, lv);

    // reparameterize + classifier
    final_kernel<<<N_NODES / 8, 128>>>(mu, lv, eps, Wc, bc, logits);
}

// round 13
// speedup vs baseline: 1.5173x; 1.0423x over previous
#include <cuda_runtime.h>
#include <cuda_bf16.h>
#include <cuda_fp16.h>
#include <math.h>
#include <stdint.h>

#define N_NODES 8192
#define NFEAT   512
#define NHID    256
#define NLAT    64
#define NCLASS  16
#define ALPHA   0.2f
#define NWORDS  (N_NODES / 32)

// ------------------------------ device scratch ------------------------------
__device__ __align__(16) float g_Wh1 [N_NODES * NHID];
__device__ __align__(16) float g_h   [N_NODES * NHID];
__device__ __align__(16) float g_Whmu[N_NODES * NLAT];
__device__ __align__(16) float g_Whlv[N_NODES * NLAT];
__device__ __align__(16) __half g_T1[NHID * N_NODES];   // Wh1^T fp16 [F][N]
__device__ __align__(16) __half g_Tm[NLAT * N_NODES];
__device__ __align__(16) __half g_Tv[NLAT * N_NODES];
__device__ unsigned g_adjb[(size_t)N_NODES * NWORDS];
__device__ float g_s1[N_NODES], g_d1[N_NODES];
__device__ float g_smu[N_NODES], g_dmu[N_NODES];
__device__ float g_slv[N_NODES], g_dlv[N_NODES];
__device__ __align__(16) float g_E1[N_NODES],  g_F1[N_NODES];
__device__ __align__(16) float g_Emu[N_NODES], g_Fmu[N_NODES];
__device__ __align__(16) float g_Elv[N_NODES], g_Flv[N_NODES];
__device__ unsigned g_dmaxu[4];
__device__ float    g_dmaxf[4];

// ------------------------------ helpers -------------------------------------
__device__ __forceinline__ uint32_t smem_u32(const void* p) {
    uint32_t a;
    asm("{ .reg .u64 t; cvta.to.shared.u64 t, %1; cvt.u32.u64 %0, t; }"
        : "=r"(a) : "l"(p));
    return a;
}
__device__ __forceinline__ void cp_async16(uint32_t dst, const void* src) {
    asm volatile("cp.async.cg.shared.global [%0], [%1], 16;"
                 :: "r"(dst), "l"(src) : "memory");
}
#define CP_COMMIT() asm volatile("cp.async.commit_group;" ::: "memory")
#define CP_WAIT1()  asm volatile("cp.async.wait_group 1;"  ::: "memory")

__device__ __forceinline__ unsigned fenc(float x) {
    int ix = __float_as_int(x);
    return ix >= 0 ? ((unsigned)ix | 0x80000000u) : ~(unsigned)ix;
}
__device__ __forceinline__ float fdec(unsigned u) {
    int ix = (u & 0x80000000u) ? (int)(u & 0x7FFFFFFFu) : ~(int)u;
    return __int_as_float(ix);
}

// mma.sync m16n8k16 row.col f16 -> f32 (HMMA on sm_103)
__device__ __forceinline__ void mma16816(float* c,
    uint32_t a0, uint32_t a1, uint32_t a2, uint32_t a3,
    uint32_t b0, uint32_t b1)
{
    asm volatile(
        "mma.sync.aligned.m16n8k16.row.col.f32.f16.f16.f32 "
        "{%0,%1,%2,%3}, {%4,%5,%6,%7}, {%8,%9}, {%0,%1,%2,%3};"
        : "+f"(c[0]), "+f"(c[1]), "+f"(c[2]), "+f"(c[3])
        : "r"(a0), "r"(a1), "r"(a2), "r"(a3), "r"(b0), "r"(b1));
}
__device__ __forceinline__ void ldsm_x4(uint32_t& r0, uint32_t& r1,
                                        uint32_t& r2, uint32_t& r3, uint32_t addr)
{
    asm volatile("ldmatrix.sync.aligned.m8n8.x4.shared.b16 {%0,%1,%2,%3}, [%4];"
                 : "=r"(r0), "=r"(r1), "=r"(r2), "=r"(r3) : "r"(addr));
}
__device__ __forceinline__ void ldsm_x2(uint32_t& r0, uint32_t& r1, uint32_t addr)
{
    asm volatile("ldmatrix.sync.aligned.m8n8.x2.shared.b16 {%0,%1}, [%2];"
                 : "=r"(r0), "=r"(r1) : "r"(addr));
}

// =============================================================================
// gemm_mma: C[M][N] = A[M][K] @ B[K][N], fp32 in/out, fp16 2-product HMMA.
// CTA 128m x 64n, 256 threads (8 warps: wm=w>>1 m-32, wn=w&1 n-32).
// In-kernel conversion: A -> hi/lo fp16, B -> fp16 [n][k] transposed.
// =============================================================================
static constexpr int GP    = 144;             // smem row pitch (64 fp16 + pad)
static constexpr int G_AH  = 0;               // 128 x 144
static constexpr int G_AL  = 18432;
static constexpr int G_B   = 36864;           // 64 x 144
static constexpr int GSMEM = 46080;

__global__ __launch_bounds__(256, 1)
void gemm_mma_kernel(const float* __restrict__ A, const float* __restrict__ B,
                     float* __restrict__ C, int M, int N, int K,
                     unsigned* __restrict__ dmaxu, int init_flag)
{
    extern __shared__ __align__(16) char smem[];
    const uint32_t sb = smem_u32(smem);
    const int tid = threadIdx.x, warp = tid >> 5, lane = tid & 31;
    const int g = lane >> 2, tq = lane & 3;
    const int wm = warp >> 1, wn = warp & 1;
    const int m0 = blockIdx.y * 128, n0 = blockIdx.x * 64;

    if (init_flag && blockIdx.x == 0 && blockIdx.y == 0 && tid < 4)
        dmaxu[tid] = 0u;

    const uint32_t a_lane = ((lane & 7) + ((lane >> 3) & 1) * 8) * GP + ((lane >> 4) & 1) * 16;
    const uint32_t b_lane = ((lane & 7) + ((lane >> 4) & 1) * 8) * GP + ((lane >> 3) & 1) * 16;

    float acc[2][4][4];
    #pragma unroll
    for (int a = 0; a < 2; ++a)
        #pragma unroll
        for (int b = 0; b < 4; ++b)
            #pragma unroll
            for (int c = 0; c < 4; ++c) acc[a][b][c] = 0.f;

    for (int k0 = 0; k0 < K; k0 += 64) {
        __syncthreads();   // previous MMA reads done
        // ---- stage A (128 x 64 fp32 -> hi/lo fp16) --------------------------
        #pragma unroll
        for (int i = 0; i < 8; ++i) {
            int c = tid + i * 256;
            int row = c >> 4, kq = (c & 15) * 4;
            float4 v = *(const float4*)&A[(size_t)(m0 + row) * K + k0 + kq];
            __half h0 = __float2half_rn(v.x), h1 = __float2half_rn(v.y);
            __half h2 = __float2half_rn(v.z), h3 = __float2half_rn(v.w);
            __half l0 = __float2half_rn(v.x - __half2float(h0));
            __half l1 = __float2half_rn(v.y - __half2float(h1));
            __half l2 = __float2half_rn(v.z - __half2float(h2));
            __half l3 = __float2half_rn(v.w - __half2float(h3));
            __half2 hh01 = __halves2half2(h0, h1), hh23 = __halves2half2(h2, h3);
            __half2 ll01 = __halves2half2(l0, l1), ll23 = __halves2half2(l2, l3);
            uint2 ph, pl;
            ph.x = *(uint32_t*)&hh01; ph.y = *(uint32_t*)&hh23;
            pl.x = *(uint32_t*)&ll01; pl.y = *(uint32_t*)&ll23;
            *(uint2*)(smem + G_AH + row * GP + kq * 2) = ph;
            *(uint2*)(smem + G_AL + row * GP + kq * 2) = pl;
        }
        // ---- stage B (64k x 64n fp32 -> fp16 [n][k]) ------------------------
        #pragma unroll
        for (int i = 0; i < 4; ++i) {
            int c = tid + i * 256;
            int kk = c >> 4, nq = (c & 15) * 4;
            float4 v = *(const float4*)&B[(size_t)(k0 + kk) * N + n0 + nq];
            *(__half*)(smem + G_B + (nq + 0) * GP + kk * 2) = __float2half_rn(v.x);
            *(__half*)(smem + G_B + (nq + 1) * GP + kk * 2) = __float2half_rn(v.y);
            *(__half*)(smem + G_B + (nq + 2) * GP + kk * 2) = __float2half_rn(v.z);
            *(__half*)(smem + G_B + (nq + 3) * GP + kk * 2) = __float2half_rn(v.w);
        }
        __syncthreads();

        // ---- MMA ------------------------------------------------------------
        const uint32_t abase = sb + G_AH + (wm * 32) * GP + a_lane;
        const uint32_t bbase = sb + G_B + (wn * 32) * GP + b_lane;
        #pragma unroll
        for (int kt = 0; kt < 4; ++kt) {
            const int koff = kt * 32;
            uint32_t ah[2][4], al[2][4];
            #pragma unroll
            for (int mi = 0; mi < 2; ++mi) {
                ldsm_x4(ah[mi][0], ah[mi][1], ah[mi][2], ah[mi][3],
                        abase + mi * (16 * GP) + koff);
                ldsm_x4(al[mi][0], al[mi][1], al[mi][2], al[mi][3],
                        abase + (G_AL - G_AH) + mi * (16 * GP) + koff);
            }
            #pragma unroll
            for (int nh = 0; nh < 2; ++nh) {
                uint32_t b0, b1, b2, b3;
                ldsm_x4(b0, b1, b2, b3, bbase + nh * (16 * GP) + koff);
                #pragma unroll
                for (int mi = 0; mi < 2; ++mi) {
                    mma16816(acc[mi][nh * 2 + 0], ah[mi][0], ah[mi][1], ah[mi][2], ah[mi][3], b0, b1);
                    mma16816(acc[mi][nh * 2 + 0], al[mi][0], al[mi][1], al[mi][2], al[mi][3], b0, b1);
                    mma16816(acc[mi][nh * 2 + 1], ah[mi][0], ah[mi][1], ah[mi][2], ah[mi][3], b2, b3);
                    mma16816(acc[mi][nh * 2 + 1], al[mi][0], al[mi][1], al[mi][2], al[mi][3], b2, b3);
                }
            }
        }
    }

    // ---- epilogue ------------------------------------------------------------
    #pragma unroll
    for (int mi = 0; mi < 2; ++mi) {
        int r0 = m0 + wm * 32 + mi * 16 + g;
        #pragma unroll
        for (int ni = 0; ni < 4; ++ni) {
            int col = n0 + wn * 32 + ni * 8 + tq * 2;
            *(float2*)&C[(size_t)r0 * N + col] =
                make_float2(acc[mi][ni][0], acc[mi][ni][1]);
            *(float2*)&C[(size_t)(r0 + 8) * N + col] =
                make_float2(acc[mi][ni][2], acc[mi][ni][3]);
        }
    }
}

// =============================================================================
// sd + tconv fused: blocks [0,1024) -> sd (warp per node);
// blocks [1024, 1024 + (F/32)*256) -> transpose+fp16 convert.
// =============================================================================
template <int F>
__global__ __launch_bounds__(256)
void sdtconv_kernel(const float* __restrict__ Wh, const float* __restrict__ a,
                    float* __restrict__ s, float* __restrict__ d,
                    unsigned* __restrict__ dmaxu, __half* __restrict__ T)
{
    if (blockIdx.x < 1024) {
        int warp = (blockIdx.x * 256 + threadIdx.x) >> 5;
        int lane = threadIdx.x & 31;
        const float* row = Wh + (size_t)warp * F;
        float ss = 0.f, dd = 0.f;
        #pragma unroll
        for (int f = lane; f < F; f += 32) {
            float w = row[f];
            ss += w * a[f];
            dd += w * a[F + f];
        }
        #pragma unroll
        for (int o = 16; o; o >>= 1) {
            ss += __shfl_down_sync(0xffffffffu, ss, o);
            dd += __shfl_down_sync(0xffffffffu, dd, o);
        }
        if (lane == 0) {
            s[warp] = ss; d[warp] = dd;
            atomicMax(dmaxu, fenc(dd));
        }
    } else {
        __shared__ float tile[32][33];
        int b = blockIdx.x - 1024;
        int f0 = (b % (F / 32)) * 32;
        int m0 = (b / (F / 32)) * 32;
        int x = threadIdx.x & 31, y = threadIdx.x >> 5;
        #pragma unroll
        for (int yy = 0; yy < 4; ++yy)
            tile[y + yy * 8][x] = Wh[(size_t)(m0 + y + yy * 8) * F + f0 + x];
        __syncthreads();
        #pragma unroll
        for (int yy = 0; yy < 4; ++yy) {
            float v = tile[x][y + yy * 8];
            T[(size_t)(f0 + y + yy * 8) * N_NODES + m0 + x] = __float2half_rn(v);
        }
    }
}

// =============================================================================
// ef + pack_adj fused: blocks [0,32) -> ef; blocks [32, ...) -> adjacency pack
// =============================================================================
__global__ __launch_bounds__(256)
void efpack_kernel(const float* __restrict__ d, const unsigned* __restrict__ dmaxu,
                   float* __restrict__ E, float* __restrict__ F,
                   float* __restrict__ dmaxf,
                   const int* __restrict__ adj, unsigned* __restrict__ bits)
{
    if (blockIdx.x < 32) {
        float dm = fdec(*dmaxu);
        int i = blockIdx.x * 256 + threadIdx.x;
        float v = d[i] - dm;
        E[i] = __expf(v);
        F[i] = __expf(ALPHA * v);
        if (i == 0) *dmaxf = dm;
    } else {
        size_t idx = (size_t)(blockIdx.x - 32) * 256 + threadIdx.x;
        int v = adj[idx] > 0;
        unsigned b = __ballot_sync(0xffffffffu, v);
        if ((threadIdx.x & 31) == 0) bits[idx >> 5] = b;
    }
}

// plain ef for layers 2/3
__global__ __launch_bounds__(256)
void ef_kernel(const float* __restrict__ d, const unsigned* __restrict__ dmaxu,
               float* __restrict__ E, float* __restrict__ F,
               float* __restrict__ dmaxf)
{
    float dm = fdec(*dmaxu);
    int i = blockIdx.x * 256 + threadIdx.x;
    float v = d[i] - dm;
    E[i] = __expf(v);
    F[i] = __expf(ALPHA * v);
    if (i == 0) *dmaxf = dm;
}

// =============================================================================
// attn1: h = ELU( softmax(mask(leaky(s_i+d_j))) @ Wh1 )  F=256, fp16 1-product
// (unchanged from R12 passing version)
// =============================================================================
static constexpr int P2      = 272;
static constexpr int S1_B    = 0;
static constexpr int S1_BBUF = 69632;
static constexpr int S1_A    = 139264;
static constexpr int S1_ABUF = 17408;
static constexpr int S1_ZT   = 174080;
static constexpr int S1_ZR   = 176128;
static constexpr int SMEM1   = 176384;

__global__ __launch_bounds__(512, 1)
void attn1_kernel(const unsigned* __restrict__ adjb,
                  const __half* __restrict__ BT,
                  const float* __restrict__ svec, const float* __restrict__ dvec,
                  const float* __restrict__ EJ, const float* __restrict__ FJ,
                  const float* __restrict__ dmaxp, float* __restrict__ outp)
{
    extern __shared__ __align__(16) char smem[];
    const uint32_t sb = smem_u32(smem);
    const int tid = threadIdx.x, warp = tid >> 5, lane = tid & 31;
    const int g = lane >> 2, tq = lane & 3;
    const int i0 = blockIdx.x * 64;
    const int n0w = warp * 16;

    const uint32_t a_lane = ((lane & 7) + ((lane >> 3) & 1) * 8) * P2 + ((lane >> 4) & 1) * 16;
    const uint32_t b_lane = ((lane & 7) + ((lane >> 4) & 1) * 8) * P2 + ((lane >> 3) & 1) * 16;

    const int r = tid >> 3, q = tid & 7;
    const float sv = svec[i0 + r];
    const float mv = sv + *dmaxp;
    const float m_r = mv > 0.f ? mv : ALPHA * mv;
    const float RA = __expf(mv - m_r);
    const float RB = __expf(ALPHA * mv - m_r);
    float zacc = 0.f;

    float acc[4][2][4];
    #pragma unroll
    for (int a = 0; a < 4; ++a)
        #pragma unroll
        for (int b = 0; b < 2; ++b)
            #pragma unroll
            for (int c = 0; c < 4; ++c) acc[a][b][c] = 0.f;

    const size_t row_adj = (size_t)(i0 + r) * NWORDS;

    for (int c = tid; c < 4096; c += 512) {
        int f = c >> 4, ch = c & 15;
        cp_async16(sb + S1_B + f * P2 + ch * 16, BT + (size_t)f * N_NODES + ch * 8);
    }
    CP_COMMIT();

    for (int t = 0; t < N_NODES / 128; ++t) {
        const int j0 = t * 128;
        const int buf = t & 1;

        if (t + 1 < N_NODES / 128) {
            const int j1 = j0 + 128;
            const uint32_t bb = sb + S1_B + (buf ^ 1) * S1_BBUF;
            for (int c = tid; c < 4096; c += 512) {
                int f = c >> 4, ch = c & 15;
                cp_async16(bb + f * P2 + ch * 16, BT + (size_t)f * N_NODES + j1 + ch * 8);
            }
        }
        CP_COMMIT();

        {
            unsigned w = adjb[row_adj + (j0 >> 5) + (q >> 1)];
            unsigned bits = w >> ((q & 1) * 16);
            char* ap = smem + S1_A + buf * S1_ABUF + r * P2;
            const int jb = q * 16;
            const float4* d4 = (const float4*)(dvec + j0 + jb);
            const float4* e4 = (const float4*)(EJ + j0 + jb);
            const float4* f4 = (const float4*)(FJ + j0 + jb);
            #pragma unroll
            for (int v = 0; v < 4; ++v) {
                float4 dd = d4[v], ee = e4[v], ff = f4[v];
                float p0 = ((bits >> (v * 4 + 0)) & 1)
                         ? ((sv + dd.x > 0.f) ? RA * ee.x : RB * ff.x) : 0.f;
                float p1 = ((bits >> (v * 4 + 1)) & 1)
                         ? ((sv + dd.y > 0.f) ? RA * ee.y : RB * ff.y) : 0.f;
                float p2 = ((bits >> (v * 4 + 2)) & 1)
                         ? ((sv + dd.z > 0.f) ? RA * ee.z : RB * ff.z) : 0.f;
                float p3 = ((bits >> (v * 4 + 3)) & 1)
                         ? ((sv + dd.w > 0.f) ? RA * ee.w : RB * ff.w) : 0.f;
                zacc += p0 + p1 + p2 + p3;
                __half2 h01 = __floats2half2_rn(p0, p1);
                __half2 h23 = __floats2half2_rn(p2, p3);
                uint2 pk;
                pk.x = *(uint32_t*)&h01;
                pk.y = *(uint32_t*)&h23;
                *(uint2*)(ap + (jb + v * 4) * 2) = pk;
            }
        }

        CP_WAIT1();
        __syncthreads();

        const uint32_t abase = sb + S1_A + buf * S1_ABUF + a_lane;
        const uint32_t bbase = sb + S1_B + buf * S1_BBUF + n0w * P2 + b_lane;
        #pragma unroll
        for (int kt = 0; kt < 8; ++kt) {
            const int koff = kt * 32;
            uint32_t ah[4][4];
            #pragma unroll
            for (int mi = 0; mi < 4; ++mi)
                ldsm_x4(ah[mi][0], ah[mi][1], ah[mi][2], ah[mi][3],
                        abase + mi * (16 * P2) + koff);
            uint32_t b0, b1, b2, b3;
            ldsm_x4(b0, b1, b2, b3, bbase + koff);
            #pragma unroll
            for (int mi = 0; mi < 4; ++mi) {
                mma16816(acc[mi][0], ah[mi][0], ah[mi][1], ah[mi][2], ah[mi][3], b0, b1);
                mma16816(acc[mi][1], ah[mi][0], ah[mi][1], ah[mi][2], ah[mi][3], b2, b3);
            }
        }
        __syncthreads();
    }

    float* zt = (float*)(smem + S1_ZT);
    float* zr = (float*)(smem + S1_ZR);
    zt[tid] = zacc;
    __syncthreads();
    if (tid < 64) {
        float z = 0.f;
        #pragma unroll
        for (int k = 0; k < 8; ++k) z += zt[8 * tid + k];
        zr[tid] = z;
    }
    __syncthreads();
    #pragma unroll
    for (int mi = 0; mi < 4; ++mi) {
        int r0 = mi * 16 + g;
        float iz0 = 1.f / zr[r0];
        float iz1 = 1.f / zr[r0 + 8];
        #pragma unroll
        for (int ni = 0; ni < 2; ++ni) {
            int col = n0w + ni * 8 + tq * 2;
            float v0 = acc[mi][ni][0] * iz0; v0 = v0 > 0.f ? v0 : expm1f(v0);
            float v1 = acc[mi][ni][1] * iz0; v1 = v1 > 0.f ? v1 : expm1f(v1);
            float v2 = acc[mi][ni][2] * iz1; v2 = v2 > 0.f ? v2 : expm1f(v2);
            float v3 = acc[mi][ni][3] * iz1; v3 = v3 > 0.f ? v3 : expm1f(v3);
            *(float2*)&outp[(size_t)(i0 + r0) * NHID + col]     = make_float2(v0, v1);
            *(float2*)&outp[(size_t)(i0 + r0 + 8) * NHID + col] = make_float2(v2, v3);
        }
    }
}

// =============================================================================
// attn23: fused mu & lv attention (unchanged from R12 passing version)
// =============================================================================
static constexpr int S2_B    = 0;
static constexpr int S2_BBUF = 34816;
static constexpr int S2_BMAT = 17408;
static constexpr int S2_A    = 69632;
static constexpr int S2_ABUF = 34816;
static constexpr int S2_AMAT = 17408;
static constexpr int S2_ZT   = 139264;
static constexpr int S2_ZR   = 143360;
static constexpr int SMEM2   = 143872;

__global__ __launch_bounds__(512, 1)
void attn23_kernel(const unsigned* __restrict__ adjb,
                   const __half* __restrict__ Bm, const __half* __restrict__ Bv,
                   const float* __restrict__ smuv, const float* __restrict__ dmuv,
                   const float* __restrict__ slvv, const float* __restrict__ dlvv,
                   const float* __restrict__ Em, const float* __restrict__ Fm,
                   const float* __restrict__ Ev, const float* __restrict__ Fv,
                   const float* __restrict__ dmaxp,
                   float* __restrict__ out_mu, float* __restrict__ out_lv)
{
    extern __shared__ __align__(16) char smem[];
    const uint32_t sb = smem_u32(smem);
    const int tid = threadIdx.x, warp = tid >> 5, lane = tid & 31;
    const int g = lane >> 2, tq = lane & 3;
    const int i0 = blockIdx.x * 64;
    const int which = warp >> 3;
    const int n0w = (warp & 7) * 8;

    const uint32_t a_lane = ((lane & 7) + ((lane >> 3) & 1) * 8) * P2 + ((lane >> 4) & 1) * 16;
    const uint32_t b_lane = (lane & 7) * P2 + ((lane >> 3) & 1) * 16;

    const int r = tid >> 3, q = tid & 7;
    const float svm = smuv[i0 + r], svv = slvv[i0 + r];
    const float mvm = svm + dmaxp[0], mvv = svv + dmaxp[1];
    const float mm = mvm > 0.f ? mvm : ALPHA * mvm;
    const float ml = mvv > 0.f ? mvv : ALPHA * mvv;
    const float RAm = __expf(mvm - mm), RBm = __expf(ALPHA * mvm - mm);
    const float RAv = __expf(mvv - ml), RBv = __expf(ALPHA * mvv - ml);
    float zm = 0.f, zv = 0.f;

    float acc[4][4];
    #pragma unroll
    for (int a = 0; a < 4; ++a)
        #pragma unroll
        for (int c = 0; c < 4; ++c) acc[a][c] = 0.f;

    const size_t row_adj = (size_t)(i0 + r) * NWORDS;

    for (int c = tid; c < 2048; c += 512) {
        int mat = c >> 10, f = (c >> 4) & 63, ch = c & 15;
        const __half* src = (mat ? Bv : Bm) + (size_t)f * N_NODES + ch * 8;
        cp_async16(sb + S2_B + mat * S2_BMAT + f * P2 + ch * 16, src);
    }
    CP_COMMIT();

    for (int t = 0; t < N_NODES / 128; ++t) {
        const int j0 = t * 128;
        const int buf = t & 1;

        if (t + 1 < N_NODES / 128) {
            const int j1 = j0 + 128;
            const uint32_t bbs = sb + S2_B + (buf ^ 1) * S2_BBUF;
            for (int c = tid; c < 2048; c += 512) {
                int mat = c >> 10, f = (c >> 4) & 63, ch = c & 15;
                const __half* src = (mat ? Bv : Bm) + (size_t)f * N_NODES + j1 + ch * 8;
                cp_async16(bbs + mat * S2_BMAT + f * P2 + ch * 16, src);
            }
        }
        CP_COMMIT();

        {
            unsigned w = adjb[row_adj + (j0 >> 5) + (q >> 1)];
            unsigned bits = w >> ((q & 1) * 16);
            char* apm = smem + S2_A + buf * S2_ABUF + r * P2;
            char* apv = apm + S2_AMAT;
            const int jb = q * 16;
            const float4* dm4 = (const float4*)(dmuv + j0 + jb);
            const float4* em4 = (const float4*)(Em + j0 + jb);
            const float4* fm4 = (const float4*)(Fm + j0 + jb);
            const float4* dv4 = (const float4*)(dlvv + j0 + jb);
            const float4* ev4 = (const float4*)(Ev + j0 + jb);
            const float4* fv4 = (const float4*)(Fv + j0 + jb);
            #pragma unroll
            for (int v = 0; v < 4; ++v) {
                int b0 = (bits >> (v * 4 + 0)) & 1;
                int b1 = (bits >> (v * 4 + 1)) & 1;
                int b2 = (bits >> (v * 4 + 2)) & 1;
                int b3 = (bits >> (v * 4 + 3)) & 1;

                float4 dd = dm4[v], ee = em4[v], ff = fm4[v];
                float p0 = b0 ? ((svm + dd.x > 0.f) ? RAm * ee.x : RBm * ff.x) : 0.f;
                float p1 = b1 ? ((svm + dd.y > 0.f) ? RAm * ee.y : RBm * ff.y) : 0.f;
                float p2 = b2 ? ((svm + dd.z > 0.f) ? RAm * ee.z : RBm * ff.z) : 0.f;
                float p3 = b3 ? ((svm + dd.w > 0.f) ? RAm * ee.w : RBm * ff.w) : 0.f;
                zm += p0 + p1 + p2 + p3;
                __half2 h01 = __floats2half2_rn(p0, p1);
                __half2 h23 = __floats2half2_rn(p2, p3);
                uint2 pk;
                pk.x = *(uint32_t*)&h01;
                pk.y = *(uint32_t*)&h23;
                *(uint2*)(apm + (jb + v * 4) * 2) = pk;

                dd = dv4[v]; ee = ev4[v]; ff = fv4[v];
                p0 = b0 ? ((svv + dd.x > 0.f) ? RAv * ee.x : RBv * ff.x) : 0.f;
                p1 = b1 ? ((svv + dd.y > 0.f) ? RAv * ee.y : RBv * ff.y) : 0.f;
                p2 = b2 ? ((svv + dd.z > 0.f) ? RAv * ee.z : RBv * ff.z) : 0.f;
                p3 = b3 ? ((svv + dd.w > 0.f) ? RAv * ee.w : RBv * ff.w) : 0.f;
                zv += p0 + p1 + p2 + p3;
                h01 = __floats2half2_rn(p0, p1);
                h23 = __floats2half2_rn(p2, p3);
                pk.x = *(uint32_t*)&h01;
                pk.y = *(uint32_t*)&h23;
                *(uint2*)(apv + (jb + v * 4) * 2) = pk;
            }
        }

        CP_WAIT1();
        __syncthreads();

        const uint32_t abase = sb + S2_A + buf * S2_ABUF + which * S2_AMAT + a_lane;
        const uint32_t bbase = sb + S2_B + buf * S2_BBUF + which * S2_BMAT
                             + n0w * P2 + b_lane;
        #pragma unroll
        for (int kt = 0; kt < 8; ++kt) {
            const int koff = kt * 32;
            uint32_t ah[4][4];
            #pragma unroll
            for (int mi = 0; mi < 4; ++mi)
                ldsm_x4(ah[mi][0], ah[mi][1], ah[mi][2], ah[mi][3],
                        abase + mi * (16 * P2) + koff);
            uint32_t b0, b1;
            ldsm_x2(b0, b1, bbase + koff);
            #pragma unroll
            for (int mi = 0; mi < 4; ++mi)
                mma16816(acc[mi], ah[mi][0], ah[mi][1], ah[mi][2], ah[mi][3], b0, b1);
        }
        __syncthreads();
    }

    float* ztm = (float*)(smem + S2_ZT);
    float* ztv = ztm + 512;
    float* zrm = (float*)(smem + S2_ZR);
    float* zrv = zrm + 64;
    ztm[tid] = zm; ztv[tid] = zv;
    __syncthreads();
    if (tid < 64) {
        float a = 0.f, b = 0.f;
        #pragma unroll
        for (int k = 0; k < 8; ++k) { a += ztm[8 * tid + k]; b += ztv[8 * tid + k]; }
        zrm[tid] = a; zrv[tid] = b;
    }
    __syncthreads();
    const float* zrow = which ? zrv : zrm;
    float* outw = which ? out_lv : out_mu;
    #pragma unroll
    for (int mi = 0; mi < 4; ++mi) {
        int r0 = mi * 16 + g;
        float iz0 = 1.f / zrow[r0];
        float iz1 = 1.f / zrow[r0 + 8];
        int col = n0w + tq * 2;
        *(float2*)&outw[(size_t)(i0 + r0) * NLAT + col] =
            make_float2(acc[mi][0] * iz0, acc[mi][1] * iz0);
        *(float2*)&outw[(size_t)(i0 + r0 + 8) * NLAT + col] =
            make_float2(acc[mi][2] * iz1, acc[mi][3] * iz1);
    }
}

// ---------------- z = mu + eps*exp(0.5*lv); logits = z @ Wc + bc ------------
__global__ __launch_bounds__(128)
void final_kernel(const float* __restrict__ mu, const float* __restrict__ lv,
                  const float* __restrict__ eps, const float* __restrict__ Wc,
                  const float* __restrict__ bc, float* __restrict__ logits)
{
    __shared__ float zs[8 * 64];
    const int tid = threadIdx.x;
    const int r0 = blockIdx.x * 8;
    #pragma unroll
    for (int l = tid; l < 8 * 64; l += 128) {
        int r = l >> 6, k = l & 63;
        size_t idx = (size_t)(r0 + r) * 64 + k;
        zs[l] = mu[idx] + eps[idx] * __expf(0.5f * lv[idx]);
    }
    __syncthreads();
    int r = tid >> 4, n = tid & 15;
    float acc = bc[n];
    #pragma unroll
    for (int k = 0; k < 64; ++k) acc += zs[r * 64 + k] * Wc[k * 16 + n];
    logits[(size_t)(r0 + r) * 16 + n] = acc;
}

// ------------------------------ launch --------------------------------------
extern "C" void kernel_launch(void* const* d_in, const int* in_sizes, int n_in,
                              void* d_out, int out_size)
{
    const float* x   = (const float*)d_in[0];
    const int*   adj = (const int*)  d_in[1];
    const float* eps = (const float*)d_in[2];
    const float* W1  = (const float*)d_in[3];
    const float* a1  = (const float*)d_in[4];
    const float* Wmu = (const float*)d_in[5];
    const float* amu = (const float*)d_in[6];
    const float* Wlv = (const float*)d_in[7];
    const float* alv = (const float*)d_in[8];
    const float* Wc  = (const float*)d_in[9];
    const float* bc  = (const float*)d_in[10];

    float* out    = (float*)d_out;
    float* logits = out;
    float* mu     = out + (size_t)N_NODES * NCLASS;
    float* lv     = mu  + (size_t)N_NODES * NLAT;

    float *Wh1, *h, *Whmu, *Whlv, *s1, *d1, *smu, *dmu, *slv, *dlv;
    float *E1, *F1, *Emu, *Fmu, *Elv, *Flv, *dmaxf;
    unsigned *dmaxu;
    __half *T1, *Tm, *Tv;
    unsigned* adjb;
    cudaGetSymbolAddress((void**)&Wh1,  g_Wh1);
    cudaGetSymbolAddress((void**)&h,    g_h);
    cudaGetSymbolAddress((void**)&Whmu, g_Whmu);
    cudaGetSymbolAddress((void**)&Whlv, g_Whlv);
    cudaGetSymbolAddress((void**)&s1,   g_s1);
    cudaGetSymbolAddress((void**)&d1,   g_d1);
    cudaGetSymbolAddress((void**)&smu,  g_smu);
    cudaGetSymbolAddress((void**)&dmu,  g_dmu);
    cudaGetSymbolAddress((void**)&slv,  g_slv);
    cudaGetSymbolAddress((void**)&dlv,  g_dlv);
    cudaGetSymbolAddress((void**)&dmaxu, g_dmaxu);
    cudaGetSymbolAddress((void**)&dmaxf, g_dmaxf);
    cudaGetSymbolAddress((void**)&E1,   g_E1);
    cudaGetSymbolAddress((void**)&F1,   g_F1);
    cudaGetSymbolAddress((void**)&Emu,  g_Emu);
    cudaGetSymbolAddress((void**)&Fmu,  g_Fmu);
    cudaGetSymbolAddress((void**)&Elv,  g_Elv);
    cudaGetSymbolAddress((void**)&Flv,  g_Flv);
    cudaGetSymbolAddress((void**)&T1,   g_T1);
    cudaGetSymbolAddress((void**)&Tm,   g_Tm);
    cudaGetSymbolAddress((void**)&Tv,   g_Tv);
    cudaGetSymbolAddress((void**)&adjb, g_adjb);

    cudaFuncSetAttribute(gemm_mma_kernel, cudaFuncAttributeMaxDynamicSharedMemorySize, GSMEM);
    cudaFuncSetAttribute(attn1_kernel,  cudaFuncAttributeMaxDynamicSharedMemorySize, SMEM1);
    cudaFuncSetAttribute(attn23_kernel, cudaFuncAttributeMaxDynamicSharedMemorySize, SMEM2);

    // 0: gemm1 (also zero-inits dmax accumulators)
    gemm_mma_kernel<<<dim3(NHID / 64, N_NODES / 128), 256, GSMEM>>>(
        x, W1, Wh1, N_NODES, NHID, NFEAT, dmaxu, 1);
    // 1: sd + tconv fused
    sdtconv_kernel<NHID><<<1024 + (NHID / 32) * (N_NODES / 32), 256>>>(
        Wh1, a1, s1, d1, dmaxu + 0, T1);
    // 2: ef + pack_adj fused
    efpack_kernel<<<32 + (size_t)N_NODES * N_NODES / 256, 256>>>(
        d1, dmaxu + 0, E1, F1, dmaxf + 0, adj, adjb);
    // 3: attn1  (ncu capture slot)
    attn1_kernel<<<N_NODES / 64, 512, SMEM1>>>(adjb, T1, s1, d1, E1, F1, dmaxf + 0, h);

    // layer 2/3
    gemm_mma_kernel<<<dim3(NLAT / 64, N_NODES / 128), 256, GSMEM>>>(
        h, Wmu, Whmu, N_NODES, NLAT, NHID, dmaxu, 0);
    gemm_mma_kernel<<<dim3(NLAT / 64, N_NODES / 128), 256, GSMEM>>>(
        h, Wlv, Whlv, N_NODES, NLAT, NHID, dmaxu, 0);
    sdtconv_kernel<NLAT><<<1024 + (NLAT / 32) * (N_NODES / 32), 256>>>(
        Whmu, amu, smu, dmu, dmaxu + 1, Tm);
    sdtconv_kernel<NLAT><<<1024 + (NLAT / 32) * (N_NODES / 32), 256>>>(
        Whlv, alv, slv, dlv, dmaxu + 2, Tv);
    ef_kernel<<<N_NODES / 256, 256>>>(dmu, dmaxu + 1, Emu, Fmu, dmaxf + 1);
    ef_kernel<<<N_NODES / 256, 256>>>(dlv, dmaxu + 2, Elv, Flv, dmaxf + 2);
    attn23_kernel<<<N_NODES / 64, 512, SMEM2>>>(adjb, Tm, Tv,
                                                smu, dmu, slv, dlv,
                                                Emu, Fmu, Elv, Flv, dmaxf + 1, mu, lv);

    // reparameterize + classifier
    final_kernel<<<N_NODES / 8, 128>>>(mu, lv, eps, Wc, bc, logits);
}

// round 14
// speedup vs baseline: 1.7900x; 1.1797x over previous
#include <cuda_runtime.h>
#include <cuda_bf16.h>
#include <cuda_fp16.h>
#include <math.h>
#include <stdint.h>

#define N_NODES 8192
#define NFEAT   512
#define NHID    256
#define NLAT    64
#define NCLASS  16
#define ALPHA   0.2f
#define NWORDS  (N_NODES / 32)

// ------------------------------ device scratch ------------------------------
__device__ __align__(16) float g_Wh1 [N_NODES * NHID];
__device__ __align__(16) float g_h   [N_NODES * NHID];
__device__ __align__(16) float g_Whmu[N_NODES * NLAT];
__device__ __align__(16) float g_Whlv[N_NODES * NLAT];
__device__ __align__(16) __half g_T1[NHID * N_NODES];
__device__ __align__(16) __half g_Tm[NLAT * N_NODES];
__device__ __align__(16) __half g_Tv[NLAT * N_NODES];
__device__ unsigned g_adjb[(size_t)N_NODES * NWORDS];
__device__ float g_s1[N_NODES], g_d1[N_NODES];
__device__ float g_smu[N_NODES], g_dmu[N_NODES];
__device__ float g_slv[N_NODES], g_dlv[N_NODES];
__device__ __align__(16) float g_E1[N_NODES],  g_F1[N_NODES];
__device__ __align__(16) float g_Emu[N_NODES], g_Fmu[N_NODES];
__device__ __align__(16) float g_Elv[N_NODES], g_Flv[N_NODES];
__device__ unsigned g_dmaxu[4];
__device__ float    g_dmaxf[4];

// ------------------------------ helpers -------------------------------------
__device__ __forceinline__ uint32_t smem_u32(const void* p) {
    uint32_t a;
    asm("{ .reg .u64 t; cvta.to.shared.u64 t, %1; cvt.u32.u64 %0, t; }"
        : "=r"(a) : "l"(p));
    return a;
}
__device__ __forceinline__ void cp_async16(uint32_t dst, const void* src) {
    asm volatile("cp.async.cg.shared.global [%0], [%1], 16;"
                 :: "r"(dst), "l"(src) : "memory");
}
#define CP_COMMIT() asm volatile("cp.async.commit_group;" ::: "memory")
#define CP_WAIT1()  asm volatile("cp.async.wait_group 1;"  ::: "memory")

__device__ __forceinline__ unsigned fenc(float x) {
    int ix = __float_as_int(x);
    return ix >= 0 ? ((unsigned)ix | 0x80000000u) : ~(unsigned)ix;
}
__device__ __forceinline__ float fdec(unsigned u) {
    int ix = (u & 0x80000000u) ? (int)(u & 0x7FFFFFFFu) : ~(int)u;
    return __int_as_float(ix);
}

// mma.sync m16n8k16 row.col f16 -> f32 (HMMA on sm_103)
__device__ __forceinline__ void mma16816(float* c,
    uint32_t a0, uint32_t a1, uint32_t a2, uint32_t a3,
    uint32_t b0, uint32_t b1)
{
    asm volatile(
        "mma.sync.aligned.m16n8k16.row.col.f32.f16.f16.f32 "
        "{%0,%1,%2,%3}, {%4,%5,%6,%7}, {%8,%9}, {%0,%1,%2,%3};"
        : "+f"(c[0]), "+f"(c[1]), "+f"(c[2]), "+f"(c[3])
        : "r"(a0), "r"(a1), "r"(a2), "r"(a3), "r"(b0), "r"(b1));
}
__device__ __forceinline__ void ldsm_x4(uint32_t& r0, uint32_t& r1,
                                        uint32_t& r2, uint32_t& r3, uint32_t addr)
{
    asm volatile("ldmatrix.sync.aligned.m8n8.x4.shared.b16 {%0,%1,%2,%3}, [%4];"
                 : "=r"(r0), "=r"(r1), "=r"(r2), "=r"(r3) : "r"(addr));
}
__device__ __forceinline__ void ldsm_x2(uint32_t& r0, uint32_t& r1, uint32_t addr)
{
    asm volatile("ldmatrix.sync.aligned.m8n8.x2.shared.b16 {%0,%1}, [%2];"
                 : "=r"(r0), "=r"(r1) : "r"(addr));
}

// =============================================================================
// gemm_mma (unchanged from R13 passing version)
// =============================================================================
static constexpr int GP    = 144;
static constexpr int G_AH  = 0;
static constexpr int G_AL  = 18432;
static constexpr int G_B   = 36864;
static constexpr int GSMEM = 46080;

__global__ __launch_bounds__(256, 1)
void gemm_mma_kernel(const float* __restrict__ A, const float* __restrict__ B,
                     float* __restrict__ C, int M, int N, int K,
                     unsigned* __restrict__ dmaxu, int init_flag)
{
    extern __shared__ __align__(16) char smem[];
    const uint32_t sb = smem_u32(smem);
    const int tid = threadIdx.x, warp = tid >> 5, lane = tid & 31;
    const int g = lane >> 2, tq = lane & 3;
    const int wm = warp >> 1, wn = warp & 1;
    const int m0 = blockIdx.y * 128, n0 = blockIdx.x * 64;

    if (init_flag && blockIdx.x == 0 && blockIdx.y == 0 && tid < 4)
        dmaxu[tid] = 0u;

    const uint32_t a_lane = ((lane & 7) + ((lane >> 3) & 1) * 8) * GP + ((lane >> 4) & 1) * 16;
    const uint32_t b_lane = ((lane & 7) + ((lane >> 4) & 1) * 8) * GP + ((lane >> 3) & 1) * 16;

    float acc[2][4][4];
    #pragma unroll
    for (int a = 0; a < 2; ++a)
        #pragma unroll
        for (int b = 0; b < 4; ++b)
            #pragma unroll
            for (int c = 0; c < 4; ++c) acc[a][b][c] = 0.f;

    for (int k0 = 0; k0 < K; k0 += 64) {
        __syncthreads();
        #pragma unroll
        for (int i = 0; i < 8; ++i) {
            int c = tid + i * 256;
            int row = c >> 4, kq = (c & 15) * 4;
            float4 v = *(const float4*)&A[(size_t)(m0 + row) * K + k0 + kq];
            __half h0 = __float2half_rn(v.x), h1 = __float2half_rn(v.y);
            __half h2 = __float2half_rn(v.z), h3 = __float2half_rn(v.w);
            __half l0 = __float2half_rn(v.x - __half2float(h0));
            __half l1 = __float2half_rn(v.y - __half2float(h1));
            __half l2 = __float2half_rn(v.z - __half2float(h2));
            __half l3 = __float2half_rn(v.w - __half2float(h3));
            __half2 hh01 = __halves2half2(h0, h1), hh23 = __halves2half2(h2, h3);
            __half2 ll01 = __halves2half2(l0, l1), ll23 = __halves2half2(l2, l3);
            uint2 ph, pl;
            ph.x = *(uint32_t*)&hh01; ph.y = *(uint32_t*)&hh23;
            pl.x = *(uint32_t*)&ll01; pl.y = *(uint32_t*)&ll23;
            *(uint2*)(smem + G_AH + row * GP + kq * 2) = ph;
            *(uint2*)(smem + G_AL + row * GP + kq * 2) = pl;
        }
        #pragma unroll
        for (int i = 0; i < 4; ++i) {
            int c = tid + i * 256;
            int kk = c >> 4, nq = (c & 15) * 4;
            float4 v = *(const float4*)&B[(size_t)(k0 + kk) * N + n0 + nq];
            *(__half*)(smem + G_B + (nq + 0) * GP + kk * 2) = __float2half_rn(v.x);
            *(__half*)(smem + G_B + (nq + 1) * GP + kk * 2) = __float2half_rn(v.y);
            *(__half*)(smem + G_B + (nq + 2) * GP + kk * 2) = __float2half_rn(v.z);
            *(__half*)(smem + G_B + (nq + 3) * GP + kk * 2) = __float2half_rn(v.w);
        }
        __syncthreads();

        const uint32_t abase = sb + G_AH + (wm * 32) * GP + a_lane;
        const uint32_t bbase = sb + G_B + (wn * 32) * GP + b_lane;
        #pragma unroll
        for (int kt = 0; kt < 4; ++kt) {
            const int koff = kt * 32;
            uint32_t ah[2][4], al[2][4];
            #pragma unroll
            for (int mi = 0; mi < 2; ++mi) {
                ldsm_x4(ah[mi][0], ah[mi][1], ah[mi][2], ah[mi][3],
                        abase + mi * (16 * GP) + koff);
                ldsm_x4(al[mi][0], al[mi][1], al[mi][2], al[mi][3],
                        abase + (G_AL - G_AH) + mi * (16 * GP) + koff);
            }
            #pragma unroll
            for (int nh = 0; nh < 2; ++nh) {
                uint32_t b0, b1, b2, b3;
                ldsm_x4(b0, b1, b2, b3, bbase + nh * (16 * GP) + koff);
                #pragma unroll
                for (int mi = 0; mi < 2; ++mi) {
                    mma16816(acc[mi][nh * 2 + 0], ah[mi][0], ah[mi][1], ah[mi][2], ah[mi][3], b0, b1);
                    mma16816(acc[mi][nh * 2 + 0], al[mi][0], al[mi][1], al[mi][2], al[mi][3], b0, b1);
                    mma16816(acc[mi][nh * 2 + 1], ah[mi][0], ah[mi][1], ah[mi][2], ah[mi][3], b2, b3);
                    mma16816(acc[mi][nh * 2 + 1], al[mi][0], al[mi][1], al[mi][2], al[mi][3], b2, b3);
                }
            }
        }
    }

    #pragma unroll
    for (int mi = 0; mi < 2; ++mi) {
        int r0 = m0 + wm * 32 + mi * 16 + g;
        #pragma unroll
        for (int ni = 0; ni < 4; ++ni) {
            int col = n0 + wn * 32 + ni * 8 + tq * 2;
            *(float2*)&C[(size_t)r0 * N + col] =
                make_float2(acc[mi][ni][0], acc[mi][ni][1]);
            *(float2*)&C[(size_t)(r0 + 8) * N + col] =
                make_float2(acc[mi][ni][2], acc[mi][ni][3]);
        }
    }
}

// =============================================================================
// sd + tconv fused (unchanged)
// =============================================================================
template <int F>
__global__ __launch_bounds__(256)
void sdtconv_kernel(const float* __restrict__ Wh, const float* __restrict__ a,
                    float* __restrict__ s, float* __restrict__ d,
                    unsigned* __restrict__ dmaxu, __half* __restrict__ T)
{
    if (blockIdx.x < 1024) {
        int warp = (blockIdx.x * 256 + threadIdx.x) >> 5;
        int lane = threadIdx.x & 31;
        const float* row = Wh + (size_t)warp * F;
        float ss = 0.f, dd = 0.f;
        #pragma unroll
        for (int f = lane; f < F; f += 32) {
            float w = row[f];
            ss += w * a[f];
            dd += w * a[F + f];
        }
        #pragma unroll
        for (int o = 16; o; o >>= 1) {
            ss += __shfl_down_sync(0xffffffffu, ss, o);
            dd += __shfl_down_sync(0xffffffffu, dd, o);
        }
        if (lane == 0) {
            s[warp] = ss; d[warp] = dd;
            atomicMax(dmaxu, fenc(dd));
        }
    } else {
        __shared__ float tile[32][33];
        int b = blockIdx.x - 1024;
        int f0 = (b % (F / 32)) * 32;
        int m0 = (b / (F / 32)) * 32;
        int x = threadIdx.x & 31, y = threadIdx.x >> 5;
        #pragma unroll
        for (int yy = 0; yy < 4; ++yy)
            tile[y + yy * 8][x] = Wh[(size_t)(m0 + y + yy * 8) * F + f0 + x];
        __syncthreads();
        #pragma unroll
        for (int yy = 0; yy < 4; ++yy) {
            float v = tile[x][y + yy * 8];
            T[(size_t)(f0 + y + yy * 8) * N_NODES + m0 + x] = __float2half_rn(v);
        }
    }
}

__global__ __launch_bounds__(256)
void efpack_kernel(const float* __restrict__ d, const unsigned* __restrict__ dmaxu,
                   float* __restrict__ E, float* __restrict__ F,
                   float* __restrict__ dmaxf,
                   const int* __restrict__ adj, unsigned* __restrict__ bits)
{
    if (blockIdx.x < 32) {
        float dm = fdec(*dmaxu);
        int i = blockIdx.x * 256 + threadIdx.x;
        float v = d[i] - dm;
        E[i] = __expf(v);
        F[i] = __expf(ALPHA * v);
        if (i == 0) *dmaxf = dm;
    } else {
        size_t idx = (size_t)(blockIdx.x - 32) * 256 + threadIdx.x;
        int v = adj[idx] > 0;
        unsigned b = __ballot_sync(0xffffffffu, v);
        if ((threadIdx.x & 31) == 0) bits[idx >> 5] = b;
    }
}

__global__ __launch_bounds__(256)
void ef_kernel(const float* __restrict__ d, const unsigned* __restrict__ dmaxu,
               float* __restrict__ E, float* __restrict__ F,
               float* __restrict__ dmaxf)
{
    float dm = fdec(*dmaxu);
    int i = blockIdx.x * 256 + threadIdx.x;
    float v = d[i] - dm;
    E[i] = __expf(v);
    F[i] = __expf(ALPHA * v);
    if (i == 0) *dmaxf = dm;
}

// =============================================================================
// attn1: CTA 32 rows x 256 F, grid 256, 512 thr, 16 warps (32r x 16c each),
// j-tile 64 double-buffered, pitch 144, target 2 CTAs/SM.
// =============================================================================
static constexpr int PA      = 144;
static constexpr int S1_B    = 0;          // 2 buf x 256x144
static constexpr int S1_BBUF = 36864;
static constexpr int S1_A    = 73728;      // 2 buf x 32x144
static constexpr int S1_ABUF = 4608;
static constexpr int S1_ZT   = 82944;      // 512 floats
static constexpr int S1_ZR   = 84992;      // 32 floats
static constexpr int SMEM1   = 85248;

__global__ __launch_bounds__(512, 2)
void attn1_kernel(const unsigned* __restrict__ adjb,
                  const __half* __restrict__ BT,
                  const float* __restrict__ svec, const float* __restrict__ dvec,
                  const float* __restrict__ EJ, const float* __restrict__ FJ,
                  const float* __restrict__ dmaxp, float* __restrict__ outp)
{
    extern __shared__ __align__(16) char smem[];
    const uint32_t sb = smem_u32(smem);
    const int tid = threadIdx.x, warp = tid >> 5, lane = tid & 31;
    const int g = lane >> 2, tq = lane & 3;
    const int i0 = blockIdx.x * 32;
    const int n0w = warp * 16;

    const uint32_t a_lane = ((lane & 7) + ((lane >> 3) & 1) * 8) * PA + ((lane >> 4) & 1) * 16;
    const uint32_t b_lane = ((lane & 7) + ((lane >> 4) & 1) * 8) * PA + ((lane >> 3) & 1) * 16;

    const int r = tid >> 4, q = tid & 15;     // row (32), 4-j slice
    const float sv = svec[i0 + r];
    const float mv = sv + *dmaxp;
    const float m_r = mv > 0.f ? mv : ALPHA * mv;
    const float RA = __expf(mv - m_r);
    const float RB = __expf(ALPHA * mv - m_r);
    float zacc = 0.f;

    float acc[2][2][4];
    #pragma unroll
    for (int a = 0; a < 2; ++a)
        #pragma unroll
        for (int b = 0; b < 2; ++b)
            #pragma unroll
            for (int c = 0; c < 4; ++c) acc[a][b][c] = 0.f;

    const size_t row_adj = (size_t)(i0 + r) * NWORDS;

    // prologue: stage B tile 0 (256 f x 64 j = 2048 chunks)
    for (int c = tid; c < 2048; c += 512) {
        int f = c >> 3, ch = c & 7;
        cp_async16(sb + S1_B + f * PA + ch * 16, BT + (size_t)f * N_NODES + ch * 8);
    }
    CP_COMMIT();

    for (int t = 0; t < N_NODES / 64; ++t) {
        const int j0 = t * 64;
        const int buf = t & 1;

        if (t + 1 < N_NODES / 64) {
            const int j1 = j0 + 64;
            const uint32_t bb = sb + S1_B + (buf ^ 1) * S1_BBUF;
            for (int c = tid; c < 2048; c += 512) {
                int f = c >> 3, ch = c & 7;
                cp_async16(bb + f * PA + ch * 16, BT + (size_t)f * N_NODES + j1 + ch * 8);
            }
        }
        CP_COMMIT();

        // ---- P-gen: thread covers (r, j in [q*4, q*4+4)) --------------------
        {
            unsigned w = adjb[row_adj + (j0 >> 5) + (q >> 3)];
            unsigned bits = (w >> ((q & 7) * 4)) & 0xF;
            const int jb = q * 4;
            float4 dd = *(const float4*)(dvec + j0 + jb);
            float4 ee = *(const float4*)(EJ + j0 + jb);
            float4 ff = *(const float4*)(FJ + j0 + jb);
            float p0 = (bits & 1) ? ((sv + dd.x > 0.f) ? RA * ee.x : RB * ff.x) : 0.f;
            float p1 = (bits & 2) ? ((sv + dd.y > 0.f) ? RA * ee.y : RB * ff.y) : 0.f;
            float p2 = (bits & 4) ? ((sv + dd.z > 0.f) ? RA * ee.z : RB * ff.z) : 0.f;
            float p3 = (bits & 8) ? ((sv + dd.w > 0.f) ? RA * ee.w : RB * ff.w) : 0.f;
            zacc += p0 + p1 + p2 + p3;
            __half2 h01 = __floats2half2_rn(p0, p1);
            __half2 h23 = __floats2half2_rn(p2, p3);
            uint2 pk;
            pk.x = *(uint32_t*)&h01;
            pk.y = *(uint32_t*)&h23;
            *(uint2*)(smem + S1_A + buf * S1_ABUF + r * PA + jb * 2) = pk;
        }

        CP_WAIT1();
        __syncthreads();

        // ---- MMA ------------------------------------------------------------
        const uint32_t abase = sb + S1_A + buf * S1_ABUF + a_lane;
        const uint32_t bbase = sb + S1_B + buf * S1_BBUF + n0w * PA + b_lane;
        #pragma unroll
        for (int kt = 0; kt < 4; ++kt) {
            const int koff = kt * 32;
            uint32_t a0[4], a1[4];
            ldsm_x4(a0[0], a0[1], a0[2], a0[3], abase + koff);
            ldsm_x4(a1[0], a1[1], a1[2], a1[3], abase + 16 * PA + koff);
            uint32_t b0, b1, b2, b3;
            ldsm_x4(b0, b1, b2, b3, bbase + koff);
            mma16816(acc[0][0], a0[0], a0[1], a0[2], a0[3], b0, b1);
            mma16816(acc[0][1], a0[0], a0[1], a0[2], a0[3], b2, b3);
            mma16816(acc[1][0], a1[0], a1[1], a1[2], a1[3], b0, b1);
            mma16816(acc[1][1], a1[0], a1[1], a1[2], a1[3], b2, b3);
        }
        __syncthreads();
    }

    // ---- epilogue --------------------------------------------------------------
    float* zt = (float*)(smem + S1_ZT);
    float* zr = (float*)(smem + S1_ZR);
    zt[tid] = zacc;
    __syncthreads();
    if (tid < 32) {
        float z = 0.f;
        #pragma unroll
        for (int k = 0; k < 16; ++k) z += zt[16 * tid + k];
        zr[tid] = z;
    }
    __syncthreads();
    #pragma unroll
    for (int mi = 0; mi < 2; ++mi) {
        int r0 = mi * 16 + g;
        float iz0 = 1.f / zr[r0];
        float iz1 = 1.f / zr[r0 + 8];
        #pragma unroll
        for (int ni = 0; ni < 2; ++ni) {
            int col = n0w + ni * 8 + tq * 2;
            float v0 = acc[mi][ni][0] * iz0; v0 = v0 > 0.f ? v0 : expm1f(v0);
            float v1 = acc[mi][ni][1] * iz0; v1 = v1 > 0.f ? v1 : expm1f(v1);
            float v2 = acc[mi][ni][2] * iz1; v2 = v2 > 0.f ? v2 : expm1f(v2);
            float v3 = acc[mi][ni][3] * iz1; v3 = v3 > 0.f ? v3 : expm1f(v3);
            *(float2*)&outp[(size_t)(i0 + r0) * NHID + col]     = make_float2(v0, v1);
            *(float2*)&outp[(size_t)(i0 + r0 + 8) * NHID + col] = make_float2(v2, v3);
        }
    }
}

// =============================================================================
// attn23: CTA 32 rows, both mats, grid 256, 512 thr.
// warps 0-7: mu cols [8w..8w+8); warps 8-15: lv. j-tile 64, pitch 144.
// =============================================================================
static constexpr int S2_B    = 0;          // 2 buf x [mu 64x144 | lv 64x144]
static constexpr int S2_BBUF = 18432;
static constexpr int S2_BMAT = 9216;
static constexpr int S2_A    = 36864;      // 2 buf x [mu 32x144 | lv 32x144]
static constexpr int S2_ABUF = 9216;
static constexpr int S2_AMAT = 4608;
static constexpr int S2_ZT   = 55296;      // 2 x 512 floats
static constexpr int S2_ZR   = 59392;      // 2 x 32 floats
static constexpr int SMEM2   = 59648;

__global__ __launch_bounds__(512, 2)
void attn23_kernel(const unsigned* __restrict__ adjb,
                   const __half* __restrict__ Bm, const __half* __restrict__ Bv,
                   const float* __restrict__ smuv, const float* __restrict__ dmuv,
                   const float* __restrict__ slvv, const float* __restrict__ dlvv,
                   const float* __restrict__ Em, const float* __restrict__ Fm,
                   const float* __restrict__ Ev, const float* __restrict__ Fv,
                   const float* __restrict__ dmaxp,
                   float* __restrict__ out_mu, float* __restrict__ out_lv)
{
    extern __shared__ __align__(16) char smem[];
    const uint32_t sb = smem_u32(smem);
    const int tid = threadIdx.x, warp = tid >> 5, lane = tid & 31;
    const int g = lane >> 2, tq = lane & 3;
    const int i0 = blockIdx.x * 32;
    const int which = warp >> 3;
    const int n0w = (warp & 7) * 8;

    const uint32_t a_lane = ((lane & 7) + ((lane >> 3) & 1) * 8) * PA + ((lane >> 4) & 1) * 16;
    const uint32_t b_lane = (lane & 7) * PA + ((lane >> 3) & 1) * 16;   // x2: lanes 0-15

    const int r = tid >> 4, q = tid & 15;     // row (32), 4-j slice
    const float svm = smuv[i0 + r], svv = slvv[i0 + r];
    const float mvm = svm + dmaxp[0], mvv = svv + dmaxp[1];
    const float mm = mvm > 0.f ? mvm : ALPHA * mvm;
    const float ml = mvv > 0.f ? mvv : ALPHA * mvv;
    const float RAm = __expf(mvm - mm), RBm = __expf(ALPHA * mvm - mm);
    const float RAv = __expf(mvv - ml), RBv = __expf(ALPHA * mvv - ml);
    float zm = 0.f, zv = 0.f;

    float acc[2][4];
    #pragma unroll
    for (int a = 0; a < 2; ++a)
        #pragma unroll
        for (int c = 0; c < 4; ++c) acc[a][c] = 0.f;

    const size_t row_adj = (size_t)(i0 + r) * NWORDS;

    // prologue: stage B tile 0 (2 mats x 64 f x 64 j = 1024 chunks)
    for (int c = tid; c < 1024; c += 512) {
        int mat = c >> 9, f = (c >> 3) & 63, ch = c & 7;
        const __half* src = (mat ? Bv : Bm) + (size_t)f * N_NODES + ch * 8;
        cp_async16(sb + S2_B + mat * S2_BMAT + f * PA + ch * 16, src);
    }
    CP_COMMIT();

    for (int t = 0; t < N_NODES / 64; ++t) {
        const int j0 = t * 64;
        const int buf = t & 1;

        if (t + 1 < N_NODES / 64) {
            const int j1 = j0 + 64;
            const uint32_t bbs = sb + S2_B + (buf ^ 1) * S2_BBUF;
            for (int c = tid; c < 1024; c += 512) {
                int mat = c >> 9, f = (c >> 3) & 63, ch = c & 7;
                const __half* src = (mat ? Bv : Bm) + (size_t)f * N_NODES + j1 + ch * 8;
                cp_async16(bbs + mat * S2_BMAT + f * PA + ch * 16, src);
            }
        }
        CP_COMMIT();

        // ---- P-gen: both mats, thread covers (r, j in [q*4, q*4+4)) ---------
        {
            unsigned w = adjb[row_adj + (j0 >> 5) + (q >> 3)];
            unsigned bits = (w >> ((q & 7) * 4)) & 0xF;
            const int jb = q * 4;

            float4 dd = *(const float4*)(dmuv + j0 + jb);
            float4 ee = *(const float4*)(Em + j0 + jb);
            float4 ff = *(const float4*)(Fm + j0 + jb);
            float p0 = (bits & 1) ? ((svm + dd.x > 0.f) ? RAm * ee.x : RBm * ff.x) : 0.f;
            float p1 = (bits & 2) ? ((svm + dd.y > 0.f) ? RAm * ee.y : RBm * ff.y) : 0.f;
            float p2 = (bits & 4) ? ((svm + dd.z > 0.f) ? RAm * ee.z : RBm * ff.z) : 0.f;
            float p3 = (bits & 8) ? ((svm + dd.w > 0.f) ? RAm * ee.w : RBm * ff.w) : 0.f;
            zm += p0 + p1 + p2 + p3;
            __half2 h01 = __floats2half2_rn(p0, p1);
            __half2 h23 = __floats2half2_rn(p2, p3);
            uint2 pk;
            pk.x = *(uint32_t*)&h01;
            pk.y = *(uint32_t*)&h23;
            *(uint2*)(smem + S2_A + buf * S2_ABUF + r * PA + jb * 2) = pk;

            dd = *(const float4*)(dlvv + j0 + jb);
            ee = *(const float4*)(Ev + j0 + jb);
            ff = *(const float4*)(Fv + j0 + jb);
            p0 = (bits & 1) ? ((svv + dd.x > 0.f) ? RAv * ee.x : RBv * ff.x) : 0.f;
            p1 = (bits & 2) ? ((svv + dd.y > 0.f) ? RAv * ee.y : RBv * ff.y) : 0.f;
            p2 = (bits & 4) ? ((svv + dd.z > 0.f) ? RAv * ee.z : RBv * ff.z) : 0.f;
            p3 = (bits & 8) ? ((svv + dd.w > 0.f) ? RAv * ee.w : RBv * ff.w) : 0.f;
            zv += p0 + p1 + p2 + p3;
            h01 = __floats2half2_rn(p0, p1);
            h23 = __floats2half2_rn(p2, p3);
            pk.x = *(uint32_t*)&h01;
            pk.y = *(uint32_t*)&h23;
            *(uint2*)(smem + S2_A + buf * S2_ABUF + S2_AMAT + r * PA + jb * 2) = pk;
        }

        CP_WAIT1();
        __syncthreads();

        // ---- MMA on this warp's matrix ---------------------------------------
        const uint32_t abase = sb + S2_A + buf * S2_ABUF + which * S2_AMAT + a_lane;
        const uint32_t bbase = sb + S2_B + buf * S2_BBUF + which * S2_BMAT
                             + n0w * PA + b_lane;
        #pragma unroll
        for (int kt = 0; kt < 4; ++kt) {
            const int koff = kt * 32;
            uint32_t a0[4], a1[4];
            ldsm_x4(a0[0], a0[1], a0[2], a0[3], abase + koff);
            ldsm_x4(a1[0], a1[1], a1[2], a1[3], abase + 16 * PA + koff);
            uint32_t b0, b1;
            ldsm_x2(b0, b1, bbase + koff);
            mma16816(acc[0], a0[0], a0[1], a0[2], a0[3], b0, b1);
            mma16816(acc[1], a1[0], a1[1], a1[2], a1[3], b0, b1);
        }
        __syncthreads();
    }

    // epilogue
    float* ztm = (float*)(smem + S2_ZT);
    float* ztv = ztm + 512;
    float* zrm = (float*)(smem + S2_ZR);
    float* zrv = zrm + 32;
    ztm[tid] = zm; ztv[tid] = zv;
    __syncthreads();
    if (tid < 32) {
        float a = 0.f, b = 0.f;
        #pragma unroll
        for (int k = 0; k < 16; ++k) { a += ztm[16 * tid + k]; b += ztv[16 * tid + k]; }
        zrm[tid] = a; zrv[tid] = b;
    }
    __syncthreads();
    const float* zrow = which ? zrv : zrm;
    float* outw = which ? out_lv : out_mu;
    #pragma unroll
    for (int mi = 0; mi < 2; ++mi) {
        int r0 = mi * 16 + g;
        float iz0 = 1.f / zrow[r0];
        float iz1 = 1.f / zrow[r0 + 8];
        int col = n0w + tq * 2;
        *(float2*)&outw[(size_t)(i0 + r0) * NLAT + col] =
            make_float2(acc[mi][0] * iz0, acc[mi][1] * iz0);
        *(float2*)&outw[(size_t)(i0 + r0 + 8) * NLAT + col] =
            make_float2(acc[mi][2] * iz1, acc[mi][3] * iz1);
    }
}

// ---------------- z = mu + eps*exp(0.5*lv); logits = z @ Wc + bc ------------
__global__ __launch_bounds__(128)
void final_kernel(const float* __restrict__ mu, const float* __restrict__ lv,
                  const float* __restrict__ eps, const float* __restrict__ Wc,
                  const float* __restrict__ bc, float* __restrict__ logits)
{
    __shared__ float zs[8 * 64];
    const int tid = threadIdx.x;
    const int r0 = blockIdx.x * 8;
    #pragma unroll
    for (int l = tid; l < 8 * 64; l += 128) {
        int r = l >> 6, k = l & 63;
        size_t idx = (size_t)(r0 + r) * 64 + k;
        zs[l] = mu[idx] + eps[idx] * __expf(0.5f * lv[idx]);
    }
    __syncthreads();
    int r = tid >> 4, n = tid & 15;
    float acc = bc[n];
    #pragma unroll
    for (int k = 0; k < 64; ++k) acc += zs[r * 64 + k] * Wc[k * 16 + n];
    logits[(size_t)(r0 + r) * 16 + n] = acc;
}

// ------------------------------ launch --------------------------------------
extern "C" void kernel_launch(void* const* d_in, const int* in_sizes, int n_in,
                              void* d_out, int out_size)
{
    const float* x   = (const float*)d_in[0];
    const int*   adj = (const int*)  d_in[1];
    const float* eps = (const float*)d_in[2];
    const float* W1  = (const float*)d_in[3];
    const float* a1  = (const float*)d_in[4];
    const float* Wmu = (const float*)d_in[5];
    const float* amu = (const float*)d_in[6];
    const float* Wlv = (const float*)d_in[7];
    const float* alv = (const float*)d_in[8];
    const float* Wc  = (const float*)d_in[9];
    const float* bc  = (const float*)d_in[10];

    float* out    = (float*)d_out;
    float* logits = out;
    float* mu     = out + (size_t)N_NODES * NCLASS;
    float* lv     = mu  + (size_t)N_NODES * NLAT;

    float *Wh1, *h, *Whmu, *Whlv, *s1, *d1, *smu, *dmu, *slv, *dlv;
    float *E1, *F1, *Emu, *Fmu, *Elv, *Flv, *dmaxf;
    unsigned *dmaxu;
    __half *T1, *Tm, *Tv;
    unsigned* adjb;
    cudaGetSymbolAddress((void**)&Wh1,  g_Wh1);
    cudaGetSymbolAddress((void**)&h,    g_h);
    cudaGetSymbolAddress((void**)&Whmu, g_Whmu);
    cudaGetSymbolAddress((void**)&Whlv, g_Whlv);
    cudaGetSymbolAddress((void**)&s1,   g_s1);
    cudaGetSymbolAddress((void**)&d1,   g_d1);
    cudaGetSymbolAddress((void**)&smu,  g_smu);
    cudaGetSymbolAddress((void**)&dmu,  g_dmu);
    cudaGetSymbolAddress((void**)&slv,  g_slv);
    cudaGetSymbolAddress((void**)&dlv,  g_dlv);
    cudaGetSymbolAddress((void**)&dmaxu, g_dmaxu);
    cudaGetSymbolAddress((void**)&dmaxf, g_dmaxf);
    cudaGetSymbolAddress((void**)&E1,   g_E1);
    cudaGetSymbolAddress((void**)&F1,   g_F1);
    cudaGetSymbolAddress((void**)&Emu,  g_Emu);
    cudaGetSymbolAddress((void**)&Fmu,  g_Fmu);
    cudaGetSymbolAddress((void**)&Elv,  g_Elv);
    cudaGetSymbolAddress((void**)&Flv,  g_Flv);
    cudaGetSymbolAddress((void**)&T1,   g_T1);
    cudaGetSymbolAddress((void**)&Tm,   g_Tm);
    cudaGetSymbolAddress((void**)&Tv,   g_Tv);
    cudaGetSymbolAddress((void**)&adjb, g_adjb);

    cudaFuncSetAttribute(gemm_mma_kernel, cudaFuncAttributeMaxDynamicSharedMemorySize, GSMEM);
    cudaFuncSetAttribute(attn1_kernel,  cudaFuncAttributeMaxDynamicSharedMemorySize, SMEM1);
    cudaFuncSetAttribute(attn23_kernel, cudaFuncAttributeMaxDynamicSharedMemorySize, SMEM2);

    // 0: gemm1 (also inits dmax)
    gemm_mma_kernel<<<dim3(NHID / 64, N_NODES / 128), 256, GSMEM>>>(
        x, W1, Wh1, N_NODES, NHID, NFEAT, dmaxu, 1);
    // 1: sd + tconv
    sdtconv_kernel<NHID><<<1024 + (NHID / 32) * (N_NODES / 32), 256>>>(
        Wh1, a1, s1, d1, dmaxu + 0, T1);
    // 2: ef + pack_adj
    efpack_kernel<<<32 + (size_t)N_NODES * N_NODES / 256, 256>>>(
        d1, dmaxu + 0, E1, F1, dmaxf + 0, adj, adjb);
    // 3: attn1 (profile slot)
    attn1_kernel<<<N_NODES / 32, 512, SMEM1>>>(adjb, T1, s1, d1, E1, F1, dmaxf + 0, h);

    // layer 2/3
    gemm_mma_kernel<<<dim3(NLAT / 64, N_NODES / 128), 256, GSMEM>>>(
        h, Wmu, Whmu, N_NODES, NLAT, NHID, dmaxu, 0);
    gemm_mma_kernel<<<dim3(NLAT / 64, N_NODES / 128), 256, GSMEM>>>(
        h, Wlv, Whlv, N_NODES, NLAT, NHID, dmaxu, 0);
    sdtconv_kernel<NLAT><<<1024 + (NLAT / 32) * (N_NODES / 32), 256>>>(
        Whmu, amu, smu, dmu, dmaxu + 1, Tm);
    sdtconv_kernel<NLAT><<<1024 + (NLAT / 32) * (N_NODES / 32), 256>>>(
        Whlv, alv, slv, dlv, dmaxu + 2, Tv);
    ef_kernel<<<N_NODES / 256, 256>>>(dmu, dmaxu + 1, Emu, Fmu, dmaxf + 1);
    ef_kernel<<<N_NODES / 256, 256>>>(dlv, dmaxu + 2, Elv, Flv, dmaxf + 2);
    attn23_kernel<<<N_NODES / 32, 512, SMEM2>>>(adjb, Tm, Tv,
                                                smu, dmu, slv, dlv,
                                                Emu, Fmu, Elv, Flv, dmaxf + 1, mu, lv);

    // reparameterize + classifier
    final_kernel<<<N_NODES / 8, 128>>>(mu, lv, eps, Wc, bc, logits);
}

// round 15
// speedup vs baseline: 2.0683x; 1.1555x over previous
#include <cuda_runtime.h>
#include <cuda_bf16.h>
#include <cuda_fp16.h>
#include <math.h>
#include <stdint.h>

#define N_NODES 8192
#define NFEAT   512
#define NHID    256
#define NLAT    64
#define NCLASS  16
#define ALPHA   0.2f
#define NWORDS  (N_NODES / 32)

// ------------------------------ device scratch ------------------------------
__device__ __align__(16) float g_Wh1 [N_NODES * NHID];
__device__ __align__(16) float g_h   [N_NODES * NHID];
__device__ __align__(16) float g_Whmu[N_NODES * NLAT];
__device__ __align__(16) float g_Whlv[N_NODES * NLAT];
__device__ __align__(16) __half g_T1[NHID * N_NODES];
__device__ __align__(16) __half g_Tm[NLAT * N_NODES];
__device__ __align__(16) __half g_Tv[NLAT * N_NODES];
__device__ __align__(16) uint4 g_Bf1[262144];     // 4MB: [jblk128][ng16][kt4][lane32]
__device__ __align__(16) uint2 g_Bf23[262144];    // 2MB: [mat2][jblk128][ng8][kt4][lane32]
__device__ unsigned g_adjb[(size_t)N_NODES * NWORDS];
__device__ float g_s1[N_NODES], g_d1[N_NODES];
__device__ float g_smu[N_NODES], g_dmu[N_NODES];
__device__ float g_slv[N_NODES], g_dlv[N_NODES];
__device__ __align__(16) float g_E1[N_NODES],  g_F1[N_NODES];
__device__ __align__(16) float g_Emu[N_NODES], g_Fmu[N_NODES];
__device__ __align__(16) float g_Elv[N_NODES], g_Flv[N_NODES];
__device__ unsigned g_dmaxu[4];
__device__ float    g_dmaxf[4];

// ------------------------------ helpers -------------------------------------
__device__ __forceinline__ uint32_t smem_u32(const void* p) {
    uint32_t a;
    asm("{ .reg .u64 t; cvta.to.shared.u64 t, %1; cvt.u32.u64 %0, t; }"
        : "=r"(a) : "l"(p));
    return a;
}
__device__ __forceinline__ unsigned fenc(float x) {
    int ix = __float_as_int(x);
    return ix >= 0 ? ((unsigned)ix | 0x80000000u) : ~(unsigned)ix;
}
__device__ __forceinline__ float fdec(unsigned u) {
    int ix = (u & 0x80000000u) ? (int)(u & 0x7FFFFFFFu) : ~(int)u;
    return __int_as_float(ix);
}

// mma.sync m16n8k16 row.col f16 -> f32 (HMMA on sm_103)
__device__ __forceinline__ void mma16816(float* c,
    uint32_t a0, uint32_t a1, uint32_t a2, uint32_t a3,
    uint32_t b0, uint32_t b1)
{
    asm volatile(
        "mma.sync.aligned.m16n8k16.row.col.f32.f16.f16.f32 "
        "{%0,%1,%2,%3}, {%4,%5,%6,%7}, {%8,%9}, {%0,%1,%2,%3};"
        : "+f"(c[0]), "+f"(c[1]), "+f"(c[2]), "+f"(c[3])
        : "r"(a0), "r"(a1), "r"(a2), "r"(a3), "r"(b0), "r"(b1));
}
__device__ __forceinline__ void ldsm_x4(uint32_t& r0, uint32_t& r1,
                                        uint32_t& r2, uint32_t& r3, uint32_t addr)
{
    asm volatile("ldmatrix.sync.aligned.m8n8.x4.shared.b16 {%0,%1,%2,%3}, [%4];"
                 : "=r"(r0), "=r"(r1), "=r"(r2), "=r"(r3) : "r"(addr));
}

// =============================================================================
// gemm_mma (unchanged from R13/R14 passing version)
// =============================================================================
static constexpr int GP    = 144;
static constexpr int G_AH  = 0;
static constexpr int G_AL  = 18432;
static constexpr int G_B   = 36864;
static constexpr int GSMEM = 46080;

__global__ __launch_bounds__(256, 1)
void gemm_mma_kernel(const float* __restrict__ A, const float* __restrict__ B,
                     float* __restrict__ C, int M, int N, int K,
                     unsigned* __restrict__ dmaxu, int init_flag)
{
    extern __shared__ __align__(16) char smem[];
    const uint32_t sb = smem_u32(smem);
    const int tid = threadIdx.x, warp = tid >> 5, lane = tid & 31;
    const int g = lane >> 2, tq = lane & 3;
    const int wm = warp >> 1, wn = warp & 1;
    const int m0 = blockIdx.y * 128, n0 = blockIdx.x * 64;

    if (init_flag && blockIdx.x == 0 && blockIdx.y == 0 && tid < 4)
        dmaxu[tid] = 0u;

    const uint32_t a_lane = ((lane & 7) + ((lane >> 3) & 1) * 8) * GP + ((lane >> 4) & 1) * 16;
    const uint32_t b_lane = ((lane & 7) + ((lane >> 4) & 1) * 8) * GP + ((lane >> 3) & 1) * 16;

    float acc[2][4][4];
    #pragma unroll
    for (int a = 0; a < 2; ++a)
        #pragma unroll
        for (int b = 0; b < 4; ++b)
            #pragma unroll
            for (int c = 0; c < 4; ++c) acc[a][b][c] = 0.f;

    for (int k0 = 0; k0 < K; k0 += 64) {
        __syncthreads();
        #pragma unroll
        for (int i = 0; i < 8; ++i) {
            int c = tid + i * 256;
            int row = c >> 4, kq = (c & 15) * 4;
            float4 v = *(const float4*)&A[(size_t)(m0 + row) * K + k0 + kq];
            __half h0 = __float2half_rn(v.x), h1 = __float2half_rn(v.y);
            __half h2 = __float2half_rn(v.z), h3 = __float2half_rn(v.w);
            __half l0 = __float2half_rn(v.x - __half2float(h0));
            __half l1 = __float2half_rn(v.y - __half2float(h1));
            __half l2 = __float2half_rn(v.z - __half2float(h2));
            __half l3 = __float2half_rn(v.w - __half2float(h3));
            __half2 hh01 = __halves2half2(h0, h1), hh23 = __halves2half2(h2, h3);
            __half2 ll01 = __halves2half2(l0, l1), ll23 = __halves2half2(l2, l3);
            uint2 ph, pl;
            ph.x = *(uint32_t*)&hh01; ph.y = *(uint32_t*)&hh23;
            pl.x = *(uint32_t*)&ll01; pl.y = *(uint32_t*)&ll23;
            *(uint2*)(smem + G_AH + row * GP + kq * 2) = ph;
            *(uint2*)(smem + G_AL + row * GP + kq * 2) = pl;
        }
        #pragma unroll
        for (int i = 0; i < 4; ++i) {
            int c = tid + i * 256;
            int kk = c >> 4, nq = (c & 15) * 4;
            float4 v = *(const float4*)&B[(size_t)(k0 + kk) * N + n0 + nq];
            *(__half*)(smem + G_B + (nq + 0) * GP + kk * 2) = __float2half_rn(v.x);
            *(__half*)(smem + G_B + (nq + 1) * GP + kk * 2) = __float2half_rn(v.y);
            *(__half*)(smem + G_B + (nq + 2) * GP + kk * 2) = __float2half_rn(v.z);
            *(__half*)(smem + G_B + (nq + 3) * GP + kk * 2) = __float2half_rn(v.w);
        }
        __syncthreads();

        const uint32_t abase = sb + G_AH + (wm * 32) * GP + a_lane;
        const uint32_t bbase = sb + G_B + (wn * 32) * GP + b_lane;
        #pragma unroll
        for (int kt = 0; kt < 4; ++kt) {
            const int koff = kt * 32;
            uint32_t ah[2][4], al[2][4];
            #pragma unroll
            for (int mi = 0; mi < 2; ++mi) {
                ldsm_x4(ah[mi][0], ah[mi][1], ah[mi][2], ah[mi][3],
                        abase + mi * (16 * GP) + koff);
                ldsm_x4(al[mi][0], al[mi][1], al[mi][2], al[mi][3],
                        abase + (G_AL - G_AH) + mi * (16 * GP) + koff);
            }
            #pragma unroll
            for (int nh = 0; nh < 2; ++nh) {
                uint32_t b0, b1, b2, b3;
                ldsm_x4(b0, b1, b2, b3, bbase + nh * (16 * GP) + koff);
                #pragma unroll
                for (int mi = 0; mi < 2; ++mi) {
                    mma16816(acc[mi][nh * 2 + 0], ah[mi][0], ah[mi][1], ah[mi][2], ah[mi][3], b0, b1);
                    mma16816(acc[mi][nh * 2 + 0], al[mi][0], al[mi][1], al[mi][2], al[mi][3], b0, b1);
                    mma16816(acc[mi][nh * 2 + 1], ah[mi][0], ah[mi][1], ah[mi][2], ah[mi][3], b2, b3);
                    mma16816(acc[mi][nh * 2 + 1], al[mi][0], al[mi][1], al[mi][2], al[mi][3], b2, b3);
                }
            }
        }
    }

    #pragma unroll
    for (int mi = 0; mi < 2; ++mi) {
        int r0 = m0 + wm * 32 + mi * 16 + g;
        #pragma unroll
        for (int ni = 0; ni < 4; ++ni) {
            int col = n0 + wn * 32 + ni * 8 + tq * 2;
            *(float2*)&C[(size_t)r0 * N + col] =
                make_float2(acc[mi][ni][0], acc[mi][ni][1]);
            *(float2*)&C[(size_t)(r0 + 8) * N + col] =
                make_float2(acc[mi][ni][2], acc[mi][ni][3]);
        }
    }
}

// =============================================================================
// sd + tconv fused (unchanged)
// =============================================================================
template <int F>
__global__ __launch_bounds__(256)
void sdtconv_kernel(const float* __restrict__ Wh, const float* __restrict__ a,
                    float* __restrict__ s, float* __restrict__ d,
                    unsigned* __restrict__ dmaxu, __half* __restrict__ T)
{
    if (blockIdx.x < 1024) {
        int warp = (blockIdx.x * 256 + threadIdx.x) >> 5;
        int lane = threadIdx.x & 31;
        const float* row = Wh + (size_t)warp * F;
        float ss = 0.f, dd = 0.f;
        #pragma unroll
        for (int f = lane; f < F; f += 32) {
            float w = row[f];
            ss += w * a[f];
            dd += w * a[F + f];
        }
        #pragma unroll
        for (int o = 16; o; o >>= 1) {
            ss += __shfl_down_sync(0xffffffffu, ss, o);
            dd += __shfl_down_sync(0xffffffffu, dd, o);
        }
        if (lane == 0) {
            s[warp] = ss; d[warp] = dd;
            atomicMax(dmaxu, fenc(dd));
        }
    } else {
        __shared__ float tile[32][33];
        int b = blockIdx.x - 1024;
        int f0 = (b % (F / 32)) * 32;
        int m0 = (b / (F / 32)) * 32;
        int x = threadIdx.x & 31, y = threadIdx.x >> 5;
        #pragma unroll
        for (int yy = 0; yy < 4; ++yy)
            tile[y + yy * 8][x] = Wh[(size_t)(m0 + y + yy * 8) * F + f0 + x];
        __syncthreads();
        #pragma unroll
        for (int yy = 0; yy < 4; ++yy) {
            float v = tile[x][y + yy * 8];
            T[(size_t)(f0 + y + yy * 8) * N_NODES + m0 + x] = __float2half_rn(v);
        }
    }
}

// =============================================================================
// efpack: ef (32 blocks) + adjacency pack (262144) + attn1 B-fragment gen (1024)
// =============================================================================
__global__ __launch_bounds__(256)
void efpack_kernel(const float* __restrict__ d, const unsigned* __restrict__ dmaxu,
                   float* __restrict__ E, float* __restrict__ F,
                   float* __restrict__ dmaxf,
                   const int* __restrict__ adj, unsigned* __restrict__ bits,
                   const __half* __restrict__ T1, uint4* __restrict__ Bf1)
{
    if (blockIdx.x < 32) {
        float dm = fdec(*dmaxu);
        int i = blockIdx.x * 256 + threadIdx.x;
        float v = d[i] - dm;
        E[i] = __expf(v);
        F[i] = __expf(ALPHA * v);
        if (i == 0) *dmaxf = dm;
    } else if (blockIdx.x < 32 + 262144) {
        size_t idx = (size_t)(blockIdx.x - 32) * 256 + threadIdx.x;
        int v = adj[idx] > 0;
        unsigned b = __ballot_sync(0xffffffffu, v);
        if ((threadIdx.x & 31) == 0) bits[idx >> 5] = b;
    } else {
        int w = (blockIdx.x - 32 - 262144) * 8 + (threadIdx.x >> 5);
        int lane = threadIdx.x & 31;
        int jblk = w >> 6, ng = (w >> 2) & 15, kt = w & 3;
        int f0 = ng * 16 + (lane >> 2);
        int jb = jblk * 64 + kt * 16 + (lane & 3) * 2;
        const __half* p = T1 + (size_t)f0 * N_NODES + jb;
        uint32_t b0 = *(const uint32_t*)p;
        uint32_t b1 = *(const uint32_t*)(p + 8);
        uint32_t b2 = *(const uint32_t*)(p + (size_t)8 * N_NODES);
        uint32_t b3 = *(const uint32_t*)(p + (size_t)8 * N_NODES + 8);
        Bf1[(size_t)w * 32 + lane] = make_uint4(b0, b1, b2, b3);
    }
}

// ef (32 blocks) + attn23 B-fragment gen for one matrix (512 blocks)
__global__ __launch_bounds__(256)
void ef_kernel(const float* __restrict__ d, const unsigned* __restrict__ dmaxu,
               float* __restrict__ E, float* __restrict__ F,
               float* __restrict__ dmaxf,
               const __half* __restrict__ T, uint2* __restrict__ Bf, int mat)
{
    if (blockIdx.x < 32) {
        float dm = fdec(*dmaxu);
        int i = blockIdx.x * 256 + threadIdx.x;
        float v = d[i] - dm;
        E[i] = __expf(v);
        F[i] = __expf(ALPHA * v);
        if (i == 0) *dmaxf = dm;
    } else {
        int w = (blockIdx.x - 32) * 8 + (threadIdx.x >> 5);
        int lane = threadIdx.x & 31;
        int jblk = w >> 5, ng = (w >> 2) & 7, kt = w & 3;
        int f0 = ng * 8 + (lane >> 2);
        int jb = jblk * 64 + kt * 16 + (lane & 3) * 2;
        const __half* p = T + (size_t)f0 * N_NODES + jb;
        uint32_t b0 = *(const uint32_t*)p;
        uint32_t b1 = *(const uint32_t*)(p + 8);
        Bf[(size_t)mat * 131072 + (size_t)w * 32 + lane] = make_uint2(b0, b1);
    }
}

// =============================================================================
// attn1: CTA 32 rows x 256 F, grid 256, 512 thr, 16 warps (32r x 16c).
// B fragments loaded directly from GMEM (L2-resident); only P tile in smem.
// One barrier per j-tile. 2 CTAs/SM.
// =============================================================================
static constexpr int PA      = 144;
static constexpr int S1_A    = 0;          // 2 buf x 32x144
static constexpr int S1_ABUF = 4608;
static constexpr int S1_ZT   = 9216;       // 512 floats
static constexpr int S1_ZR   = 11264;      // 32 floats
static constexpr int SMEM1   = 11520;

__global__ __launch_bounds__(512, 2)
void attn1_kernel(const unsigned* __restrict__ adjb,
                  const uint4* __restrict__ Bf,
                  const float* __restrict__ svec, const float* __restrict__ dvec,
                  const float* __restrict__ EJ, const float* __restrict__ FJ,
                  const float* __restrict__ dmaxp, float* __restrict__ outp)
{
    extern __shared__ __align__(16) char smem[];
    const uint32_t sb = smem_u32(smem);
    const int tid = threadIdx.x, warp = tid >> 5, lane = tid & 31;
    const int g = lane >> 2, tq = lane & 3;
    const int i0 = blockIdx.x * 32;
    const int n0w = warp * 16;

    const uint32_t a_lane = ((lane & 7) + ((lane >> 3) & 1) * 8) * PA + ((lane >> 4) & 1) * 16;

    const int r = tid >> 4, q = tid & 15;
    const float sv = svec[i0 + r];
    const float mv = sv + *dmaxp;
    const float m_r = mv > 0.f ? mv : ALPHA * mv;
    const float RA = __expf(mv - m_r);
    const float RB = __expf(ALPHA * mv - m_r);
    float zacc = 0.f;

    float acc[2][2][4];
    #pragma unroll
    for (int a = 0; a < 2; ++a)
        #pragma unroll
        for (int b = 0; b < 2; ++b)
            #pragma unroll
            for (int c = 0; c < 4; ++c) acc[a][b][c] = 0.f;

    const size_t row_adj = (size_t)(i0 + r) * NWORDS;
    const uint4* bfp = Bf + (size_t)warp * 128 + lane;   // + t*2048 + kt*32

    uint4 bf[4];

    // ---- prologue: P-gen tile 0 + B fragments tile 0 ------------------------
    {
        unsigned w = adjb[row_adj + (q >> 3)];
        unsigned bits = (w >> ((q & 7) * 4)) & 0xF;
        const int jb = q * 4;
        float4 dd = *(const float4*)(dvec + jb);
        float4 ee = *(const float4*)(EJ + jb);
        float4 ff = *(const float4*)(FJ + jb);
        float p0 = (bits & 1) ? ((sv + dd.x > 0.f) ? RA * ee.x : RB * ff.x) : 0.f;
        float p1 = (bits & 2) ? ((sv + dd.y > 0.f) ? RA * ee.y : RB * ff.y) : 0.f;
        float p2 = (bits & 4) ? ((sv + dd.z > 0.f) ? RA * ee.z : RB * ff.z) : 0.f;
        float p3 = (bits & 8) ? ((sv + dd.w > 0.f) ? RA * ee.w : RB * ff.w) : 0.f;
        zacc += p0 + p1 + p2 + p3;
        __half2 h01 = __floats2half2_rn(p0, p1);
        __half2 h23 = __floats2half2_rn(p2, p3);
        uint2 pk;
        pk.x = *(uint32_t*)&h01; pk.y = *(uint32_t*)&h23;
        *(uint2*)(smem + S1_A + r * PA + jb * 2) = pk;
    }
    #pragma unroll
    for (int kt = 0; kt < 4; ++kt) bf[kt] = bfp[kt * 32];
    __syncthreads();

    for (int t = 0; t < N_NODES / 64; ++t) {
        const int buf = t & 1;

        // ---- MMA on A[buf] + bf regs ----------------------------------------
        const uint32_t abase = sb + S1_A + buf * S1_ABUF + a_lane;
        #pragma unroll
        for (int kt = 0; kt < 4; ++kt) {
            const int koff = kt * 32;
            uint32_t a0[4], a1[4];
            ldsm_x4(a0[0], a0[1], a0[2], a0[3], abase + koff);
            ldsm_x4(a1[0], a1[1], a1[2], a1[3], abase + 16 * PA + koff);
            mma16816(acc[0][0], a0[0], a0[1], a0[2], a0[3], bf[kt].x, bf[kt].y);
            mma16816(acc[0][1], a0[0], a0[1], a0[2], a0[3], bf[kt].z, bf[kt].w);
            mma16816(acc[1][0], a1[0], a1[1], a1[2], a1[3], bf[kt].x, bf[kt].y);
            mma16816(acc[1][1], a1[0], a1[1], a1[2], a1[3], bf[kt].z, bf[kt].w);
        }

        if (t + 1 < N_NODES / 64) {
            // B fragments for next tile (latency hidden by P-gen + barrier)
            const uint4* nb = bfp + (size_t)(t + 1) * 2048;
            #pragma unroll
            for (int kt = 0; kt < 4; ++kt) bf[kt] = nb[kt * 32];

            // P-gen for next tile into A[buf^1]
            const int j0 = (t + 1) * 64;
            unsigned w = adjb[row_adj + (j0 >> 5) + (q >> 3)];
            unsigned bits = (w >> ((q & 7) * 4)) & 0xF;
            const int jb = q * 4;
            float4 dd = *(const float4*)(dvec + j0 + jb);
            float4 ee = *(const float4*)(EJ + j0 + jb);
            float4 ff = *(const float4*)(FJ + j0 + jb);
            float p0 = (bits & 1) ? ((sv + dd.x > 0.f) ? RA * ee.x : RB * ff.x) : 0.f;
            float p1 = (bits & 2) ? ((sv + dd.y > 0.f) ? RA * ee.y : RB * ff.y) : 0.f;
            float p2 = (bits & 4) ? ((sv + dd.z > 0.f) ? RA * ee.z : RB * ff.z) : 0.f;
            float p3 = (bits & 8) ? ((sv + dd.w > 0.f) ? RA * ee.w : RB * ff.w) : 0.f;
            zacc += p0 + p1 + p2 + p3;
            __half2 h01 = __floats2half2_rn(p0, p1);
            __half2 h23 = __floats2half2_rn(p2, p3);
            uint2 pk;
            pk.x = *(uint32_t*)&h01; pk.y = *(uint32_t*)&h23;
            *(uint2*)(smem + S1_A + (buf ^ 1) * S1_ABUF + r * PA + jb * 2) = pk;
        }
        __syncthreads();
    }

    // ---- epilogue ------------------------------------------------------------
    float* zt = (float*)(smem + S1_ZT);
    float* zr = (float*)(smem + S1_ZR);
    zt[tid] = zacc;
    __syncthreads();
    if (tid < 32) {
        float z = 0.f;
        #pragma unroll
        for (int k = 0; k < 16; ++k) z += zt[16 * tid + k];
        zr[tid] = z;
    }
    __syncthreads();
    #pragma unroll
    for (int mi = 0; mi < 2; ++mi) {
        int r0 = mi * 16 + g;
        float iz0 = 1.f / zr[r0];
        float iz1 = 1.f / zr[r0 + 8];
        #pragma unroll
        for (int ni = 0; ni < 2; ++ni) {
            int col = n0w + ni * 8 + tq * 2;
            float v0 = acc[mi][ni][0] * iz0; v0 = v0 > 0.f ? v0 : expm1f(v0);
            float v1 = acc[mi][ni][1] * iz0; v1 = v1 > 0.f ? v1 : expm1f(v1);
            float v2 = acc[mi][ni][2] * iz1; v2 = v2 > 0.f ? v2 : expm1f(v2);
            float v3 = acc[mi][ni][3] * iz1; v3 = v3 > 0.f ? v3 : expm1f(v3);
            *(float2*)&outp[(size_t)(i0 + r0) * NHID + col]     = make_float2(v0, v1);
            *(float2*)&outp[(size_t)(i0 + r0 + 8) * NHID + col] = make_float2(v2, v3);
        }
    }
}

// =============================================================================
// attn23: CTA 32 rows, both mats, grid 256, 512 thr. B fragments from GMEM.
// warps 0-7: mu cols [8w..8w+8); warps 8-15: lv.
// =============================================================================
static constexpr int S2_A    = 0;          // 2 buf x [mu 32x144 | lv 32x144]
static constexpr int S2_ABUF = 9216;
static constexpr int S2_AMAT = 4608;
static constexpr int S2_ZT   = 18432;      // 2 x 512 floats
static constexpr int S2_ZR   = 22528;      // 2 x 32 floats
static constexpr int SMEM2   = 22784;

__global__ __launch_bounds__(512, 2)
void attn23_kernel(const unsigned* __restrict__ adjb,
                   const uint2* __restrict__ Bf,
                   const float* __restrict__ smuv, const float* __restrict__ dmuv,
                   const float* __restrict__ slvv, const float* __restrict__ dlvv,
                   const float* __restrict__ Em, const float* __restrict__ Fm,
                   const float* __restrict__ Ev, const float* __restrict__ Fv,
                   const float* __restrict__ dmaxp,
                   float* __restrict__ out_mu, float* __restrict__ out_lv)
{
    extern __shared__ __align__(16) char smem[];
    const uint32_t sb = smem_u32(smem);
    const int tid = threadIdx.x, warp = tid >> 5, lane = tid & 31;
    const int g = lane >> 2, tq = lane & 3;
    const int i0 = blockIdx.x * 32;
    const int which = warp >> 3;
    const int n0w = (warp & 7) * 8;

    const uint32_t a_lane = ((lane & 7) + ((lane >> 3) & 1) * 8) * PA + ((lane >> 4) & 1) * 16;

    const int r = tid >> 4, q = tid & 15;
    const float svm = smuv[i0 + r], svv = slvv[i0 + r];
    const float mvm = svm + dmaxp[0], mvv = svv + dmaxp[1];
    const float mm = mvm > 0.f ? mvm : ALPHA * mvm;
    const float ml = mvv > 0.f ? mvv : ALPHA * mvv;
    const float RAm = __expf(mvm - mm), RBm = __expf(ALPHA * mvm - mm);
    const float RAv = __expf(mvv - ml), RBv = __expf(ALPHA * mvv - ml);
    float zm = 0.f, zv = 0.f;

    float acc[2][4];
    #pragma unroll
    for (int a = 0; a < 2; ++a)
        #pragma unroll
        for (int c = 0; c < 4; ++c) acc[a][c] = 0.f;

    const size_t row_adj = (size_t)(i0 + r) * NWORDS;
    const uint2* bfp = Bf + (size_t)which * 131072 + (size_t)(warp & 7) * 128 + lane;

    uint2 bf[4];

    // ---- prologue: P-gen tile 0 (both mats) + B fragments tile 0 ------------
    {
        unsigned w = adjb[row_adj + (q >> 3)];
        unsigned bits = (w >> ((q & 7) * 4)) & 0xF;
        const int jb = q * 4;

        float4 dd = *(const float4*)(dmuv + jb);
        float4 ee = *(const float4*)(Em + jb);
        float4 ff = *(const float4*)(Fm + jb);
        float p0 = (bits & 1) ? ((svm + dd.x > 0.f) ? RAm * ee.x : RBm * ff.x) : 0.f;
        float p1 = (bits & 2) ? ((svm + dd.y > 0.f) ? RAm * ee.y : RBm * ff.y) : 0.f;
        float p2 = (bits & 4) ? ((svm + dd.z > 0.f) ? RAm * ee.z : RBm * ff.z) : 0.f;
        float p3 = (bits & 8) ? ((svm + dd.w > 0.f) ? RAm * ee.w : RBm * ff.w) : 0.f;
        zm += p0 + p1 + p2 + p3;
        __half2 h01 = __floats2half2_rn(p0, p1);
        __half2 h23 = __floats2half2_rn(p2, p3);
        uint2 pk;
        pk.x = *(uint32_t*)&h01; pk.y = *(uint32_t*)&h23;
        *(uint2*)(smem + S2_A + r * PA + jb * 2) = pk;

        dd = *(const float4*)(dlvv + jb);
        ee = *(const float4*)(Ev + jb);
        ff = *(const float4*)(Fv + jb);
        p0 = (bits & 1) ? ((svv + dd.x > 0.f) ? RAv * ee.x : RBv * ff.x) : 0.f;
        p1 = (bits & 2) ? ((svv + dd.y > 0.f) ? RAv * ee.y : RBv * ff.y) : 0.f;
        p2 = (bits & 4) ? ((svv + dd.z > 0.f) ? RAv * ee.z : RBv * ff.z) : 0.f;
        p3 = (bits & 8) ? ((svv + dd.w > 0.f) ? RAv * ee.w : RBv * ff.w) : 0.f;
        zv += p0 + p1 + p2 + p3;
        h01 = __floats2half2_rn(p0, p1);
        h23 = __floats2half2_rn(p2, p3);
        pk.x = *(uint32_t*)&h01; pk.y = *(uint32_t*)&h23;
        *(uint2*)(smem + S2_A + S2_AMAT + r * PA + jb * 2) = pk;
    }
    #pragma unroll
    for (int kt = 0; kt < 4; ++kt) bf[kt] = bfp[kt * 32];
    __syncthreads();

    for (int t = 0; t < N_NODES / 64; ++t) {
        const int buf = t & 1;

        const uint32_t abase = sb + S2_A + buf * S2_ABUF + which * S2_AMAT + a_lane;
        #pragma unroll
        for (int kt = 0; kt < 4; ++kt) {
            const int koff = kt * 32;
            uint32_t a0[4], a1[4];
            ldsm_x4(a0[0], a0[1], a0[2], a0[3], abase + koff);
            ldsm_x4(a1[0], a1[1], a1[2], a1[3], abase + 16 * PA + koff);
            mma16816(acc[0], a0[0], a0[1], a0[2], a0[3], bf[kt].x, bf[kt].y);
            mma16816(acc[1], a1[0], a1[1], a1[2], a1[3], bf[kt].x, bf[kt].y);
        }

        if (t + 1 < N_NODES / 64) {
            const uint2* nb = bfp + (size_t)(t + 1) * 1024;
            #pragma unroll
            for (int kt = 0; kt < 4; ++kt) bf[kt] = nb[kt * 32];

            const int j0 = (t + 1) * 64;
            unsigned w = adjb[row_adj + (j0 >> 5) + (q >> 3)];
            unsigned bits = (w >> ((q & 7) * 4)) & 0xF;
            const int jb = q * 4;

            float4 dd = *(const float4*)(dmuv + j0 + jb);
            float4 ee = *(const float4*)(Em + j0 + jb);
            float4 ff = *(const float4*)(Fm + j0 + jb);
            float p0 = (bits & 1) ? ((svm + dd.x > 0.f) ? RAm * ee.x : RBm * ff.x) : 0.f;
            float p1 = (bits & 2) ? ((svm + dd.y > 0.f) ? RAm * ee.y : RBm * ff.y) : 0.f;
            float p2 = (bits & 4) ? ((svm + dd.z > 0.f) ? RAm * ee.z : RBm * ff.z) : 0.f;
            float p3 = (bits & 8) ? ((svm + dd.w > 0.f) ? RAm * ee.w : RBm * ff.w) : 0.f;
            zm += p0 + p1 + p2 + p3;
            __half2 h01 = __floats2half2_rn(p0, p1);
            __half2 h23 = __floats2half2_rn(p2, p3);
            uint2 pk;
            pk.x = *(uint32_t*)&h01; pk.y = *(uint32_t*)&h23;
            *(uint2*)(smem + S2_A + (buf ^ 1) * S2_ABUF + r * PA + jb * 2) = pk;

            dd = *(const float4*)(dlvv + j0 + jb);
            ee = *(const float4*)(Ev + j0 + jb);
            ff = *(const float4*)(Fv + j0 + jb);
            p0 = (bits & 1) ? ((svv + dd.x > 0.f) ? RAv * ee.x : RBv * ff.x) : 0.f;
            p1 = (bits & 2) ? ((svv + dd.y > 0.f) ? RAv * ee.y : RBv * ff.y) : 0.f;
            p2 = (bits & 4) ? ((svv + dd.z > 0.f) ? RAv * ee.z : RBv * ff.z) : 0.f;
            p3 = (bits & 8) ? ((svv + dd.w > 0.f) ? RAv * ee.w : RBv * ff.w) : 0.f;
            zv += p0 + p1 + p2 + p3;
            h01 = __floats2half2_rn(p0, p1);
            h23 = __floats2half2_rn(p2, p3);
            pk.x = *(uint32_t*)&h01; pk.y = *(uint32_t*)&h23;
            *(uint2*)(smem + S2_A + (buf ^ 1) * S2_ABUF + S2_AMAT + r * PA + jb * 2) = pk;
        }
        __syncthreads();
    }

    // epilogue
    float* ztm = (float*)(smem + S2_ZT);
    float* ztv = ztm + 512;
    float* zrm = (float*)(smem + S2_ZR);
    float* zrv = zrm + 32;
    ztm[tid] = zm; ztv[tid] = zv;
    __syncthreads();
    if (tid < 32) {
        float a = 0.f, b = 0.f;
        #pragma unroll
        for (int k = 0; k < 16; ++k) { a += ztm[16 * tid + k]; b += ztv[16 * tid + k]; }
        zrm[tid] = a; zrv[tid] = b;
    }
    __syncthreads();
    const float* zrow = which ? zrv : zrm;
    float* outw = which ? out_lv : out_mu;
    #pragma unroll
    for (int mi = 0; mi < 2; ++mi) {
        int r0 = mi * 16 + g;
        float iz0 = 1.f / zrow[r0];
        float iz1 = 1.f / zrow[r0 + 8];
        int col = n0w + tq * 2;
        *(float2*)&outw[(size_t)(i0 + r0) * NLAT + col] =
            make_float2(acc[mi][0] * iz0, acc[mi][1] * iz0);
        *(float2*)&outw[(size_t)(i0 + r0 + 8) * NLAT + col] =
            make_float2(acc[mi][2] * iz1, acc[mi][3] * iz1);
    }
}

// ---------------- z = mu + eps*exp(0.5*lv); logits = z @ Wc + bc ------------
__global__ __launch_bounds__(128)
void final_kernel(const float* __restrict__ mu, const float* __restrict__ lv,
                  const float* __restrict__ eps, const float* __restrict__ Wc,
                  const float* __restrict__ bc, float* __restrict__ logits)
{
    __shared__ float zs[8 * 64];
    const int tid = threadIdx.x;
    const int r0 = blockIdx.x * 8;
    #pragma unroll
    for (int l = tid; l < 8 * 64; l += 128) {
        int r = l >> 6, k = l & 63;
        size_t idx = (size_t)(r0 + r) * 64 + k;
        zs[l] = mu[idx] + eps[idx] * __expf(0.5f * lv[idx]);
    }
    __syncthreads();
    int r = tid >> 4, n = tid & 15;
    float acc = bc[n];
    #pragma unroll
    for (int k = 0; k < 64; ++k) acc += zs[r * 64 + k] * Wc[k * 16 + n];
    logits[(size_t)(r0 + r) * 16 + n] = acc;
}

// ------------------------------ launch --------------------------------------
extern "C" void kernel_launch(void* const* d_in, const int* in_sizes, int n_in,
                              void* d_out, int out_size)
{
    const float* x   = (const float*)d_in[0];
    const int*   adj = (const int*)  d_in[1];
    const float* eps = (const float*)d_in[2];
    const float* W1  = (const float*)d_in[3];
    const float* a1  = (const float*)d_in[4];
    const float* Wmu = (const float*)d_in[5];
    const float* amu = (const float*)d_in[6];
    const float* Wlv = (const float*)d_in[7];
    const float* alv = (const float*)d_in[8];
    const float* Wc  = (const float*)d_in[9];
    const float* bc  = (const float*)d_in[10];

    float* out    = (float*)d_out;
    float* logits = out;
    float* mu     = out + (size_t)N_NODES * NCLASS;
    float* lv     = mu  + (size_t)N_NODES * NLAT;

    float *Wh1, *h, *Whmu, *Whlv, *s1, *d1, *smu, *dmu, *slv, *dlv;
    float *E1, *F1, *Emu, *Fmu, *Elv, *Flv, *dmaxf;
    unsigned *dmaxu;
    __half *T1, *Tm, *Tv;
    uint4 *Bf1;
    uint2 *Bf23;
    unsigned* adjb;
    cudaGetSymbolAddress((void**)&Wh1,  g_Wh1);
    cudaGetSymbolAddress((void**)&h,    g_h);
    cudaGetSymbolAddress((void**)&Whmu, g_Whmu);
    cudaGetSymbolAddress((void**)&Whlv, g_Whlv);
    cudaGetSymbolAddress((void**)&s1,   g_s1);
    cudaGetSymbolAddress((void**)&d1,   g_d1);
    cudaGetSymbolAddress((void**)&smu,  g_smu);
    cudaGetSymbolAddress((void**)&dmu,  g_dmu);
    cudaGetSymbolAddress((void**)&slv,  g_slv);
    cudaGetSymbolAddress((void**)&dlv,  g_dlv);
    cudaGetSymbolAddress((void**)&dmaxu, g_dmaxu);
    cudaGetSymbolAddress((void**)&dmaxf, g_dmaxf);
    cudaGetSymbolAddress((void**)&E1,   g_E1);
    cudaGetSymbolAddress((void**)&F1,   g_F1);
    cudaGetSymbolAddress((void**)&Emu,  g_Emu);
    cudaGetSymbolAddress((void**)&Fmu,  g_Fmu);
    cudaGetSymbolAddress((void**)&Elv,  g_Elv);
    cudaGetSymbolAddress((void**)&Flv,  g_Flv);
    cudaGetSymbolAddress((void**)&T1,   g_T1);
    cudaGetSymbolAddress((void**)&Tm,   g_Tm);
    cudaGetSymbolAddress((void**)&Tv,   g_Tv);
    cudaGetSymbolAddress((void**)&Bf1,  g_Bf1);
    cudaGetSymbolAddress((void**)&Bf23, g_Bf23);
    cudaGetSymbolAddress((void**)&adjb, g_adjb);

    cudaFuncSetAttribute(gemm_mma_kernel, cudaFuncAttributeMaxDynamicSharedMemorySize, GSMEM);
    cudaFuncSetAttribute(attn1_kernel,  cudaFuncAttributeMaxDynamicSharedMemorySize, SMEM1);
    cudaFuncSetAttribute(attn23_kernel, cudaFuncAttributeMaxDynamicSharedMemorySize, SMEM2);

    // 0: gemm1 (inits dmax)
    gemm_mma_kernel<<<dim3(NHID / 64, N_NODES / 128), 256, GSMEM>>>(
        x, W1, Wh1, N_NODES, NHID, NFEAT, dmaxu, 1);
    // 1: sd + tconv
    sdtconv_kernel<NHID><<<1024 + (NHID / 32) * (N_NODES / 32), 256>>>(
        Wh1, a1, s1, d1, dmaxu + 0, T1);
    // 2: ef + pack_adj + attn1 B-fragment gen
    efpack_kernel<<<32 + 262144 + 1024, 256>>>(
        d1, dmaxu + 0, E1, F1, dmaxf + 0, adj, adjb, T1, Bf1);
    // 3: attn1 (profile slot)
    attn1_kernel<<<N_NODES / 32, 512, SMEM1>>>(adjb, Bf1, s1, d1, E1, F1, dmaxf + 0, h);

    // layer 2/3
    gemm_mma_kernel<<<dim3(NLAT / 64, N_NODES / 128), 256, GSMEM>>>(
        h, Wmu, Whmu, N_NODES, NLAT, NHID, dmaxu, 0);
    gemm_mma_kernel<<<dim3(NLAT / 64, N_NODES / 128), 256, GSMEM>>>(
        h, Wlv, Whlv, N_NODES, NLAT, NHID, dmaxu, 0);
    sdtconv_kernel<NLAT><<<1024 + (NLAT / 32) * (N_NODES / 32), 256>>>(
        Whmu, amu, smu, dmu, dmaxu + 1, Tm);
    sdtconv_kernel<NLAT><<<1024 + (NLAT / 32) * (N_NODES / 32), 256>>>(
        Whlv, alv, slv, dlv, dmaxu + 2, Tv);
    ef_kernel<<<32 + 512, 256>>>(dmu, dmaxu + 1, Emu, Fmu, dmaxf + 1, Tm, Bf23, 0);
    ef_kernel<<<32 + 512, 256>>>(dlv, dmaxu + 2, Elv, Flv, dmaxf + 2, Tv, Bf23, 1);
    attn23_kernel<<<N_NODES / 32, 512, SMEM2>>>(adjb, Bf23,
                                                smu, dmu, slv, dlv,
                                                Emu, Fmu, Elv, Flv, dmaxf + 1, mu, lv);

    // reparameterize + classifier
    final_kernel<<<N_NODES / 8, 128>>>(mu, lv, eps, Wc, bc, logits);
}

// round 16
// speedup vs baseline: 2.1081x; 1.0192x over previous
#include <cuda_runtime.h>
#include <cuda_bf16.h>
#include <cuda_fp16.h>
#include <math.h>
#include <stdint.h>

#define N_NODES 8192
#define NFEAT   512
#define NHID    256
#define NLAT    64
#define NCLASS  16
#define ALPHA   0.2f
#define NWORDS  (N_NODES / 32)

// ------------------------------ device scratch ------------------------------
__device__ __align__(16) float g_Wh1 [N_NODES * NHID];
__device__ __align__(16) float g_h   [N_NODES * NHID];
__device__ __align__(16) float g_Whmu[N_NODES * NLAT];
__device__ __align__(16) float g_Whlv[N_NODES * NLAT];
__device__ __align__(16) __half g_T1[NHID * N_NODES];
__device__ __align__(16) __half g_Tm[NLAT * N_NODES];
__device__ __align__(16) __half g_Tv[NLAT * N_NODES];
__device__ __align__(16) uint4 g_Bf1[262144];     // [jblk128][ng16][kt4][lane32]
__device__ __align__(16) uint2 g_Bf23[262144];    // [mat2][jblk128][ng8][kt4][lane32]
__device__ unsigned g_adjb[(size_t)N_NODES * NWORDS];
__device__ float g_s1[N_NODES], g_d1[N_NODES];
__device__ float g_smu[N_NODES], g_dmu[N_NODES];
__device__ float g_slv[N_NODES], g_dlv[N_NODES];
__device__ __align__(16) float g_E1[N_NODES],  g_F1[N_NODES];
__device__ __align__(16) float g_Emu[N_NODES], g_Fmu[N_NODES];
__device__ __align__(16) float g_Elv[N_NODES], g_Flv[N_NODES];
__device__ unsigned g_dmaxu[4];
__device__ float    g_dmaxf[4];

// ------------------------------ helpers -------------------------------------
__device__ __forceinline__ uint32_t smem_u32(const void* p) {
    uint32_t a;
    asm("{ .reg .u64 t; cvta.to.shared.u64 t, %1; cvt.u32.u64 %0, t; }"
        : "=r"(a) : "l"(p));
    return a;
}
__device__ __forceinline__ unsigned fenc(float x) {
    int ix = __float_as_int(x);
    return ix >= 0 ? ((unsigned)ix | 0x80000000u) : ~(unsigned)ix;
}
__device__ __forceinline__ float fdec(unsigned u) {
    int ix = (u & 0x80000000u) ? (int)(u & 0x7FFFFFFFu) : ~(int)u;
    return __int_as_float(ix);
}

__device__ __forceinline__ void mma16816(float* c,
    uint32_t a0, uint32_t a1, uint32_t a2, uint32_t a3,
    uint32_t b0, uint32_t b1)
{
    asm volatile(
        "mma.sync.aligned.m16n8k16.row.col.f32.f16.f16.f32 "
        "{%0,%1,%2,%3}, {%4,%5,%6,%7}, {%8,%9}, {%0,%1,%2,%3};"
        : "+f"(c[0]), "+f"(c[1]), "+f"(c[2]), "+f"(c[3])
        : "r"(a0), "r"(a1), "r"(a2), "r"(a3), "r"(b0), "r"(b1));
}
__device__ __forceinline__ void ldsm_x4(uint32_t& r0, uint32_t& r1,
                                        uint32_t& r2, uint32_t& r3, uint32_t addr)
{
    asm volatile("ldmatrix.sync.aligned.m8n8.x4.shared.b16 {%0,%1,%2,%3}, [%4];"
                 : "=r"(r0), "=r"(r1), "=r"(r2), "=r"(r3) : "r"(addr));
}

// =============================================================================
// gemm_mma (unchanged)
// =============================================================================
static constexpr int GP    = 144;
static constexpr int G_AH  = 0;
static constexpr int G_AL  = 18432;
static constexpr int G_B   = 36864;
static constexpr int GSMEM = 46080;

__global__ __launch_bounds__(256, 1)
void gemm_mma_kernel(const float* __restrict__ A, const float* __restrict__ B,
                     float* __restrict__ C, int M, int N, int K,
                     unsigned* __restrict__ dmaxu, int init_flag)
{
    extern __shared__ __align__(16) char smem[];
    const uint32_t sb = smem_u32(smem);
    const int tid = threadIdx.x, warp = tid >> 5, lane = tid & 31;
    const int g = lane >> 2, tq = lane & 3;
    const int wm = warp >> 1, wn = warp & 1;
    const int m0 = blockIdx.y * 128, n0 = blockIdx.x * 64;

    if (init_flag && blockIdx.x == 0 && blockIdx.y == 0 && tid < 4)
        dmaxu[tid] = 0u;

    const uint32_t a_lane = ((lane & 7) + ((lane >> 3) & 1) * 8) * GP + ((lane >> 4) & 1) * 16;
    const uint32_t b_lane = ((lane & 7) + ((lane >> 4) & 1) * 8) * GP + ((lane >> 3) & 1) * 16;

    float acc[2][4][4];
    #pragma unroll
    for (int a = 0; a < 2; ++a)
        #pragma unroll
        for (int b = 0; b < 4; ++b)
            #pragma unroll
            for (int c = 0; c < 4; ++c) acc[a][b][c] = 0.f;

    for (int k0 = 0; k0 < K; k0 += 64) {
        __syncthreads();
        #pragma unroll
        for (int i = 0; i < 8; ++i) {
            int c = tid + i * 256;
            int row = c >> 4, kq = (c & 15) * 4;
            float4 v = *(const float4*)&A[(size_t)(m0 + row) * K + k0 + kq];
            __half h0 = __float2half_rn(v.x), h1 = __float2half_rn(v.y);
            __half h2 = __float2half_rn(v.z), h3 = __float2half_rn(v.w);
            __half l0 = __float2half_rn(v.x - __half2float(h0));
            __half l1 = __float2half_rn(v.y - __half2float(h1));
            __half l2 = __float2half_rn(v.z - __half2float(h2));
            __half l3 = __float2half_rn(v.w - __half2float(h3));
            __half2 hh01 = __halves2half2(h0, h1), hh23 = __halves2half2(h2, h3);
            __half2 ll01 = __halves2half2(l0, l1), ll23 = __halves2half2(l2, l3);
            uint2 ph, pl;
            ph.x = *(uint32_t*)&hh01; ph.y = *(uint32_t*)&hh23;
            pl.x = *(uint32_t*)&ll01; pl.y = *(uint32_t*)&ll23;
            *(uint2*)(smem + G_AH + row * GP + kq * 2) = ph;
            *(uint2*)(smem + G_AL + row * GP + kq * 2) = pl;
        }
        #pragma unroll
        for (int i = 0; i < 4; ++i) {
            int c = tid + i * 256;
            int kk = c >> 4, nq = (c & 15) * 4;
            float4 v = *(const float4*)&B[(size_t)(k0 + kk) * N + n0 + nq];
            *(__half*)(smem + G_B + (nq + 0) * GP + kk * 2) = __float2half_rn(v.x);
            *(__half*)(smem + G_B + (nq + 1) * GP + kk * 2) = __float2half_rn(v.y);
            *(__half*)(smem + G_B + (nq + 2) * GP + kk * 2) = __float2half_rn(v.z);
            *(__half*)(smem + G_B + (nq + 3) * GP + kk * 2) = __float2half_rn(v.w);
        }
        __syncthreads();

        const uint32_t abase = sb + G_AH + (wm * 32) * GP + a_lane;
        const uint32_t bbase = sb + G_B + (wn * 32) * GP + b_lane;
        #pragma unroll
        for (int kt = 0; kt < 4; ++kt) {
            const int koff = kt * 32;
            uint32_t ah[2][4], al[2][4];
            #pragma unroll
            for (int mi = 0; mi < 2; ++mi) {
                ldsm_x4(ah[mi][0], ah[mi][1], ah[mi][2], ah[mi][3],
                        abase + mi * (16 * GP) + koff);
                ldsm_x4(al[mi][0], al[mi][1], al[mi][2], al[mi][3],
                        abase + (G_AL - G_AH) + mi * (16 * GP) + koff);
            }
            #pragma unroll
            for (int nh = 0; nh < 2; ++nh) {
                uint32_t b0, b1, b2, b3;
                ldsm_x4(b0, b1, b2, b3, bbase + nh * (16 * GP) + koff);
                #pragma unroll
                for (int mi = 0; mi < 2; ++mi) {
                    mma16816(acc[mi][nh * 2 + 0], ah[mi][0], ah[mi][1], ah[mi][2], ah[mi][3], b0, b1);
                    mma16816(acc[mi][nh * 2 + 0], al[mi][0], al[mi][1], al[mi][2], al[mi][3], b0, b1);
                    mma16816(acc[mi][nh * 2 + 1], ah[mi][0], ah[mi][1], ah[mi][2], ah[mi][3], b2, b3);
                    mma16816(acc[mi][nh * 2 + 1], al[mi][0], al[mi][1], al[mi][2], al[mi][3], b2, b3);
                }
            }
        }
    }

    #pragma unroll
    for (int mi = 0; mi < 2; ++mi) {
        int r0 = m0 + wm * 32 + mi * 16 + g;
        #pragma unroll
        for (int ni = 0; ni < 4; ++ni) {
            int col = n0 + wn * 32 + ni * 8 + tq * 2;
            *(float2*)&C[(size_t)r0 * N + col] =
                make_float2(acc[mi][ni][0], acc[mi][ni][1]);
            *(float2*)&C[(size_t)(r0 + 8) * N + col] =
                make_float2(acc[mi][ni][2], acc[mi][ni][3]);
        }
    }
}

// =============================================================================
// sd + tconv fused (unchanged)
// =============================================================================
template <int F>
__global__ __launch_bounds__(256)
void sdtconv_kernel(const float* __restrict__ Wh, const float* __restrict__ a,
                    float* __restrict__ s, float* __restrict__ d,
                    unsigned* __restrict__ dmaxu, __half* __restrict__ T)
{
    if (blockIdx.x < 1024) {
        int warp = (blockIdx.x * 256 + threadIdx.x) >> 5;
        int lane = threadIdx.x & 31;
        const float* row = Wh + (size_t)warp * F;
        float ss = 0.f, dd = 0.f;
        #pragma unroll
        for (int f = lane; f < F; f += 32) {
            float w = row[f];
            ss += w * a[f];
            dd += w * a[F + f];
        }
        #pragma unroll
        for (int o = 16; o; o >>= 1) {
            ss += __shfl_down_sync(0xffffffffu, ss, o);
            dd += __shfl_down_sync(0xffffffffu, dd, o);
        }
        if (lane == 0) {
            s[warp] = ss; d[warp] = dd;
            atomicMax(dmaxu, fenc(dd));
        }
    } else {
        __shared__ float tile[32][33];
        int b = blockIdx.x - 1024;
        int f0 = (b % (F / 32)) * 32;
        int m0 = (b / (F / 32)) * 32;
        int x = threadIdx.x & 31, y = threadIdx.x >> 5;
        #pragma unroll
        for (int yy = 0; yy < 4; ++yy)
            tile[y + yy * 8][x] = Wh[(size_t)(m0 + y + yy * 8) * F + f0 + x];
        __syncthreads();
        #pragma unroll
        for (int yy = 0; yy < 4; ++yy) {
            float v = tile[x][y + yy * 8];
            T[(size_t)(f0 + y + yy * 8) * N_NODES + m0 + x] = __float2half_rn(v);
        }
    }
}

// =============================================================================
// efpack: ef + adjacency pack + attn1 B-fragment gen (unchanged)
// =============================================================================
__global__ __launch_bounds__(256)
void efpack_kernel(const float* __restrict__ d, const unsigned* __restrict__ dmaxu,
                   float* __restrict__ E, float* __restrict__ F,
                   float* __restrict__ dmaxf,
                   const int* __restrict__ adj, unsigned* __restrict__ bits,
                   const __half* __restrict__ T1, uint4* __restrict__ Bf1)
{
    if (blockIdx.x < 32) {
        float dm = fdec(*dmaxu);
        int i = blockIdx.x * 256 + threadIdx.x;
        float v = d[i] - dm;
        E[i] = __expf(v);
        F[i] = __expf(ALPHA * v);
        if (i == 0) *dmaxf = dm;
    } else if (blockIdx.x < 32 + 262144) {
        size_t idx = (size_t)(blockIdx.x - 32) * 256 + threadIdx.x;
        int v = adj[idx] > 0;
        unsigned b = __ballot_sync(0xffffffffu, v);
        if ((threadIdx.x & 31) == 0) bits[idx >> 5] = b;
    } else {
        int w = (blockIdx.x - 32 - 262144) * 8 + (threadIdx.x >> 5);
        int lane = threadIdx.x & 31;
        int jblk = w >> 6, ng = (w >> 2) & 15, kt = w & 3;
        int f0 = ng * 16 + (lane >> 2);
        int jb = jblk * 64 + kt * 16 + (lane & 3) * 2;
        const __half* p = T1 + (size_t)f0 * N_NODES + jb;
        uint32_t b0 = *(const uint32_t*)p;
        uint32_t b1 = *(const uint32_t*)(p + 8);
        uint32_t b2 = *(const uint32_t*)(p + (size_t)8 * N_NODES);
        uint32_t b3 = *(const uint32_t*)(p + (size_t)8 * N_NODES + 8);
        Bf1[(size_t)w * 32 + lane] = make_uint4(b0, b1, b2, b3);
    }
}

__global__ __launch_bounds__(256)
void ef_kernel(const float* __restrict__ d, const unsigned* __restrict__ dmaxu,
               float* __restrict__ E, float* __restrict__ F,
               float* __restrict__ dmaxf,
               const __half* __restrict__ T, uint2* __restrict__ Bf, int mat)
{
    if (blockIdx.x < 32) {
        float dm = fdec(*dmaxu);
        int i = blockIdx.x * 256 + threadIdx.x;
        float v = d[i] - dm;
        E[i] = __expf(v);
        F[i] = __expf(ALPHA * v);
        if (i == 0) *dmaxf = dm;
    } else {
        int w = (blockIdx.x - 32) * 8 + (threadIdx.x >> 5);
        int lane = threadIdx.x & 31;
        int jblk = w >> 5, ng = (w >> 2) & 7, kt = w & 3;
        int f0 = ng * 8 + (lane >> 2);
        int jb = jblk * 64 + kt * 16 + (lane & 3) * 2;
        const __half* p = T + (size_t)f0 * N_NODES + jb;
        uint32_t b0 = *(const uint32_t*)p;
        uint32_t b1 = *(const uint32_t*)(p + 8);
        Bf[(size_t)mat * 131072 + (size_t)w * 32 + lane] = make_uint2(b0, b1);
    }
}

// =============================================================================
// attn1: CTA 32 rows x 256 F, 256 thr, 8 warps (32r x 32c each), grid 256.
// A-ldsm duplication 8x; B fragments from GMEM; 3 CTAs/SM target.
// =============================================================================
static constexpr int PA      = 144;
static constexpr int S1_A    = 0;          // 2 buf x 32x144
static constexpr int S1_ABUF = 4608;
static constexpr int S1_ZT   = 9216;       // 256 floats
static constexpr int S1_ZR   = 10240;      // 32 floats
static constexpr int SMEM1   = 10368;

__global__ __launch_bounds__(256, 3)
void attn1_kernel(const unsigned* __restrict__ adjb,
                  const uint4* __restrict__ Bf,
                  const float* __restrict__ svec, const float* __restrict__ dvec,
                  const float* __restrict__ EJ, const float* __restrict__ FJ,
                  const float* __restrict__ dmaxp, float* __restrict__ outp)
{
    extern __shared__ __align__(16) char smem[];
    const uint32_t sb = smem_u32(smem);
    const int tid = threadIdx.x, warp = tid >> 5, lane = tid & 31;
    const int g = lane >> 2, tq = lane & 3;
    const int i0 = blockIdx.x * 32;
    const int n0w = warp * 32;

    const uint32_t a_lane = ((lane & 7) + ((lane >> 3) & 1) * 8) * PA + ((lane >> 4) & 1) * 16;

    const int r = tid >> 3, q = tid & 7;     // row (32), 8-j slice
    const float sv = svec[i0 + r];
    const float mv = sv + *dmaxp;
    const float m_r = mv > 0.f ? mv : ALPHA * mv;
    const float RA = __expf(mv - m_r);
    const float RB = __expf(ALPHA * mv - m_r);
    float zacc = 0.f;

    float acc[2][4][4];
    #pragma unroll
    for (int a = 0; a < 2; ++a)
        #pragma unroll
        for (int b = 0; b < 4; ++b)
            #pragma unroll
            for (int c = 0; c < 4; ++c) acc[a][b][c] = 0.f;

    const size_t row_adj = (size_t)(i0 + r) * NWORDS;
    const uint4* bfp = Bf + (size_t)warp * 256 + lane;   // + t*2048 + ng2*128 + kt*32

    // ---- prologue: P-gen tile 0 ----------------------------------------------
    {
        unsigned w = adjb[row_adj + (q >> 2)];
        unsigned bits8 = (w >> ((q & 3) * 8)) & 0xFF;
        const int jb = q * 8;
        #pragma unroll
        for (int v = 0; v < 2; ++v) {
            unsigned bits = (bits8 >> (v * 4)) & 0xF;
            int jj = jb + v * 4;
            float4 dd = *(const float4*)(dvec + jj);
            float4 ee = *(const float4*)(EJ + jj);
            float4 ff = *(const float4*)(FJ + jj);
            float p0 = (bits & 1) ? ((sv + dd.x > 0.f) ? RA * ee.x : RB * ff.x) : 0.f;
            float p1 = (bits & 2) ? ((sv + dd.y > 0.f) ? RA * ee.y : RB * ff.y) : 0.f;
            float p2 = (bits & 4) ? ((sv + dd.z > 0.f) ? RA * ee.z : RB * ff.z) : 0.f;
            float p3 = (bits & 8) ? ((sv + dd.w > 0.f) ? RA * ee.w : RB * ff.w) : 0.f;
            zacc += p0 + p1 + p2 + p3;
            __half2 h01 = __floats2half2_rn(p0, p1);
            __half2 h23 = __floats2half2_rn(p2, p3);
            uint2 pk;
            pk.x = *(uint32_t*)&h01; pk.y = *(uint32_t*)&h23;
            *(uint2*)(smem + S1_A + r * PA + jj * 2) = pk;
        }
    }
    __syncthreads();

    for (int t = 0; t < N_NODES / 64; ++t) {
        const int buf = t & 1;

        // ---- MMA on A[buf] with GMEM B fragments ------------------------------
        const uint32_t abase = sb + S1_A + buf * S1_ABUF + a_lane;
        const uint4* bft = bfp + (size_t)t * 2048;
        #pragma unroll
        for (int kt = 0; kt < 4; ++kt) {
            uint4 b0v = bft[kt * 32];
            uint4 b1v = bft[128 + kt * 32];
            uint32_t a0[4], a1[4];
            ldsm_x4(a0[0], a0[1], a0[2], a0[3], abase + kt * 32);
            ldsm_x4(a1[0], a1[1], a1[2], a1[3], abase + 16 * PA + kt * 32);
            mma16816(acc[0][0], a0[0], a0[1], a0[2], a0[3], b0v.x, b0v.y);
            mma16816(acc[0][1], a0[0], a0[1], a0[2], a0[3], b0v.z, b0v.w);
            mma16816(acc[0][2], a0[0], a0[1], a0[2], a0[3], b1v.x, b1v.y);
            mma16816(acc[0][3], a0[0], a0[1], a0[2], a0[3], b1v.z, b1v.w);
            mma16816(acc[1][0], a1[0], a1[1], a1[2], a1[3], b0v.x, b0v.y);
            mma16816(acc[1][1], a1[0], a1[1], a1[2], a1[3], b0v.z, b0v.w);
            mma16816(acc[1][2], a1[0], a1[1], a1[2], a1[3], b1v.x, b1v.y);
            mma16816(acc[1][3], a1[0], a1[1], a1[2], a1[3], b1v.z, b1v.w);
        }

        if (t + 1 < N_NODES / 64) {
            const int j0 = (t + 1) * 64;
            unsigned w = adjb[row_adj + (j0 >> 5) + (q >> 2)];
            unsigned bits8 = (w >> ((q & 3) * 8)) & 0xFF;
            const int jb = q * 8;
            #pragma unroll
            for (int v = 0; v < 2; ++v) {
                unsigned bits = (bits8 >> (v * 4)) & 0xF;
                int jj = jb + v * 4;
                float4 dd = *(const float4*)(dvec + j0 + jj);
                float4 ee = *(const float4*)(EJ + j0 + jj);
                float4 ff = *(const float4*)(FJ + j0 + jj);
                float p0 = (bits & 1) ? ((sv + dd.x > 0.f) ? RA * ee.x : RB * ff.x) : 0.f;
                float p1 = (bits & 2) ? ((sv + dd.y > 0.f) ? RA * ee.y : RB * ff.y) : 0.f;
                float p2 = (bits & 4) ? ((sv + dd.z > 0.f) ? RA * ee.z : RB * ff.z) : 0.f;
                float p3 = (bits & 8) ? ((sv + dd.w > 0.f) ? RA * ee.w : RB * ff.w) : 0.f;
                zacc += p0 + p1 + p2 + p3;
                __half2 h01 = __floats2half2_rn(p0, p1);
                __half2 h23 = __floats2half2_rn(p2, p3);
                uint2 pk;
                pk.x = *(uint32_t*)&h01; pk.y = *(uint32_t*)&h23;
                *(uint2*)(smem + S1_A + (buf ^ 1) * S1_ABUF + r * PA + jj * 2) = pk;
            }
        }
        __syncthreads();
    }

    // ---- epilogue ------------------------------------------------------------
    float* zt = (float*)(smem + S1_ZT);
    float* zr = (float*)(smem + S1_ZR);
    zt[tid] = zacc;
    __syncthreads();
    if (tid < 32) {
        float z = 0.f;
        #pragma unroll
        for (int k = 0; k < 8; ++k) z += zt[8 * tid + k];
        zr[tid] = z;
    }
    __syncthreads();
    #pragma unroll
    for (int mi = 0; mi < 2; ++mi) {
        int r0 = mi * 16 + g;
        float iz0 = 1.f / zr[r0];
        float iz1 = 1.f / zr[r0 + 8];
        #pragma unroll
        for (int ni = 0; ni < 4; ++ni) {
            int col = n0w + ni * 8 + tq * 2;
            float v0 = acc[mi][ni][0] * iz0; v0 = v0 > 0.f ? v0 : expm1f(v0);
            float v1 = acc[mi][ni][1] * iz0; v1 = v1 > 0.f ? v1 : expm1f(v1);
            float v2 = acc[mi][ni][2] * iz1; v2 = v2 > 0.f ? v2 : expm1f(v2);
            float v3 = acc[mi][ni][3] * iz1; v3 = v3 > 0.f ? v3 : expm1f(v3);
            *(float2*)&outp[(size_t)(i0 + r0) * NHID + col]     = make_float2(v0, v1);
            *(float2*)&outp[(size_t)(i0 + r0 + 8) * NHID + col] = make_float2(v2, v3);
        }
    }
}

// =============================================================================
// attn23: CTA 64 rows, 512 thr, 16 warps: which=w>>3, mhalf=(w>>2)&1, ng4=(w&3).
// warp = 32r x 16n. grid 128. B fragments from GMEM.
// =============================================================================
static constexpr int S2_A    = 0;          // 2 buf x [mu 64x144 | lv 64x144]
static constexpr int S2_ABUF = 18432;
static constexpr int S2_AMAT = 9216;
static constexpr int S2_ZT   = 36864;      // 2 x 512 floats
static constexpr int S2_ZR   = 40960;      // 2 x 64 floats
static constexpr int SMEM2   = 41472;

__global__ __launch_bounds__(512, 2)
void attn23_kernel(const unsigned* __restrict__ adjb,
                   const uint2* __restrict__ Bf,
                   const float* __restrict__ smuv, const float* __restrict__ dmuv,
                   const float* __restrict__ slvv, const float* __restrict__ dlvv,
                   const float* __restrict__ Em, const float* __restrict__ Fm,
                   const float* __restrict__ Ev, const float* __restrict__ Fv,
                   const float* __restrict__ dmaxp,
                   float* __restrict__ out_mu, float* __restrict__ out_lv)
{
    extern __shared__ __align__(16) char smem[];
    const uint32_t sb = smem_u32(smem);
    const int tid = threadIdx.x, warp = tid >> 5, lane = tid & 31;
    const int g = lane >> 2, tq = lane & 3;
    const int i0 = blockIdx.x * 64;
    const int which = warp >> 3;
    const int mhalf = (warp >> 2) & 1;
    const int ng0 = (warp & 3) * 2;          // 8-f group base (n = 16 per warp)
    const int n0w = (warp & 3) * 16;

    const uint32_t a_lane = ((lane & 7) + ((lane >> 3) & 1) * 8) * PA + ((lane >> 4) & 1) * 16;

    const int r = tid >> 3, q = tid & 7;     // row (64), 8-j slice
    const float svm = smuv[i0 + r], svv = slvv[i0 + r];
    const float mvm = svm + dmaxp[0], mvv = svv + dmaxp[1];
    const float mm = mvm > 0.f ? mvm : ALPHA * mvm;
    const float ml = mvv > 0.f ? mvv : ALPHA * mvv;
    const float RAm = __expf(mvm - mm), RBm = __expf(ALPHA * mvm - mm);
    const float RAv = __expf(mvv - ml), RBv = __expf(ALPHA * mvv - ml);
    float zm = 0.f, zv = 0.f;

    float acc[2][2][4];
    #pragma unroll
    for (int a = 0; a < 2; ++a)
        #pragma unroll
        for (int b = 0; b < 2; ++b)
            #pragma unroll
            for (int c = 0; c < 4; ++c) acc[a][b][c] = 0.f;

    const size_t row_adj = (size_t)(i0 + r) * NWORDS;
    const uint2* bfp = Bf + (size_t)which * 131072 + (size_t)ng0 * 128 + lane;

    // ---- prologue: P-gen tile 0 (both mats) ----------------------------------
    {
        unsigned w = adjb[row_adj + (q >> 2)];
        unsigned bits8 = (w >> ((q & 3) * 8)) & 0xFF;
        const int jb = q * 8;
        #pragma unroll
        for (int v = 0; v < 2; ++v) {
            unsigned bits = (bits8 >> (v * 4)) & 0xF;
            int jj = jb + v * 4;
            float4 dd = *(const float4*)(dmuv + jj);
            float4 ee = *(const float4*)(Em + jj);
            float4 ff = *(const float4*)(Fm + jj);
            float p0 = (bits & 1) ? ((svm + dd.x > 0.f) ? RAm * ee.x : RBm * ff.x) : 0.f;
            float p1 = (bits & 2) ? ((svm + dd.y > 0.f) ? RAm * ee.y : RBm * ff.y) : 0.f;
            float p2 = (bits & 4) ? ((svm + dd.z > 0.f) ? RAm * ee.z : RBm * ff.z) : 0.f;
            float p3 = (bits & 8) ? ((svm + dd.w > 0.f) ? RAm * ee.w : RBm * ff.w) : 0.f;
            zm += p0 + p1 + p2 + p3;
            __half2 h01 = __floats2half2_rn(p0, p1);
            __half2 h23 = __floats2half2_rn(p2, p3);
            uint2 pk;
            pk.x = *(uint32_t*)&h01; pk.y = *(uint32_t*)&h23;
            *(uint2*)(smem + S2_A + r * PA + jj * 2) = pk;

            dd = *(const float4*)(dlvv + jj);
            ee = *(const float4*)(Ev + jj);
            ff = *(const float4*)(Fv + jj);
            p0 = (bits & 1) ? ((svv + dd.x > 0.f) ? RAv * ee.x : RBv * ff.x) : 0.f;
            p1 = (bits & 2) ? ((svv + dd.y > 0.f) ? RAv * ee.y : RBv * ff.y) : 0.f;
            p2 = (bits & 4) ? ((svv + dd.z > 0.f) ? RAv * ee.z : RBv * ff.z) : 0.f;
            p3 = (bits & 8) ? ((svv + dd.w > 0.f) ? RAv * ee.w : RBv * ff.w) : 0.f;
            zv += p0 + p1 + p2 + p3;
            h01 = __floats2half2_rn(p0, p1);
            h23 = __floats2half2_rn(p2, p3);
            pk.x = *(uint32_t*)&h01; pk.y = *(uint32_t*)&h23;
            *(uint2*)(smem + S2_A + S2_AMAT + r * PA + jj * 2) = pk;
        }
    }
    __syncthreads();

    for (int t = 0; t < N_NODES / 64; ++t) {
        const int buf = t & 1;

        const uint32_t abase = sb + S2_A + buf * S2_ABUF + which * S2_AMAT
                             + mhalf * (32 * PA) + a_lane;
        const uint2* bft = bfp + (size_t)t * 1024;
        #pragma unroll
        for (int kt = 0; kt < 4; ++kt) {
            uint2 b0v = bft[kt * 32];
            uint2 b1v = bft[128 + kt * 32];
            uint32_t a0[4], a1[4];
            ldsm_x4(a0[0], a0[1], a0[2], a0[3], abase + kt * 32);
            ldsm_x4(a1[0], a1[1], a1[2], a1[3], abase + 16 * PA + kt * 32);
            mma16816(acc[0][0], a0[0], a0[1], a0[2], a0[3], b0v.x, b0v.y);
            mma16816(acc[0][1], a0[0], a0[1], a0[2], a0[3], b1v.x, b1v.y);
            mma16816(acc[1][0], a1[0], a1[1], a1[2], a1[3], b0v.x, b0v.y);
            mma16816(acc[1][1], a1[0], a1[1], a1[2], a1[3], b1v.x, b1v.y);
        }

        if (t + 1 < N_NODES / 64) {
            const int j0 = (t + 1) * 64;
            unsigned w = adjb[row_adj + (j0 >> 5) + (q >> 2)];
            unsigned bits8 = (w >> ((q & 3) * 8)) & 0xFF;
            const int jb = q * 8;
            #pragma unroll
            for (int v = 0; v < 2; ++v) {
                unsigned bits = (bits8 >> (v * 4)) & 0xF;
                int jj = jb + v * 4;
                float4 dd = *(const float4*)(dmuv + j0 + jj);
                float4 ee = *(const float4*)(Em + j0 + jj);
                float4 ff = *(const float4*)(Fm + j0 + jj);
                float p0 = (bits & 1) ? ((svm + dd.x > 0.f) ? RAm * ee.x : RBm * ff.x) : 0.f;
                float p1 = (bits & 2) ? ((svm + dd.y > 0.f) ? RAm * ee.y : RBm * ff.y) : 0.f;
                float p2 = (bits & 4) ? ((svm + dd.z > 0.f) ? RAm * ee.z : RBm * ff.z) : 0.f;
                float p3 = (bits & 8) ? ((svm + dd.w > 0.f) ? RAm * ee.w : RBm * ff.w) : 0.f;
                zm += p0 + p1 + p2 + p3;
                __half2 h01 = __floats2half2_rn(p0, p1);
                __half2 h23 = __floats2half2_rn(p2, p3);
                uint2 pk;
                pk.x = *(uint32_t*)&h01; pk.y = *(uint32_t*)&h23;
                *(uint2*)(smem + S2_A + (buf ^ 1) * S2_ABUF + r * PA + jj * 2) = pk;

                dd = *(const float4*)(dlvv + j0 + jj);
                ee = *(const float4*)(Ev + j0 + jj);
                ff = *(const float4*)(Fv + j0 + jj);
                p0 = (bits & 1) ? ((svv + dd.x > 0.f) ? RAv * ee.x : RBv * ff.x) : 0.f;
                p1 = (bits & 2) ? ((svv + dd.y > 0.f) ? RAv * ee.y : RBv * ff.y) : 0.f;
                p2 = (bits & 4) ? ((svv + dd.z > 0.f) ? RAv * ee.z : RBv * ff.z) : 0.f;
                p3 = (bits & 8) ? ((svv + dd.w > 0.f) ? RAv * ee.w : RBv * ff.w) : 0.f;
                zv += p0 + p1 + p2 + p3;
                h01 = __floats2half2_rn(p0, p1);
                h23 = __floats2half2_rn(p2, p3);
                pk.x = *(uint32_t*)&h01; pk.y = *(uint32_t*)&h23;
                *(uint2*)(smem + S2_A + (buf ^ 1) * S2_ABUF + S2_AMAT + r * PA + jj * 2) = pk;
            }
        }
        __syncthreads();
    }

    // epilogue
    float* ztm = (float*)(smem + S2_ZT);
    float* ztv = ztm + 512;
    float* zrm = (float*)(smem + S2_ZR);
    float* zrv = zrm + 64;
    ztm[tid] = zm; ztv[tid] = zv;
    __syncthreads();
    if (tid < 64) {
        float a = 0.f, b = 0.f;
        #pragma unroll
        for (int k = 0; k < 8; ++k) { a += ztm[8 * tid + k]; b += ztv[8 * tid + k]; }
        zrm[tid] = a; zrv[tid] = b;
    }
    __syncthreads();
    const float* zrow = which ? zrv : zrm;
    float* outw = which ? out_lv : out_mu;
    #pragma unroll
    for (int mi = 0; mi < 2; ++mi) {
        int r0 = mhalf * 32 + mi * 16 + g;
        float iz0 = 1.f / zrow[r0];
        float iz1 = 1.f / zrow[r0 + 8];
        #pragma unroll
        for (int ni = 0; ni < 2; ++ni) {
            int col = n0w + ni * 8 + tq * 2;
            *(float2*)&outw[(size_t)(i0 + r0) * NLAT + col] =
                make_float2(acc[mi][ni][0] * iz0, acc[mi][ni][1] * iz0);
            *(float2*)&outw[(size_t)(i0 + r0 + 8) * NLAT + col] =
                make_float2(acc[mi][ni][2] * iz1, acc[mi][ni][3] * iz1);
        }
    }
}

// ---------------- z = mu + eps*exp(0.5*lv); logits = z @ Wc + bc ------------
__global__ __launch_bounds__(128)
void final_kernel(const float* __restrict__ mu, const float* __restrict__ lv,
                  const float* __restrict__ eps, const float* __restrict__ Wc,
                  const float* __restrict__ bc, float* __restrict__ logits)
{
    __shared__ float zs[8 * 64];
    const int tid = threadIdx.x;
    const int r0 = blockIdx.x * 8;
    #pragma unroll
    for (int l = tid; l < 8 * 64; l += 128) {
        int r = l >> 6, k = l & 63;
        size_t idx = (size_t)(r0 + r) * 64 + k;
        zs[l] = mu[idx] + eps[idx] * __expf(0.5f * lv[idx]);
    }
    __syncthreads();
    int r = tid >> 4, n = tid & 15;
    float acc = bc[n];
    #pragma unroll
    for (int k = 0; k < 64; ++k) acc += zs[r * 64 + k] * Wc[k * 16 + n];
    logits[(size_t)(r0 + r) * 16 + n] = acc;
}

// ------------------------------ launch --------------------------------------
extern "C" void kernel_launch(void* const* d_in, const int* in_sizes, int n_in,
                              void* d_out, int out_size)
{
    const float* x   = (const float*)d_in[0];
    const int*   adj = (const int*)  d_in[1];
    const float* eps = (const float*)d_in[2];
    const float* W1  = (const float*)d_in[3];
    const float* a1  = (const float*)d_in[4];
    const float* Wmu = (const float*)d_in[5];
    const float* amu = (const float*)d_in[6];
    const float* Wlv = (const float*)d_in[7];
    const float* alv = (const float*)d_in[8];
    const float* Wc  = (const float*)d_in[9];
    const float* bc  = (const float*)d_in[10];

    float* out    = (float*)d_out;
    float* logits = out;
    float* mu     = out + (size_t)N_NODES * NCLASS;
    float* lv     = mu  + (size_t)N_NODES * NLAT;

    float *Wh1, *h, *Whmu, *Whlv, *s1, *d1, *smu, *dmu, *slv, *dlv;
    float *E1, *F1, *Emu, *Fmu, *Elv, *Flv, *dmaxf;
    unsigned *dmaxu;
    __half *T1, *Tm, *Tv;
    uint4 *Bf1;
    uint2 *Bf23;
    unsigned* adjb;
    cudaGetSymbolAddress((void**)&Wh1,  g_Wh1);
    cudaGetSymbolAddress((void**)&h,    g_h);
    cudaGetSymbolAddress((void**)&Whmu, g_Whmu);
    cudaGetSymbolAddress((void**)&Whlv, g_Whlv);
    cudaGetSymbolAddress((void**)&s1,   g_s1);
    cudaGetSymbolAddress((void**)&d1,   g_d1);
    cudaGetSymbolAddress((void**)&smu,  g_smu);
    cudaGetSymbolAddress((void**)&dmu,  g_dmu);
    cudaGetSymbolAddress((void**)&slv,  g_slv);
    cudaGetSymbolAddress((void**)&dlv,  g_dlv);
    cudaGetSymbolAddress((void**)&dmaxu, g_dmaxu);
    cudaGetSymbolAddress((void**)&dmaxf, g_dmaxf);
    cudaGetSymbolAddress((void**)&E1,   g_E1);
    cudaGetSymbolAddress((void**)&F1,   g_F1);
    cudaGetSymbolAddress((void**)&Emu,  g_Emu);
    cudaGetSymbolAddress((void**)&Fmu,  g_Fmu);
    cudaGetSymbolAddress((void**)&Elv,  g_Elv);
    cudaGetSymbolAddress((void**)&Flv,  g_Flv);
    cudaGetSymbolAddress((void**)&T1,   g_T1);
    cudaGetSymbolAddress((void**)&Tm,   g_Tm);
    cudaGetSymbolAddress((void**)&Tv,   g_Tv);
    cudaGetSymbolAddress((void**)&Bf1,  g_Bf1);
    cudaGetSymbolAddress((void**)&Bf23, g_Bf23);
    cudaGetSymbolAddress((void**)&adjb, g_adjb);

    cudaFuncSetAttribute(gemm_mma_kernel, cudaFuncAttributeMaxDynamicSharedMemorySize, GSMEM);
    cudaFuncSetAttribute(attn1_kernel,  cudaFuncAttributeMaxDynamicSharedMemorySize, SMEM1);
    cudaFuncSetAttribute(attn23_kernel, cudaFuncAttributeMaxDynamicSharedMemorySize, SMEM2);

    // 0: gemm1 (inits dmax)
    gemm_mma_kernel<<<dim3(NHID / 64, N_NODES / 128), 256, GSMEM>>>(
        x, W1, Wh1, N_NODES, NHID, NFEAT, dmaxu, 1);
    // 1: sd + tconv
    sdtconv_kernel<NHID><<<1024 + (NHID / 32) * (N_NODES / 32), 256>>>(
        Wh1, a1, s1, d1, dmaxu + 0, T1);
    // 2: ef + pack_adj + attn1 B-fragment gen
    efpack_kernel<<<32 + 262144 + 1024, 256>>>(
        d1, dmaxu + 0, E1, F1, dmaxf + 0, adj, adjb, T1, Bf1);
    // 3: attn1 (profile slot)
    attn1_kernel<<<N_NODES / 32, 256, SMEM1>>>(adjb, Bf1, s1, d1, E1, F1, dmaxf + 0, h);

    // layer 2/3
    gemm_mma_kernel<<<dim3(NLAT / 64, N_NODES / 128), 256, GSMEM>>>(
        h, Wmu, Whmu, N_NODES, NLAT, NHID, dmaxu, 0);
    gemm_mma_kernel<<<dim3(NLAT / 64, N_NODES / 128), 256, GSMEM>>>(
        h, Wlv, Whlv, N_NODES, NLAT, NHID, dmaxu, 0);
    sdtconv_kernel<NLAT><<<1024 + (NLAT / 32) * (N_NODES / 32), 256>>>(
        Whmu, amu, smu, dmu, dmaxu + 1, Tm);
    sdtconv_kernel<NLAT><<<1024 + (NLAT / 32) * (N_NODES / 32), 256>>>(
        Whlv, alv, slv, dlv, dmaxu + 2, Tv);
    ef_kernel<<<32 + 512, 256>>>(dmu, dmaxu + 1, Emu, Fmu, dmaxf + 1, Tm, Bf23, 0);
    ef_kernel<<<32 + 512, 256>>>(dlv, dmaxu + 2, Elv, Flv, dmaxf + 2, Tv, Bf23, 1);
    attn23_kernel<<<N_NODES / 64, 512, SMEM2>>>(adjb, Bf23,
                                                smu, dmu, slv, dlv,
                                                Emu, Fmu, Elv, Flv, dmaxf + 1, mu, lv);

    // reparameterize + classifier
    final_kernel<<<N_NODES / 8, 128>>>(mu, lv, eps, Wc, bc, logits);
}